// round 11
// baseline (speedup 1.0000x reference)
#include <cuda_runtime.h>
#include <cuda_bf16.h>
#include <stdint.h>

#define BB      2
#define SEQ     2048
#define EE      512
#define HH      8
#define DDIM    64
#define NLAYERS 2
#define DFFN    2048
#define NROWS   4096   // BB*SEQ

// mma.sync GEMM config: 128x128 tile, K-chunk 32 (bf16), hi/lo x3 passes
#define GM_CHUNK     32
#define GM_STRIDE    80
#define GM_MAT_BYTES (128 * GM_STRIDE)
#define GM_BUF_BYTES (4 * GM_MAT_BYTES)
#define GM_SMEM      (2 * GM_BUF_BYTES)

// flash mma config: BQ=128, BK=32, 8 warps (16 q-rows each)
#define FB_STRIDE_B  144                   // 64 bf16 = 128B + 16B pad
#define FB_Q_BYTES   (128 * FB_STRIDE_B)   // 18432 per matrix (hi or lo)
#define FB_KV_MAT    (32 * FB_STRIDE_B)    // 4608
#define FB_STAGE     (4 * FB_KV_MAT)       // Kh,Kl,Vh,Vl = 18432
#define FB_SMEM      (2*FB_Q_BYTES + 2*FB_STAGE + 256)

// ---------------- scratch (device globals) ----------------------------------
__device__ float g_x[NROWS * EE];
__device__ float g_attn[NROWS * EE];
__device__ float g_part[2 * NROWS * EE];                      // FF2 split-K partials
__device__ __nv_bfloat16 g_qhi[NROWS*EE], g_qlo[NROWS*EE];
__device__ __nv_bfloat16 g_khi[NROWS*EE], g_klo[NROWS*EE];
__device__ __nv_bfloat16 g_vhi[NROWS*EE], g_vlo[NROWS*EE];
__device__ __nv_bfloat16 g_ckh[NROWS*EE], g_ckl[NROWS*EE];   // compacted K hi/lo
__device__ __nv_bfloat16 g_cvh[NROWS*EE], g_cvl[NROWS*EE];   // compacted V hi/lo
__device__ int g_cnt[BB];
__device__ int g_cidx[BB*SEQ];
__device__ __nv_bfloat16 g_hhi[NROWS * EE];
__device__ __nv_bfloat16 g_hlo[NROWS * EE];
__device__ __nv_bfloat16 g_fhi[NROWS * DFFN];
__device__ __nv_bfloat16 g_flo[NROWS * DFFN];
__device__ __nv_bfloat16 g_wqhi[NLAYERS*EE*EE], g_wqlo[NLAYERS*EE*EE];
__device__ __nv_bfloat16 g_wkhi[NLAYERS*EE*EE], g_wklo[NLAYERS*EE*EE];
__device__ __nv_bfloat16 g_wvhi[NLAYERS*EE*EE], g_wvlo[NLAYERS*EE*EE];
__device__ __nv_bfloat16 g_W1hi[DFFN*EE], g_W1lo[DFFN*EE];
__device__ __nv_bfloat16 g_W2hi[EE*DFFN], g_W2lo[EE*DFFN];

// ---------------- PTX helpers ------------------------------------------------
__device__ __forceinline__ uint32_t smem_u32(const void* p) {
    uint32_t a;
    asm("{ .reg .u64 t; cvta.to.shared.u64 t, %1; cvt.u32.u64 %0, t; }" : "=r"(a) : "l"(p));
    return a;
}
__device__ __forceinline__ void cp16(uint32_t saddr, const void* g) {
    asm volatile("cp.async.cg.shared.global [%0], [%1], 16;" :: "r"(saddr), "l"(g));
}
__device__ __forceinline__ void cp_commit() {
    asm volatile("cp.async.commit_group;" ::: "memory");
}
__device__ __forceinline__ void cp_wait0() {
    asm volatile("cp.async.wait_group 0;" ::: "memory");
}
__device__ __forceinline__ void cp_wait1() {
    asm volatile("cp.async.wait_group 1;" ::: "memory");
}
__device__ __forceinline__ void ldmx4(uint32_t* r, uint32_t addr) {
    asm volatile("ldmatrix.sync.aligned.m8n8.x4.shared.b16 {%0,%1,%2,%3}, [%4];"
        : "=r"(r[0]), "=r"(r[1]), "=r"(r[2]), "=r"(r[3]) : "r"(addr));
}
__device__ __forceinline__ void ldmx4t(uint32_t* r, uint32_t addr) {
    asm volatile("ldmatrix.sync.aligned.m8n8.x4.trans.shared.b16 {%0,%1,%2,%3}, [%4];"
        : "=r"(r[0]), "=r"(r[1]), "=r"(r[2]), "=r"(r[3]) : "r"(addr));
}
__device__ __forceinline__ void mma_bf16(float* d, const uint32_t* a, const uint32_t* b) {
    asm volatile(
        "mma.sync.aligned.m16n8k16.row.col.f32.bf16.bf16.f32 "
        "{%0,%1,%2,%3}, {%4,%5,%6,%7}, {%8,%9}, {%0,%1,%2,%3};"
        : "+f"(d[0]), "+f"(d[1]), "+f"(d[2]), "+f"(d[3])
        : "r"(a[0]), "r"(a[1]), "r"(a[2]), "r"(a[3]), "r"(b[0]), "r"(b[1]));
}

// ---------------- hi/lo split ------------------------------------------------
__device__ __forceinline__ void split_bf16(float v, __nv_bfloat16& h, __nv_bfloat16& l) {
    h = __float2bfloat16(v);
    l = __float2bfloat16(v - __bfloat162float(h));
}
__device__ __forceinline__ void pack_hilo(float a, float b, uint32_t& h, uint32_t& l) {
    __nv_bfloat162 hp, lp;
    hp.x = __float2bfloat16(a);
    hp.y = __float2bfloat16(b);
    lp.x = __float2bfloat16(a - __bfloat162float(hp.x));
    lp.y = __float2bfloat16(b - __bfloat162float(hp.y));
    h = *reinterpret_cast<uint32_t*>(&hp);
    l = *reinterpret_cast<uint32_t*>(&lp);
}

// ---------------- reductions -------------------------------------------------
__device__ __forceinline__ void block_reduce2(float& s, float& s2) {
    __shared__ float shm[8];
    #pragma unroll
    for (int o = 16; o > 0; o >>= 1) {
        s  += __shfl_down_sync(0xffffffffu, s,  o);
        s2 += __shfl_down_sync(0xffffffffu, s2, o);
    }
    int w = threadIdx.x >> 5;
    __syncthreads();
    if ((threadIdx.x & 31) == 0) { shm[w] = s; shm[4 + w] = s2; }
    __syncthreads();
    s  = shm[0] + shm[1] + shm[2] + shm[3];
    s2 = shm[4] + shm[5] + shm[6] + shm[7];
}

// ---------------- LayerNorm variants ----------------------------------------
__global__ void ln_f32(const float* __restrict__ in, float* __restrict__ outp,
                       const float* __restrict__ g, const float* __restrict__ b) {
    int row = blockIdx.x, t = threadIdx.x;
    const float* xr = in + (size_t)row * EE;
    float v[4], s = 0.f, s2 = 0.f;
    #pragma unroll
    for (int i = 0; i < 4; i++) { v[i] = xr[t + i*128]; s += v[i]; s2 += v[i]*v[i]; }
    block_reduce2(s, s2);
    float mu = s * (1.f/EE), var = s2 * (1.f/EE) - mu*mu, r = rsqrtf(var + 1e-5f);
    #pragma unroll
    for (int i = 0; i < 4; i++) {
        int idx = t + i*128;
        outp[(size_t)row*EE + idx] = (v[i]-mu)*r*g[idx] + b[idx];
    }
}
__global__ void ln_bf16(const float* __restrict__ in,
                        __nv_bfloat16* __restrict__ hi, __nv_bfloat16* __restrict__ lo,
                        const float* __restrict__ g, const float* __restrict__ b) {
    int row = blockIdx.x, t = threadIdx.x;
    const float* xr = in + (size_t)row * EE;
    float v[4], s = 0.f, s2 = 0.f;
    #pragma unroll
    for (int i = 0; i < 4; i++) { v[i] = xr[t + i*128]; s += v[i]; s2 += v[i]*v[i]; }
    block_reduce2(s, s2);
    float mu = s * (1.f/EE), var = s2 * (1.f/EE) - mu*mu, r = rsqrtf(var + 1e-5f);
    #pragma unroll
    for (int i = 0; i < 4; i++) {
        int idx = t + i*128;
        float y = (v[i]-mu)*r*g[idx] + b[idx];
        __nv_bfloat16 h, l; split_bf16(y, h, l);
        hi[(size_t)row*EE + idx] = h;
        lo[(size_t)row*EE + idx] = l;
    }
}
__global__ void fuse_attn_res_ln(const float* __restrict__ attn, float* x,
                                 __nv_bfloat16* __restrict__ hhi, __nv_bfloat16* __restrict__ hlo,
                                 const float* __restrict__ g2, const float* __restrict__ b2) {
    int row = blockIdx.x, t = threadIdx.x;
    const float* ar = attn + (size_t)row * EE;
    float a[4], s = 0.f, s2 = 0.f;
    #pragma unroll
    for (int i = 0; i < 4; i++) { a[i] = ar[t + i*128]; s += a[i]; s2 += a[i]*a[i]; }
    block_reduce2(s, s2);
    float mu = s * (1.f/EE), var = s2 * (1.f/EE) - mu*mu, r = rsqrtf(var + 1e-5f);
    float xv[4];
    s = 0.f; s2 = 0.f;
    #pragma unroll
    for (int i = 0; i < 4; i++) {
        int idx = t + i*128;
        float y = (a[i]-mu)*r*g2[idx] + b2[idx];
        float xn = x[(size_t)row*EE + idx] + y;
        x[(size_t)row*EE + idx] = xn;
        xv[i] = xn; s += xn; s2 += xn*xn;
    }
    block_reduce2(s, s2);
    float mu2 = s * (1.f/EE), var2 = s2 * (1.f/EE) - mu2*mu2, r2 = rsqrtf(var2 + 1e-5f);
    #pragma unroll
    for (int i = 0; i < 4; i++) {
        int idx = t + i*128;
        float y = (xv[i]-mu2)*r2;
        __nv_bfloat16 h, l; split_bf16(y, h, l);
        hhi[(size_t)row*EE + idx] = h;
        hlo[(size_t)row*EE + idx] = l;
    }
}

// ---------------- weight fp32 -> bf16 hi/lo (vectorized) ---------------------
__global__ void cvt_kernel(const float4* __restrict__ in,
                           __nv_bfloat162* __restrict__ hi, __nv_bfloat162* __restrict__ lo,
                           int n4) {
    int i = blockIdx.x * blockDim.x + threadIdx.x;
    if (i < n4) {
        float4 v = in[i];
        uint32_t h0, l0, h1, l1;
        pack_hilo(v.x, v.y, h0, l0);
        pack_hilo(v.z, v.w, h1, l1);
        hi[2*i]   = *reinterpret_cast<__nv_bfloat162*>(&h0);
        hi[2*i+1] = *reinterpret_cast<__nv_bfloat162*>(&h1);
        lo[2*i]   = *reinterpret_cast<__nv_bfloat162*>(&l0);
        lo[2*i+1] = *reinterpret_cast<__nv_bfloat162*>(&l1);
    }
}

// ---------------- FF2 split-K reduce: x += p0 + p1 + bias --------------------
__global__ void reduce_ff2(float* __restrict__ x, const float* __restrict__ part,
                           const float* __restrict__ B2) {
    int i = blockIdx.x * blockDim.x + threadIdx.x;
    const int n4 = NROWS * EE / 4;
    if (i < n4) {
        float4 a  = ((const float4*)part)[i];
        float4 b  = ((const float4*)(part + (size_t)NROWS*EE))[i];
        float4 xv = ((float4*)x)[i];
        float4 bs = ((const float4*)B2)[i & (EE/4 - 1)];
        xv.x += a.x + b.x + bs.x;
        xv.y += a.y + b.y + bs.y;
        xv.z += a.z + b.z + bs.z;
        xv.w += a.w + b.w + bs.w;
        ((float4*)x)[i] = xv;
    }
}

// ---------------- mask compaction --------------------------------------------
__global__ __launch_bounds__(1024) void compact_idx(const int* __restrict__ mask) {
    __shared__ int part[1024];
    int b = blockIdx.x, t = threadIdx.x;
    const int* mb = mask + (size_t)b * SEQ;
    int v0 = (mb[2*t]   == 0);
    int v1 = (mb[2*t+1] == 0);
    part[t] = v0 + v1;
    __syncthreads();
    for (int o = 1; o < 1024; o <<= 1) {
        int x = part[t];
        int y = (t >= o) ? part[t-o] : 0;
        __syncthreads();
        part[t] = x + y;
        __syncthreads();
    }
    int incl = part[t];
    int excl = incl - (v0 + v1);
    if (v0) g_cidx[b*SEQ + excl]      = 2*t;
    if (v1) g_cidx[b*SEQ + excl + v0] = 2*t+1;
    if (t == 1023) g_cnt[b] = incl;
}

__global__ __launch_bounds__(256) void compact_copy(
    const __nv_bfloat16* __restrict__ kh, const __nv_bfloat16* __restrict__ kl,
    const __nv_bfloat16* __restrict__ vh, const __nv_bfloat16* __restrict__ vl) {
    int b = blockIdx.y, j = blockIdx.x, t = threadIdx.x;
    int cnt = g_cnt[b];
    int lim = (cnt + 31) & ~31;
    if (j >= lim) return;
    int m = t >> 6, c = t & 63;
    size_t dst = ((size_t)b * SEQ + j) * EE + c * 8;
    const __nv_bfloat16* sp;
    __nv_bfloat16* dp;
    if      (m == 0) dp = g_ckh;
    else if (m == 1) dp = g_ckl;
    else if (m == 2) dp = g_cvh;
    else             dp = g_cvl;
    if (j < cnt) {
        int src = g_cidx[b*SEQ + j];
        size_t sof = ((size_t)b * SEQ + src) * EE + c * 8;
        if      (m == 0) sp = kh;
        else if (m == 1) sp = kl;
        else if (m == 2) sp = vh;
        else             sp = vl;
        *(uint4*)(dp + dst) = *(const uint4*)(sp + sof);
    } else {
        uint4 z; z.x = 0; z.y = 0; z.z = 0; z.w = 0;
        *(uint4*)(dp + dst) = z;
    }
}

// ---------------- mma.sync GEMM ----------------------------------------------
// MODE 1: bias+relu -> bf16 hi/lo. MODE 3: bias -> bf16 hi/lo.
// MODE 4: raw fp32 partial (no bias) — for split-K.
// Kloop = summed K extent; ld = row stride of A and B (elements).
template<int MODE>
__device__ __forceinline__ void gemm_mma_body(
    const __nv_bfloat16* __restrict__ Ahi, const __nv_bfloat16* __restrict__ Alo,
    const __nv_bfloat16* __restrict__ Bhi, const __nv_bfloat16* __restrict__ Blo,
    const float* __restrict__ bias, int Kloop, int ld, int N,
    float* __restrict__ Cf, __nv_bfloat16* __restrict__ Chi, __nv_bfloat16* __restrict__ Clo,
    int rowBase, int colBase)
{
    extern __shared__ char sm8[];
    uint32_t sbase = smem_u32(sm8);
    int tid = threadIdx.x, lane = tid & 31, warp = tid >> 5;
    int wm = warp >> 2, wn = warp & 3;

    float acc[4][4][4];
    #pragma unroll
    for (int i = 0; i < 4; i++)
        #pragma unroll
        for (int j = 0; j < 4; j++)
            #pragma unroll
            for (int c = 0; c < 4; c++) acc[i][j][c] = 0.f;

    uint32_t aAddr = (uint32_t)((wm*64 + ((lane>>3)&1)*8 + (lane&7)) * GM_STRIDE
                                + (lane>>4)*16);
    uint32_t bAddr = (uint32_t)((wn*32 + (lane>>4)*8 + (lane&7)) * GM_STRIDE
                                + ((lane>>3)&1)*16);

    const int T = Kloop / GM_CHUNK;
    int lrow0 = tid >> 2, lseg = tid & 3;

    {
        uint32_t sb = sbase;
        #pragma unroll
        for (int j = 0; j < 2; j++) {
            int row = lrow0 + j*64;
            uint32_t so = row*GM_STRIDE + lseg*16;
            size_t ga = (size_t)(rowBase+row)*ld + lseg*8;
            size_t gb = (size_t)(colBase+row)*ld + lseg*8;
            cp16(sb + 0*GM_MAT_BYTES + so, Ahi + ga);
            cp16(sb + 1*GM_MAT_BYTES + so, Alo + ga);
            cp16(sb + 2*GM_MAT_BYTES + so, Bhi + gb);
            cp16(sb + 3*GM_MAT_BYTES + so, Blo + gb);
        }
        cp_commit();
    }

    for (int t = 0; t < T; t++) {
        cp_wait0();
        __syncthreads();
        if (t + 1 < T) {
            uint32_t sb = sbase + ((t+1) & 1) * GM_BUF_BYTES;
            int koff = (t+1) * GM_CHUNK;
            #pragma unroll
            for (int j = 0; j < 2; j++) {
                int row = lrow0 + j*64;
                uint32_t so = row*GM_STRIDE + lseg*16;
                size_t ga = (size_t)(rowBase+row)*ld + koff + lseg*8;
                size_t gb = (size_t)(colBase+row)*ld + koff + lseg*8;
                cp16(sb + 0*GM_MAT_BYTES + so, Ahi + ga);
                cp16(sb + 1*GM_MAT_BYTES + so, Alo + ga);
                cp16(sb + 2*GM_MAT_BYTES + so, Bhi + gb);
                cp16(sb + 3*GM_MAT_BYTES + so, Blo + gb);
            }
            cp_commit();
        }
        uint32_t buf = sbase + (t & 1) * GM_BUF_BYTES;
        #pragma unroll
        for (int ks = 0; ks < 2; ks++) {
            uint32_t ah[4][4], al[4][4], bh[2][4], bl[2][4];
            #pragma unroll
            for (int i = 0; i < 4; i++) {
                uint32_t ad = buf + aAddr + i*16*GM_STRIDE + ks*32;
                ldmx4(ah[i], ad);
                ldmx4(al[i], ad + GM_MAT_BYTES);
            }
            #pragma unroll
            for (int p = 0; p < 2; p++) {
                uint32_t bd = buf + 2*GM_MAT_BYTES + bAddr + p*16*GM_STRIDE + ks*32;
                ldmx4(bh[p], bd);
                ldmx4(bl[p], bd + GM_MAT_BYTES);
            }
            #pragma unroll
            for (int i = 0; i < 4; i++)
                #pragma unroll
                for (int j = 0; j < 4; j++) {
                    const uint32_t* bhp = &bh[j>>1][(j&1)*2];
                    const uint32_t* blp = &bl[j>>1][(j&1)*2];
                    mma_bf16(acc[i][j], ah[i], bhp);
                    mma_bf16(acc[i][j], ah[i], blp);
                    mma_bf16(acc[i][j], al[i], bhp);
                }
        }
    }

    int g = lane >> 2, tg = lane & 3;
    #pragma unroll
    for (int i = 0; i < 4; i++) {
        int r0 = rowBase + wm*64 + i*16 + g;
        #pragma unroll
        for (int j = 0; j < 4; j++) {
            int c = colBase + wn*32 + j*8 + tg*2;
            float b0 = (MODE == 4) ? 0.f : bias[c];
            float b1 = (MODE == 4) ? 0.f : bias[c+1];
            #pragma unroll
            for (int half = 0; half < 2; half++) {
                int r = r0 + half*8;
                float v0 = acc[i][j][half*2+0] + b0;
                float v1 = acc[i][j][half*2+1] + b1;
                if (MODE == 1 || MODE == 3) {
                    if (MODE == 1) { v0 = fmaxf(v0, 0.f); v1 = fmaxf(v1, 0.f); }
                    __nv_bfloat16 h0, l0, h1, l1;
                    split_bf16(v0, h0, l0); split_bf16(v1, h1, l1);
                    __nv_bfloat162 hp; hp.x = h0; hp.y = h1;
                    __nv_bfloat162 lp; lp.x = l0; lp.y = l1;
                    *(__nv_bfloat162*)&Chi[(size_t)r * N + c] = hp;
                    *(__nv_bfloat162*)&Clo[(size_t)r * N + c] = lp;
                } else {
                    float2 o; o.x = v0; o.y = v1;
                    *(float2*)&Cf[(size_t)r * N + c] = o;
                }
            }
        }
    }
}

template<int MODE>
__global__ __launch_bounds__(256) void gemm_mma(
    const __nv_bfloat16* __restrict__ Ahi, const __nv_bfloat16* __restrict__ Alo,
    const __nv_bfloat16* __restrict__ Bhi, const __nv_bfloat16* __restrict__ Blo,
    const float* __restrict__ bias, int K, int N,
    float* __restrict__ Cf, __nv_bfloat16* __restrict__ Chi, __nv_bfloat16* __restrict__ Clo)
{
    gemm_mma_body<MODE>(Ahi, Alo, Bhi, Blo, bias, K, K, N, Cf, Chi, Clo,
                        blockIdx.y * 128, blockIdx.x * 128);
}

// FF2 split-K: z in {0,1} handles K-half z; writes fp32 partial.
__global__ __launch_bounds__(256) void gemm_mma_splitk(
    const __nv_bfloat16* __restrict__ Ahi, const __nv_bfloat16* __restrict__ Alo,
    const __nv_bfloat16* __restrict__ Bhi, const __nv_bfloat16* __restrict__ Blo,
    float* __restrict__ part)
{
    int z = blockIdx.z;
    int koff = z * (DFFN / 2);
    float* outp = part + (size_t)z * NROWS * EE;
    gemm_mma_body<4>(Ahi + koff, Alo + koff, Bhi + koff, Blo + koff,
                     nullptr, DFFN / 2, DFFN, EE, outp, nullptr, nullptr,
                     blockIdx.y * 128, blockIdx.x * 128);
}

__global__ __launch_bounds__(256) void gemm_mma_qkv(
    const __nv_bfloat16* __restrict__ hhi, const __nv_bfloat16* __restrict__ hlo,
    const __nv_bfloat16* __restrict__ wqh, const __nv_bfloat16* __restrict__ wql,
    const __nv_bfloat16* __restrict__ wkh, const __nv_bfloat16* __restrict__ wkl,
    const __nv_bfloat16* __restrict__ wvh, const __nv_bfloat16* __restrict__ wvl,
    const float* __restrict__ bq, const float* __restrict__ bk, const float* __restrict__ bv,
    __nv_bfloat16* qh, __nv_bfloat16* ql, __nv_bfloat16* kh, __nv_bfloat16* kl,
    __nv_bfloat16* vh, __nv_bfloat16* vl)
{
    const __nv_bfloat16 *Bh, *Bl; const float* bi; __nv_bfloat16 *Ch, *Cl;
    if (blockIdx.z == 0)      { Bh = wqh; Bl = wql; bi = bq; Ch = qh; Cl = ql; }
    else if (blockIdx.z == 1) { Bh = wkh; Bl = wkl; bi = bk; Ch = kh; Cl = kl; }
    else                      { Bh = wvh; Bl = wvl; bi = bv; Ch = vh; Cl = vl; }
    gemm_mma_body<3>(hhi, hlo, Bh, Bl, bi, EE, EE, EE, nullptr, Ch, Cl,
                     blockIdx.y * 128, blockIdx.x * 128);
}

// ---------------- Flash attention on mma.sync + compacted keys ---------------
__global__ __launch_bounds__(256) void flash_attn_mma(
    const __nv_bfloat16* __restrict__ qh_g, const __nv_bfloat16* __restrict__ ql_g,
    float* __restrict__ out)
{
    extern __shared__ char fsm[];
    uint32_t sQh = smem_u32(fsm);
    uint32_t sQl = sQh + FB_Q_BYTES;
    uint32_t sKV = sQl + FB_Q_BYTES;

    int tid = threadIdx.x, lane = tid & 31, warp = tid >> 5;
    int g = lane >> 2, tg = lane & 3;
    int q0 = blockIdx.x * 128;
    int h  = blockIdx.y;
    int b  = blockIdx.z;
    int hoff = h * DDIM;
    size_t bS = (size_t)b * SEQ;

    int cnt = g_cnt[b];
    const int T = (cnt + 31) >> 5;

    {
        int row = tid >> 3, seg = tid & 7;
        #pragma unroll
        for (int i = 0; i < 4; i++) {
            int r = row + i * 32;
            uint32_t so = (uint32_t)r * FB_STRIDE_B + seg * 16;
            size_t ga = (bS + q0 + r) * EE + hoff + seg * 8;
            cp16(sQh + so, qh_g + ga);
            cp16(sQl + so, ql_g + ga);
        }
        uint32_t so = (uint32_t)(tid >> 3) * FB_STRIDE_B + seg * 16;
        size_t gk = (bS + (tid >> 3)) * EE + hoff + seg * 8;
        cp16(sKV + 0*FB_KV_MAT + so, g_ckh + gk);
        cp16(sKV + 1*FB_KV_MAT + so, g_ckl + gk);
        cp16(sKV + 2*FB_KV_MAT + so, g_cvh + gk);
        cp16(sKV + 3*FB_KV_MAT + so, g_cvl + gk);
        cp_commit();
    }
    cp_wait0();
    __syncthreads();

    uint32_t qfh[4][4], qfl[4][4];
    {
        uint32_t base = (uint32_t)(warp*16 + ((lane>>3)&1)*8 + (lane&7)) * FB_STRIDE_B
                      + (lane>>4)*16;
        #pragma unroll
        for (int ks = 0; ks < 4; ks++) {
            ldmx4(qfh[ks], sQh + base + ks*32);
            ldmx4(qfl[ks], sQl + base + ks*32);
        }
    }

    float accO[8][4];
    #pragma unroll
    for (int j = 0; j < 8; j++)
        #pragma unroll
        for (int c = 0; c < 4; c++) accO[j][c] = 0.f;
    float mOld0 = -1e30f, mOld1 = -1e30f, l0 = 0.f, l1 = 0.f;

    uint32_t kAddrBase = (uint32_t)(((lane>>4)*8 + (lane&7)) * FB_STRIDE_B)
                       + ((lane>>3)&1)*16;
    uint32_t vAddrBase = (uint32_t)((((lane>>3)&1)*8 + (lane&7)) * FB_STRIDE_B)
                       + (lane>>4)*16;

    for (int it = 0; it < T; it++) {
        if (it + 1 < T) {
            uint32_t stg2 = sKV + ((it+1) & 1) * FB_STAGE;
            int seg = tid & 7;
            uint32_t so = (uint32_t)(tid >> 3) * FB_STRIDE_B + seg * 16;
            size_t gk = (bS + (it+1)*32 + (tid >> 3)) * EE + hoff + seg * 8;
            cp16(stg2 + 0*FB_KV_MAT + so, g_ckh + gk);
            cp16(stg2 + 1*FB_KV_MAT + so, g_ckl + gk);
            cp16(stg2 + 2*FB_KV_MAT + so, g_cvh + gk);
            cp16(stg2 + 3*FB_KV_MAT + so, g_cvl + gk);
            cp_commit();
            cp_wait1();
        } else {
            cp_wait0();
        }
        __syncthreads();

        uint32_t stg = sKV + (it & 1) * FB_STAGE;

        float accS[4][4];
        #pragma unroll
        for (int j = 0; j < 4; j++)
            #pragma unroll
            for (int c = 0; c < 4; c++) accS[j][c] = 0.f;
        #pragma unroll
        for (int ks = 0; ks < 4; ks++) {
            uint32_t bh[2][4], bl[2][4];
            #pragma unroll
            for (int p = 0; p < 2; p++) {
                uint32_t ad = stg + kAddrBase + (uint32_t)p*16*FB_STRIDE_B + ks*32;
                ldmx4(bh[p], ad);
                ldmx4(bl[p], ad + FB_KV_MAT);
            }
            #pragma unroll
            for (int j = 0; j < 4; j++) {
                const uint32_t* bhp = &bh[j>>1][(j&1)*2];
                const uint32_t* blp = &bl[j>>1][(j&1)*2];
                mma_bf16(accS[j], qfh[ks], bhp);
                mma_bf16(accS[j], qfh[ks], blp);
                mma_bf16(accS[j], qfl[ks], bhp);
            }
        }

        int lim = cnt - it*32;
        if (lim >= 32) {
            #pragma unroll
            for (int j = 0; j < 4; j++) {
                accS[j][0] *= 0.125f; accS[j][1] *= 0.125f;
                accS[j][2] *= 0.125f; accS[j][3] *= 0.125f;
            }
        } else {
            #pragma unroll
            for (int j = 0; j < 4; j++) {
                int n0 = j*8 + tg*2;
                bool k0 = n0 < lim, k1 = (n0 + 1) < lim;
                accS[j][0] = k0 ? accS[j][0]*0.125f : -1e30f;
                accS[j][1] = k1 ? accS[j][1]*0.125f : -1e30f;
                accS[j][2] = k0 ? accS[j][2]*0.125f : -1e30f;
                accS[j][3] = k1 ? accS[j][3]*0.125f : -1e30f;
            }
        }
        float mx0 = -1e30f, mx1 = -1e30f;
        #pragma unroll
        for (int j = 0; j < 4; j++) {
            mx0 = fmaxf(mx0, fmaxf(accS[j][0], accS[j][1]));
            mx1 = fmaxf(mx1, fmaxf(accS[j][2], accS[j][3]));
        }
        mx0 = fmaxf(mx0, __shfl_xor_sync(0xffffffffu, mx0, 1));
        mx0 = fmaxf(mx0, __shfl_xor_sync(0xffffffffu, mx0, 2));
        mx1 = fmaxf(mx1, __shfl_xor_sync(0xffffffffu, mx1, 1));
        mx1 = fmaxf(mx1, __shfl_xor_sync(0xffffffffu, mx1, 2));
        float mn0 = fmaxf(mOld0, mx0), mn1 = fmaxf(mOld1, mx1);
        float scl0 = __expf(mOld0 - mn0), scl1 = __expf(mOld1 - mn1);
        float p[4][4];
        float ls0 = 0.f, ls1 = 0.f;
        #pragma unroll
        for (int j = 0; j < 4; j++) {
            p[j][0] = __expf(accS[j][0] - mn0);
            p[j][1] = __expf(accS[j][1] - mn0);
            p[j][2] = __expf(accS[j][2] - mn1);
            p[j][3] = __expf(accS[j][3] - mn1);
            ls0 += p[j][0] + p[j][1];
            ls1 += p[j][2] + p[j][3];
        }
        ls0 += __shfl_xor_sync(0xffffffffu, ls0, 1);
        ls0 += __shfl_xor_sync(0xffffffffu, ls0, 2);
        ls1 += __shfl_xor_sync(0xffffffffu, ls1, 1);
        ls1 += __shfl_xor_sync(0xffffffffu, ls1, 2);
        l0 = l0 * scl0 + ls0;
        l1 = l1 * scl1 + ls1;
        mOld0 = mn0; mOld1 = mn1;
        #pragma unroll
        for (int j = 0; j < 8; j++) {
            accO[j][0] *= scl0; accO[j][1] *= scl0;
            accO[j][2] *= scl1; accO[j][3] *= scl1;
        }

        uint32_t aph[2][4], apl[2][4];
        #pragma unroll
        for (int jj = 0; jj < 2; jj++) {
            int t0 = 2*jj, t1 = 2*jj + 1;
            pack_hilo(p[t0][0], p[t0][1], aph[jj][0], apl[jj][0]);
            pack_hilo(p[t0][2], p[t0][3], aph[jj][1], apl[jj][1]);
            pack_hilo(p[t1][0], p[t1][1], aph[jj][2], apl[jj][2]);
            pack_hilo(p[t1][2], p[t1][3], aph[jj][3], apl[jj][3]);
        }

        #pragma unroll
        for (int ks2 = 0; ks2 < 2; ks2++) {
            uint32_t vh2[4][4], vl2[4][4];
            #pragma unroll
            for (int ng = 0; ng < 4; ng++) {
                uint32_t ad = stg + 2*FB_KV_MAT + vAddrBase
                            + (uint32_t)ks2*16*FB_STRIDE_B + ng*32;
                ldmx4t(vh2[ng], ad);
                ldmx4t(vl2[ng], ad + FB_KV_MAT);
            }
            #pragma unroll
            for (int jd = 0; jd < 8; jd++) {
                const uint32_t* bvh = &vh2[jd>>1][(jd&1)*2];
                const uint32_t* bvl = &vl2[jd>>1][(jd&1)*2];
                mma_bf16(accO[jd], aph[ks2], bvh);
                mma_bf16(accO[jd], aph[ks2], bvl);
                mma_bf16(accO[jd], apl[ks2], bvh);
            }
        }
        __syncthreads();
    }

    float inv0 = 1.f / l0, inv1 = 1.f / l1;
    size_t row0 = bS + q0 + warp*16 + g;
    #pragma unroll
    for (int jd = 0; jd < 8; jd++) {
        int c = hoff + jd*8 + tg*2;
        float2 o0; o0.x = accO[jd][0] * inv0; o0.y = accO[jd][1] * inv0;
        float2 o1; o1.x = accO[jd][2] * inv1; o1.y = accO[jd][3] * inv1;
        *(float2*)&out[row0 * EE + c]       = o0;
        *(float2*)&out[(row0 + 8) * EE + c] = o1;
    }
}

// ---------------- misc ------------------------------------------------------
__global__ void copy_f4(const float4* __restrict__ in, float4* __restrict__ out, int n4) {
    int i = blockIdx.x * blockDim.x + threadIdx.x;
    if (i < n4) out[i] = in[i];
}

// ---------------- launch ----------------------------------------------------
extern "C" void kernel_launch(void* const* d_in, const int* in_sizes, int n_in,
                              void* d_out, int out_size) {
    const float* x_in = (const float*)d_in[0];
    const int* mask = (const int*)d_in[1];
    const float* wq = (const float*)d_in[2];
    const float* bq = (const float*)d_in[3];
    const float* wk = (const float*)d_in[4];
    const float* bk = (const float*)d_in[5];
    const float* wv = (const float*)d_in[6];
    const float* bv = (const float*)d_in[7];
    const float* g1 = (const float*)d_in[8];
    const float* b1 = (const float*)d_in[9];
    const float* g2 = (const float*)d_in[10];
    const float* b2 = (const float*)d_in[11];
    const float* gf = (const float*)d_in[12];
    const float* bf = (const float*)d_in[13];
    const float* W1 = (const float*)d_in[14];
    const float* B1 = (const float*)d_in[15];
    const float* W2 = (const float*)d_in[16];
    const float* B2 = (const float*)d_in[17];
    float* outp = (float*)d_out;

    float *px, *pattn, *ppart;
    __nv_bfloat16 *pqh, *pql, *pkh, *pkl, *pvh, *pvl;
    __nv_bfloat16 *phhi, *phlo, *pfhi, *pflo;
    __nv_bfloat16 *pwqh, *pwql, *pwkh, *pwkl, *pwvh, *pwvl, *pW1h, *pW1l, *pW2h, *pW2l;
    cudaGetSymbolAddress((void**)&px,    g_x);
    cudaGetSymbolAddress((void**)&pattn, g_attn);
    cudaGetSymbolAddress((void**)&ppart, g_part);
    cudaGetSymbolAddress((void**)&pqh,   g_qhi);
    cudaGetSymbolAddress((void**)&pql,   g_qlo);
    cudaGetSymbolAddress((void**)&pkh,   g_khi);
    cudaGetSymbolAddress((void**)&pkl,   g_klo);
    cudaGetSymbolAddress((void**)&pvh,   g_vhi);
    cudaGetSymbolAddress((void**)&pvl,   g_vlo);
    cudaGetSymbolAddress((void**)&phhi,  g_hhi);
    cudaGetSymbolAddress((void**)&phlo,  g_hlo);
    cudaGetSymbolAddress((void**)&pfhi,  g_fhi);
    cudaGetSymbolAddress((void**)&pflo,  g_flo);
    cudaGetSymbolAddress((void**)&pwqh,  g_wqhi);
    cudaGetSymbolAddress((void**)&pwql,  g_wqlo);
    cudaGetSymbolAddress((void**)&pwkh,  g_wkhi);
    cudaGetSymbolAddress((void**)&pwkl,  g_wklo);
    cudaGetSymbolAddress((void**)&pwvh,  g_wvhi);
    cudaGetSymbolAddress((void**)&pwvl,  g_wvlo);
    cudaGetSymbolAddress((void**)&pW1h,  g_W1hi);
    cudaGetSymbolAddress((void**)&pW1l,  g_W1lo);
    cudaGetSymbolAddress((void**)&pW2h,  g_W2hi);
    cudaGetSymbolAddress((void**)&pW2l,  g_W2lo);

    cudaFuncSetAttribute(flash_attn_mma,
                         cudaFuncAttributeMaxDynamicSharedMemorySize, FB_SMEM);
    cudaFuncSetAttribute(gemm_mma_qkv,
                         cudaFuncAttributeMaxDynamicSharedMemorySize, GM_SMEM);
    cudaFuncSetAttribute(gemm_mma<1>,
                         cudaFuncAttributeMaxDynamicSharedMemorySize, GM_SMEM);
    cudaFuncSetAttribute(gemm_mma_splitk,
                         cudaFuncAttributeMaxDynamicSharedMemorySize, GM_SMEM);

    {
        int n4 = NROWS * EE / 4;
        copy_f4<<<(n4 + 255) / 256, 256>>>((const float4*)x_in, (float4*)px, n4);
    }
    {
        int nq4 = NLAYERS * EE * EE / 4;
        cvt_kernel<<<(nq4 + 255) / 256, 256>>>((const float4*)wq,
            (__nv_bfloat162*)pwqh, (__nv_bfloat162*)pwql, nq4);
        cvt_kernel<<<(nq4 + 255) / 256, 256>>>((const float4*)wk,
            (__nv_bfloat162*)pwkh, (__nv_bfloat162*)pwkl, nq4);
        cvt_kernel<<<(nq4 + 255) / 256, 256>>>((const float4*)wv,
            (__nv_bfloat162*)pwvh, (__nv_bfloat162*)pwvl, nq4);
        int n14 = DFFN * EE / 4;
        cvt_kernel<<<(n14 + 255) / 256, 256>>>((const float4*)W1,
            (__nv_bfloat162*)pW1h, (__nv_bfloat162*)pW1l, n14);
        cvt_kernel<<<(n14 + 255) / 256, 256>>>((const float4*)W2,
            (__nv_bfloat162*)pW2h, (__nv_bfloat162*)pW2l, n14);
    }
    compact_idx<<<BB, 1024>>>(mask);       // mask is layer-invariant

    dim3 gQKV(EE / 128, NROWS / 128, 3);   // (4, 32, 3)
    dim3 gFF1(DFFN / 128, NROWS / 128);    // (16, 32)
    dim3 gFF2(EE / 128, NROWS / 128, 2);   // (4, 32, 2) split-K
    dim3 gAtt(SEQ / 128, HH, BB);          // (16, 8, 2)
    dim3 gCpy(SEQ, BB);
    int nred = (NROWS * EE / 4 + 255) / 256;

    for (int l = 0; l < NLAYERS; l++) {
        const __nv_bfloat16* wqh = pwqh + (size_t)l * EE * EE;
        const __nv_bfloat16* wql = pwql + (size_t)l * EE * EE;
        const __nv_bfloat16* wkh = pwkh + (size_t)l * EE * EE;
        const __nv_bfloat16* wkl = pwkl + (size_t)l * EE * EE;
        const __nv_bfloat16* wvh = pwvh + (size_t)l * EE * EE;
        const __nv_bfloat16* wvl = pwvl + (size_t)l * EE * EE;
        const float* bql = bq + (size_t)l * EE;
        const float* bkl = bk + (size_t)l * EE;
        const float* bvl = bv + (size_t)l * EE;

        ln_bf16<<<NROWS, 128>>>(px, phhi, phlo, g1, b1);
        gemm_mma_qkv<<<gQKV, 256, GM_SMEM>>>(phhi, phlo,
            wqh, wql, wkh, wkl, wvh, wvl, bql, bkl, bvl,
            pqh, pql, pkh, pkl, pvh, pvl);
        compact_copy<<<gCpy, 256>>>(pkh, pkl, pvh, pvl);
        flash_attn_mma<<<gAtt, 256, FB_SMEM>>>(pqh, pql, pattn);
        fuse_attn_res_ln<<<NROWS, 128>>>(pattn, px, phhi, phlo, g2, b2);
        gemm_mma<1><<<gFF1, 256, GM_SMEM>>>(phhi, phlo, pW1h, pW1l,
            B1, EE, DFFN, nullptr, pfhi, pflo);
        gemm_mma_splitk<<<gFF2, 256, GM_SMEM>>>(pfhi, pflo, pW2h, pW2l, ppart);
        reduce_ff2<<<nred, 256>>>(px, ppart, B2);
    }
    ln_f32<<<NROWS, 128>>>(px, outp, gf, bf);
}

// round 12
// speedup vs baseline: 1.0441x; 1.0441x over previous
#include <cuda_runtime.h>
#include <cuda_bf16.h>
#include <stdint.h>

#define BB      2
#define SEQ     2048
#define EE      512
#define HH      8
#define DDIM    64
#define NLAYERS 2
#define DFFN    2048
#define NROWS   4096   // BB*SEQ

// mma.sync GEMM config: 128x128 tile, K-chunk 32 (bf16), hi/lo x3 passes
#define GM_CHUNK     32
#define GM_STRIDE    80
#define GM_MAT_BYTES (128 * GM_STRIDE)
#define GM_BUF_BYTES (4 * GM_MAT_BYTES)
#define GM_SMEM      (2 * GM_BUF_BYTES)

// flash mma config: BQ=128, BK=32, 8 warps (16 q-rows each)
#define FB_STRIDE_B  144                   // 64 bf16 = 128B + 16B pad
#define FB_Q_BYTES   (128 * FB_STRIDE_B)   // 18432 per matrix (hi or lo)
#define FB_KV_MAT    (32 * FB_STRIDE_B)    // 4608
#define FB_STAGE     (4 * FB_KV_MAT)       // Kh,Kl,Vh,Vl = 18432
#define FB_SMEM      (2*FB_Q_BYTES + 2*FB_STAGE + 256)

// ---------------- scratch (device globals) ----------------------------------
__device__ float g_x[NROWS * EE];
__device__ float g_attn[NROWS * EE];
__device__ __nv_bfloat16 g_qhi[NROWS*EE], g_qlo[NROWS*EE];
__device__ __nv_bfloat16 g_khi[NROWS*EE], g_klo[NROWS*EE];
__device__ __nv_bfloat16 g_vhi[NROWS*EE], g_vlo[NROWS*EE];
__device__ __nv_bfloat16 g_ckh[NROWS*EE], g_ckl[NROWS*EE];   // compacted K hi/lo
__device__ __nv_bfloat16 g_cvh[NROWS*EE], g_cvl[NROWS*EE];   // compacted V hi/lo
__device__ int g_cnt[BB];
__device__ int g_cidx[BB*SEQ];
__device__ __nv_bfloat16 g_hhi[NROWS * EE];
__device__ __nv_bfloat16 g_hlo[NROWS * EE];
__device__ __nv_bfloat16 g_fhi[NROWS * DFFN];
__device__ __nv_bfloat16 g_flo[NROWS * DFFN];
__device__ __nv_bfloat16 g_wqhi[NLAYERS*EE*EE], g_wqlo[NLAYERS*EE*EE];
__device__ __nv_bfloat16 g_wkhi[NLAYERS*EE*EE], g_wklo[NLAYERS*EE*EE];
__device__ __nv_bfloat16 g_wvhi[NLAYERS*EE*EE], g_wvlo[NLAYERS*EE*EE];
__device__ __nv_bfloat16 g_W1hi[DFFN*EE], g_W1lo[DFFN*EE];
__device__ __nv_bfloat16 g_W2hi[EE*DFFN], g_W2lo[EE*DFFN];

// ---------------- PTX helpers ------------------------------------------------
__device__ __forceinline__ uint32_t smem_u32(const void* p) {
    uint32_t a;
    asm("{ .reg .u64 t; cvta.to.shared.u64 t, %1; cvt.u32.u64 %0, t; }" : "=r"(a) : "l"(p));
    return a;
}
__device__ __forceinline__ void cp16(uint32_t saddr, const void* g) {
    asm volatile("cp.async.cg.shared.global [%0], [%1], 16;" :: "r"(saddr), "l"(g));
}
__device__ __forceinline__ void cp_commit() {
    asm volatile("cp.async.commit_group;" ::: "memory");
}
__device__ __forceinline__ void cp_wait0() {
    asm volatile("cp.async.wait_group 0;" ::: "memory");
}
__device__ __forceinline__ void cp_wait1() {
    asm volatile("cp.async.wait_group 1;" ::: "memory");
}
__device__ __forceinline__ void ldmx4(uint32_t* r, uint32_t addr) {
    asm volatile("ldmatrix.sync.aligned.m8n8.x4.shared.b16 {%0,%1,%2,%3}, [%4];"
        : "=r"(r[0]), "=r"(r[1]), "=r"(r[2]), "=r"(r[3]) : "r"(addr));
}
__device__ __forceinline__ void ldmx4t(uint32_t* r, uint32_t addr) {
    asm volatile("ldmatrix.sync.aligned.m8n8.x4.trans.shared.b16 {%0,%1,%2,%3}, [%4];"
        : "=r"(r[0]), "=r"(r[1]), "=r"(r[2]), "=r"(r[3]) : "r"(addr));
}
__device__ __forceinline__ void mma_bf16(float* d, const uint32_t* a, const uint32_t* b) {
    asm volatile(
        "mma.sync.aligned.m16n8k16.row.col.f32.bf16.bf16.f32 "
        "{%0,%1,%2,%3}, {%4,%5,%6,%7}, {%8,%9}, {%0,%1,%2,%3};"
        : "+f"(d[0]), "+f"(d[1]), "+f"(d[2]), "+f"(d[3])
        : "r"(a[0]), "r"(a[1]), "r"(a[2]), "r"(a[3]), "r"(b[0]), "r"(b[1]));
}

// ---------------- hi/lo split ------------------------------------------------
__device__ __forceinline__ void split_bf16(float v, __nv_bfloat16& h, __nv_bfloat16& l) {
    h = __float2bfloat16(v);
    l = __float2bfloat16(v - __bfloat162float(h));
}
__device__ __forceinline__ void pack_hilo(float a, float b, uint32_t& h, uint32_t& l) {
    __nv_bfloat162 hp, lp;
    hp.x = __float2bfloat16(a);
    hp.y = __float2bfloat16(b);
    lp.x = __float2bfloat16(a - __bfloat162float(hp.x));
    lp.y = __float2bfloat16(b - __bfloat162float(hp.y));
    h = *reinterpret_cast<uint32_t*>(&hp);
    l = *reinterpret_cast<uint32_t*>(&lp);
}

// ---------------- reductions -------------------------------------------------
__device__ __forceinline__ void block_reduce2(float& s, float& s2) {
    __shared__ float shm[8];
    #pragma unroll
    for (int o = 16; o > 0; o >>= 1) {
        s  += __shfl_down_sync(0xffffffffu, s,  o);
        s2 += __shfl_down_sync(0xffffffffu, s2, o);
    }
    int w = threadIdx.x >> 5;
    __syncthreads();
    if ((threadIdx.x & 31) == 0) { shm[w] = s; shm[4 + w] = s2; }
    __syncthreads();
    s  = shm[0] + shm[1] + shm[2] + shm[3];
    s2 = shm[4] + shm[5] + shm[6] + shm[7];
}

// ---------------- LayerNorm variants ----------------------------------------
__global__ void ln_f32(const float* __restrict__ in, float* __restrict__ outp,
                       const float* __restrict__ g, const float* __restrict__ b) {
    int row = blockIdx.x, t = threadIdx.x;
    const float* xr = in + (size_t)row * EE;
    float v[4], s = 0.f, s2 = 0.f;
    #pragma unroll
    for (int i = 0; i < 4; i++) { v[i] = xr[t + i*128]; s += v[i]; s2 += v[i]*v[i]; }
    block_reduce2(s, s2);
    float mu = s * (1.f/EE), var = s2 * (1.f/EE) - mu*mu, r = rsqrtf(var + 1e-5f);
    #pragma unroll
    for (int i = 0; i < 4; i++) {
        int idx = t + i*128;
        outp[(size_t)row*EE + idx] = (v[i]-mu)*r*g[idx] + b[idx];
    }
}
__global__ void ln_bf16(const float* __restrict__ in,
                        __nv_bfloat16* __restrict__ hi, __nv_bfloat16* __restrict__ lo,
                        const float* __restrict__ g, const float* __restrict__ b) {
    int row = blockIdx.x, t = threadIdx.x;
    const float* xr = in + (size_t)row * EE;
    float v[4], s = 0.f, s2 = 0.f;
    #pragma unroll
    for (int i = 0; i < 4; i++) { v[i] = xr[t + i*128]; s += v[i]; s2 += v[i]*v[i]; }
    block_reduce2(s, s2);
    float mu = s * (1.f/EE), var = s2 * (1.f/EE) - mu*mu, r = rsqrtf(var + 1e-5f);
    #pragma unroll
    for (int i = 0; i < 4; i++) {
        int idx = t + i*128;
        float y = (v[i]-mu)*r*g[idx] + b[idx];
        __nv_bfloat16 h, l; split_bf16(y, h, l);
        hi[(size_t)row*EE + idx] = h;
        lo[(size_t)row*EE + idx] = l;
    }
}
__global__ void fuse_attn_res_ln(const float* __restrict__ attn, float* x,
                                 __nv_bfloat16* __restrict__ hhi, __nv_bfloat16* __restrict__ hlo,
                                 const float* __restrict__ g2, const float* __restrict__ b2) {
    int row = blockIdx.x, t = threadIdx.x;
    const float* ar = attn + (size_t)row * EE;
    float a[4], s = 0.f, s2 = 0.f;
    #pragma unroll
    for (int i = 0; i < 4; i++) { a[i] = ar[t + i*128]; s += a[i]; s2 += a[i]*a[i]; }
    block_reduce2(s, s2);
    float mu = s * (1.f/EE), var = s2 * (1.f/EE) - mu*mu, r = rsqrtf(var + 1e-5f);
    float xv[4];
    s = 0.f; s2 = 0.f;
    #pragma unroll
    for (int i = 0; i < 4; i++) {
        int idx = t + i*128;
        float y = (a[i]-mu)*r*g2[idx] + b2[idx];
        float xn = x[(size_t)row*EE + idx] + y;
        x[(size_t)row*EE + idx] = xn;
        xv[i] = xn; s += xn; s2 += xn*xn;
    }
    block_reduce2(s, s2);
    float mu2 = s * (1.f/EE), var2 = s2 * (1.f/EE) - mu2*mu2, r2 = rsqrtf(var2 + 1e-5f);
    #pragma unroll
    for (int i = 0; i < 4; i++) {
        int idx = t + i*128;
        float y = (xv[i]-mu2)*r2;
        __nv_bfloat16 h, l; split_bf16(y, h, l);
        hhi[(size_t)row*EE + idx] = h;
        hlo[(size_t)row*EE + idx] = l;
    }
}

// ---------------- weight fp32 -> bf16 hi/lo (vectorized) ---------------------
__global__ void cvt_kernel(const float4* __restrict__ in,
                           __nv_bfloat162* __restrict__ hi, __nv_bfloat162* __restrict__ lo,
                           int n4) {
    int i = blockIdx.x * blockDim.x + threadIdx.x;
    if (i < n4) {
        float4 v = in[i];
        uint32_t h0, l0, h1, l1;
        pack_hilo(v.x, v.y, h0, l0);
        pack_hilo(v.z, v.w, h1, l1);
        hi[2*i]   = *reinterpret_cast<__nv_bfloat162*>(&h0);
        hi[2*i+1] = *reinterpret_cast<__nv_bfloat162*>(&h1);
        lo[2*i]   = *reinterpret_cast<__nv_bfloat162*>(&l0);
        lo[2*i+1] = *reinterpret_cast<__nv_bfloat162*>(&l1);
    }
}

// ---------------- mask compaction --------------------------------------------
__global__ __launch_bounds__(1024) void compact_idx(const int* __restrict__ mask) {
    __shared__ int part[1024];
    int b = blockIdx.x, t = threadIdx.x;
    const int* mb = mask + (size_t)b * SEQ;
    int v0 = (mb[2*t]   == 0);
    int v1 = (mb[2*t+1] == 0);
    part[t] = v0 + v1;
    __syncthreads();
    for (int o = 1; o < 1024; o <<= 1) {
        int x = part[t];
        int y = (t >= o) ? part[t-o] : 0;
        __syncthreads();
        part[t] = x + y;
        __syncthreads();
    }
    int incl = part[t];
    int excl = incl - (v0 + v1);
    if (v0) g_cidx[b*SEQ + excl]      = 2*t;
    if (v1) g_cidx[b*SEQ + excl + v0] = 2*t+1;
    if (t == 1023) g_cnt[b] = incl;
}

__global__ __launch_bounds__(256) void compact_copy(
    const __nv_bfloat16* __restrict__ kh, const __nv_bfloat16* __restrict__ kl,
    const __nv_bfloat16* __restrict__ vh, const __nv_bfloat16* __restrict__ vl) {
    int b = blockIdx.y, j = blockIdx.x, t = threadIdx.x;
    int cnt = g_cnt[b];
    int lim = (cnt + 31) & ~31;
    if (j >= lim) return;
    int m = t >> 6, c = t & 63;
    size_t dst = ((size_t)b * SEQ + j) * EE + c * 8;
    const __nv_bfloat16* sp;
    __nv_bfloat16* dp;
    if      (m == 0) dp = g_ckh;
    else if (m == 1) dp = g_ckl;
    else if (m == 2) dp = g_cvh;
    else             dp = g_cvl;
    if (j < cnt) {
        int src = g_cidx[b*SEQ + j];
        size_t sof = ((size_t)b * SEQ + src) * EE + c * 8;
        if      (m == 0) sp = kh;
        else if (m == 1) sp = kl;
        else if (m == 2) sp = vh;
        else             sp = vl;
        *(uint4*)(dp + dst) = *(const uint4*)(sp + sof);
    } else {
        uint4 z; z.x = 0; z.y = 0; z.z = 0; z.w = 0;
        *(uint4*)(dp + dst) = z;
    }
}

// ---------------- mma.sync GEMM ----------------------------------------------
// MODE 1: bias+relu -> bf16 hi/lo. MODE 2: fp32+bias+residual. MODE 3: bias -> bf16 hi/lo.
// Pass-reordered inner loop: 16 independent accumulators per pass (no HMMA RAW chains).
template<int MODE>
__device__ __forceinline__ void gemm_mma_body(
    const __nv_bfloat16* __restrict__ Ahi, const __nv_bfloat16* __restrict__ Alo,
    const __nv_bfloat16* __restrict__ Bhi, const __nv_bfloat16* __restrict__ Blo,
    const float* __restrict__ bias, int K, int N,
    float* __restrict__ Cf, __nv_bfloat16* __restrict__ Chi, __nv_bfloat16* __restrict__ Clo,
    const float* __restrict__ res, int rowBase, int colBase)
{
    extern __shared__ char sm8[];
    uint32_t sbase = smem_u32(sm8);
    int tid = threadIdx.x, lane = tid & 31, warp = tid >> 5;
    int wm = warp >> 2, wn = warp & 3;

    float acc[4][4][4];
    #pragma unroll
    for (int i = 0; i < 4; i++)
        #pragma unroll
        for (int j = 0; j < 4; j++)
            #pragma unroll
            for (int c = 0; c < 4; c++) acc[i][j][c] = 0.f;

    uint32_t aAddr = (uint32_t)((wm*64 + ((lane>>3)&1)*8 + (lane&7)) * GM_STRIDE
                                + (lane>>4)*16);
    uint32_t bAddr = (uint32_t)((wn*32 + (lane>>4)*8 + (lane&7)) * GM_STRIDE
                                + ((lane>>3)&1)*16);

    const int T = K / GM_CHUNK;
    int lrow0 = tid >> 2, lseg = tid & 3;

    {
        uint32_t sb = sbase;
        #pragma unroll
        for (int j = 0; j < 2; j++) {
            int row = lrow0 + j*64;
            uint32_t so = row*GM_STRIDE + lseg*16;
            size_t ga = (size_t)(rowBase+row)*K + lseg*8;
            size_t gb = (size_t)(colBase+row)*K + lseg*8;
            cp16(sb + 0*GM_MAT_BYTES + so, Ahi + ga);
            cp16(sb + 1*GM_MAT_BYTES + so, Alo + ga);
            cp16(sb + 2*GM_MAT_BYTES + so, Bhi + gb);
            cp16(sb + 3*GM_MAT_BYTES + so, Blo + gb);
        }
        cp_commit();
    }

    for (int t = 0; t < T; t++) {
        cp_wait0();
        __syncthreads();
        if (t + 1 < T) {
            uint32_t sb = sbase + ((t+1) & 1) * GM_BUF_BYTES;
            int koff = (t+1) * GM_CHUNK;
            #pragma unroll
            for (int j = 0; j < 2; j++) {
                int row = lrow0 + j*64;
                uint32_t so = row*GM_STRIDE + lseg*16;
                size_t ga = (size_t)(rowBase+row)*K + koff + lseg*8;
                size_t gb = (size_t)(colBase+row)*K + koff + lseg*8;
                cp16(sb + 0*GM_MAT_BYTES + so, Ahi + ga);
                cp16(sb + 1*GM_MAT_BYTES + so, Alo + ga);
                cp16(sb + 2*GM_MAT_BYTES + so, Bhi + gb);
                cp16(sb + 3*GM_MAT_BYTES + so, Blo + gb);
            }
            cp_commit();
        }
        uint32_t buf = sbase + (t & 1) * GM_BUF_BYTES;
        #pragma unroll
        for (int ks = 0; ks < 2; ks++) {
            uint32_t ah[4][4], al[4][4], bh[2][4], bl[2][4];
            #pragma unroll
            for (int i = 0; i < 4; i++) {
                uint32_t ad = buf + aAddr + i*16*GM_STRIDE + ks*32;
                ldmx4(ah[i], ad);
                ldmx4(al[i], ad + GM_MAT_BYTES);
            }
            #pragma unroll
            for (int p = 0; p < 2; p++) {
                uint32_t bd = buf + 2*GM_MAT_BYTES + bAddr + p*16*GM_STRIDE + ks*32;
                ldmx4(bh[p], bd);
                ldmx4(bl[p], bd + GM_MAT_BYTES);
            }
            // pass 1: Ahi x Bhi (16 independent accumulators)
            #pragma unroll
            for (int i = 0; i < 4; i++)
                #pragma unroll
                for (int j = 0; j < 4; j++)
                    mma_bf16(acc[i][j], ah[i], &bh[j>>1][(j&1)*2]);
            // pass 2: Ahi x Blo
            #pragma unroll
            for (int i = 0; i < 4; i++)
                #pragma unroll
                for (int j = 0; j < 4; j++)
                    mma_bf16(acc[i][j], ah[i], &bl[j>>1][(j&1)*2]);
            // pass 3: Alo x Bhi
            #pragma unroll
            for (int i = 0; i < 4; i++)
                #pragma unroll
                for (int j = 0; j < 4; j++)
                    mma_bf16(acc[i][j], al[i], &bh[j>>1][(j&1)*2]);
        }
    }

    int g = lane >> 2, tg = lane & 3;
    #pragma unroll
    for (int i = 0; i < 4; i++) {
        int r0 = rowBase + wm*64 + i*16 + g;
        #pragma unroll
        for (int j = 0; j < 4; j++) {
            int c = colBase + wn*32 + j*8 + tg*2;
            float b0 = bias[c], b1 = bias[c+1];
            #pragma unroll
            for (int half = 0; half < 2; half++) {
                int r = r0 + half*8;
                float v0 = acc[i][j][half*2+0] + b0;
                float v1 = acc[i][j][half*2+1] + b1;
                if (MODE == 1 || MODE == 3) {
                    if (MODE == 1) { v0 = fmaxf(v0, 0.f); v1 = fmaxf(v1, 0.f); }
                    __nv_bfloat16 h0, l0, h1, l1;
                    split_bf16(v0, h0, l0); split_bf16(v1, h1, l1);
                    __nv_bfloat162 hp; hp.x = h0; hp.y = h1;
                    __nv_bfloat162 lp; lp.x = l0; lp.y = l1;
                    *(__nv_bfloat162*)&Chi[(size_t)r * N + c] = hp;
                    *(__nv_bfloat162*)&Clo[(size_t)r * N + c] = lp;
                } else {
                    if (MODE == 2) {
                        float2 rv = *(const float2*)&res[(size_t)r * N + c];
                        v0 += rv.x; v1 += rv.y;
                    }
                    float2 o; o.x = v0; o.y = v1;
                    *(float2*)&Cf[(size_t)r * N + c] = o;
                }
            }
        }
    }
}

template<int MODE>
__global__ __launch_bounds__(256, 2) void gemm_mma(
    const __nv_bfloat16* __restrict__ Ahi, const __nv_bfloat16* __restrict__ Alo,
    const __nv_bfloat16* __restrict__ Bhi, const __nv_bfloat16* __restrict__ Blo,
    const float* __restrict__ bias, int K, int N,
    float* __restrict__ Cf, __nv_bfloat16* __restrict__ Chi, __nv_bfloat16* __restrict__ Clo,
    const float* __restrict__ res)
{
    gemm_mma_body<MODE>(Ahi, Alo, Bhi, Blo, bias, K, N, Cf, Chi, Clo, res,
                        blockIdx.y * 128, blockIdx.x * 128);
}

__global__ __launch_bounds__(256, 2) void gemm_mma_qkv(
    const __nv_bfloat16* __restrict__ hhi, const __nv_bfloat16* __restrict__ hlo,
    const __nv_bfloat16* __restrict__ wqh, const __nv_bfloat16* __restrict__ wql,
    const __nv_bfloat16* __restrict__ wkh, const __nv_bfloat16* __restrict__ wkl,
    const __nv_bfloat16* __restrict__ wvh, const __nv_bfloat16* __restrict__ wvl,
    const float* __restrict__ bq, const float* __restrict__ bk, const float* __restrict__ bv,
    __nv_bfloat16* qh, __nv_bfloat16* ql, __nv_bfloat16* kh, __nv_bfloat16* kl,
    __nv_bfloat16* vh, __nv_bfloat16* vl)
{
    const __nv_bfloat16 *Bh, *Bl; const float* bi; __nv_bfloat16 *Ch, *Cl;
    if (blockIdx.z == 0)      { Bh = wqh; Bl = wql; bi = bq; Ch = qh; Cl = ql; }
    else if (blockIdx.z == 1) { Bh = wkh; Bl = wkl; bi = bk; Ch = kh; Cl = kl; }
    else                      { Bh = wvh; Bl = wvl; bi = bv; Ch = vh; Cl = vl; }
    gemm_mma_body<3>(hhi, hlo, Bh, Bl, bi, EE, EE, nullptr, Ch, Cl, nullptr,
                     blockIdx.y * 128, blockIdx.x * 128);
}

// ---------------- Flash attention on mma.sync + compacted keys ---------------
// Pass-reordered mma loops (independent accumulators per pass).
__global__ __launch_bounds__(256) void flash_attn_mma(
    const __nv_bfloat16* __restrict__ qh_g, const __nv_bfloat16* __restrict__ ql_g,
    float* __restrict__ out)
{
    extern __shared__ char fsm[];
    uint32_t sQh = smem_u32(fsm);
    uint32_t sQl = sQh + FB_Q_BYTES;
    uint32_t sKV = sQl + FB_Q_BYTES;

    int tid = threadIdx.x, lane = tid & 31, warp = tid >> 5;
    int g = lane >> 2, tg = lane & 3;
    int q0 = blockIdx.x * 128;
    int h  = blockIdx.y;
    int b  = blockIdx.z;
    int hoff = h * DDIM;
    size_t bS = (size_t)b * SEQ;

    int cnt = g_cnt[b];
    const int T = (cnt + 31) >> 5;

    {
        int row = tid >> 3, seg = tid & 7;
        #pragma unroll
        for (int i = 0; i < 4; i++) {
            int r = row + i * 32;
            uint32_t so = (uint32_t)r * FB_STRIDE_B + seg * 16;
            size_t ga = (bS + q0 + r) * EE + hoff + seg * 8;
            cp16(sQh + so, qh_g + ga);
            cp16(sQl + so, ql_g + ga);
        }
        uint32_t so = (uint32_t)(tid >> 3) * FB_STRIDE_B + seg * 16;
        size_t gk = (bS + (tid >> 3)) * EE + hoff + seg * 8;
        cp16(sKV + 0*FB_KV_MAT + so, g_ckh + gk);
        cp16(sKV + 1*FB_KV_MAT + so, g_ckl + gk);
        cp16(sKV + 2*FB_KV_MAT + so, g_cvh + gk);
        cp16(sKV + 3*FB_KV_MAT + so, g_cvl + gk);
        cp_commit();
    }
    cp_wait0();
    __syncthreads();

    uint32_t qfh[4][4], qfl[4][4];
    {
        uint32_t base = (uint32_t)(warp*16 + ((lane>>3)&1)*8 + (lane&7)) * FB_STRIDE_B
                      + (lane>>4)*16;
        #pragma unroll
        for (int ks = 0; ks < 4; ks++) {
            ldmx4(qfh[ks], sQh + base + ks*32);
            ldmx4(qfl[ks], sQl + base + ks*32);
        }
    }

    float accO[8][4];
    #pragma unroll
    for (int j = 0; j < 8; j++)
        #pragma unroll
        for (int c = 0; c < 4; c++) accO[j][c] = 0.f;
    float mOld0 = -1e30f, mOld1 = -1e30f, l0 = 0.f, l1 = 0.f;

    uint32_t kAddrBase = (uint32_t)(((lane>>4)*8 + (lane&7)) * FB_STRIDE_B)
                       + ((lane>>3)&1)*16;
    uint32_t vAddrBase = (uint32_t)((((lane>>3)&1)*8 + (lane&7)) * FB_STRIDE_B)
                       + (lane>>4)*16;

    for (int it = 0; it < T; it++) {
        if (it + 1 < T) {
            uint32_t stg2 = sKV + ((it+1) & 1) * FB_STAGE;
            int seg = tid & 7;
            uint32_t so = (uint32_t)(tid >> 3) * FB_STRIDE_B + seg * 16;
            size_t gk = (bS + (it+1)*32 + (tid >> 3)) * EE + hoff + seg * 8;
            cp16(stg2 + 0*FB_KV_MAT + so, g_ckh + gk);
            cp16(stg2 + 1*FB_KV_MAT + so, g_ckl + gk);
            cp16(stg2 + 2*FB_KV_MAT + so, g_cvh + gk);
            cp16(stg2 + 3*FB_KV_MAT + so, g_cvl + gk);
            cp_commit();
            cp_wait1();
        } else {
            cp_wait0();
        }
        __syncthreads();

        uint32_t stg = sKV + (it & 1) * FB_STAGE;

        float accS[4][4];
        #pragma unroll
        for (int j = 0; j < 4; j++)
            #pragma unroll
            for (int c = 0; c < 4; c++) accS[j][c] = 0.f;
        #pragma unroll
        for (int ks = 0; ks < 4; ks++) {
            uint32_t bh[2][4], bl[2][4];
            #pragma unroll
            for (int p = 0; p < 2; p++) {
                uint32_t ad = stg + kAddrBase + (uint32_t)p*16*FB_STRIDE_B + ks*32;
                ldmx4(bh[p], ad);
                ldmx4(bl[p], ad + FB_KV_MAT);
            }
            // pass-reordered: 4 independent accs per pass
            #pragma unroll
            for (int j = 0; j < 4; j++)
                mma_bf16(accS[j], qfh[ks], &bh[j>>1][(j&1)*2]);
            #pragma unroll
            for (int j = 0; j < 4; j++)
                mma_bf16(accS[j], qfh[ks], &bl[j>>1][(j&1)*2]);
            #pragma unroll
            for (int j = 0; j < 4; j++)
                mma_bf16(accS[j], qfl[ks], &bh[j>>1][(j&1)*2]);
        }

        int lim = cnt - it*32;
        if (lim >= 32) {
            #pragma unroll
            for (int j = 0; j < 4; j++) {
                accS[j][0] *= 0.125f; accS[j][1] *= 0.125f;
                accS[j][2] *= 0.125f; accS[j][3] *= 0.125f;
            }
        } else {
            #pragma unroll
            for (int j = 0; j < 4; j++) {
                int n0 = j*8 + tg*2;
                bool k0 = n0 < lim, k1 = (n0 + 1) < lim;
                accS[j][0] = k0 ? accS[j][0]*0.125f : -1e30f;
                accS[j][1] = k1 ? accS[j][1]*0.125f : -1e30f;
                accS[j][2] = k0 ? accS[j][2]*0.125f : -1e30f;
                accS[j][3] = k1 ? accS[j][3]*0.125f : -1e30f;
            }
        }
        float mx0 = -1e30f, mx1 = -1e30f;
        #pragma unroll
        for (int j = 0; j < 4; j++) {
            mx0 = fmaxf(mx0, fmaxf(accS[j][0], accS[j][1]));
            mx1 = fmaxf(mx1, fmaxf(accS[j][2], accS[j][3]));
        }
        mx0 = fmaxf(mx0, __shfl_xor_sync(0xffffffffu, mx0, 1));
        mx0 = fmaxf(mx0, __shfl_xor_sync(0xffffffffu, mx0, 2));
        mx1 = fmaxf(mx1, __shfl_xor_sync(0xffffffffu, mx1, 1));
        mx1 = fmaxf(mx1, __shfl_xor_sync(0xffffffffu, mx1, 2));
        float mn0 = fmaxf(mOld0, mx0), mn1 = fmaxf(mOld1, mx1);
        float scl0 = __expf(mOld0 - mn0), scl1 = __expf(mOld1 - mn1);
        float p[4][4];
        float ls0 = 0.f, ls1 = 0.f;
        #pragma unroll
        for (int j = 0; j < 4; j++) {
            p[j][0] = __expf(accS[j][0] - mn0);
            p[j][1] = __expf(accS[j][1] - mn0);
            p[j][2] = __expf(accS[j][2] - mn1);
            p[j][3] = __expf(accS[j][3] - mn1);
            ls0 += p[j][0] + p[j][1];
            ls1 += p[j][2] + p[j][3];
        }
        ls0 += __shfl_xor_sync(0xffffffffu, ls0, 1);
        ls0 += __shfl_xor_sync(0xffffffffu, ls0, 2);
        ls1 += __shfl_xor_sync(0xffffffffu, ls1, 1);
        ls1 += __shfl_xor_sync(0xffffffffu, ls1, 2);
        l0 = l0 * scl0 + ls0;
        l1 = l1 * scl1 + ls1;
        mOld0 = mn0; mOld1 = mn1;
        #pragma unroll
        for (int j = 0; j < 8; j++) {
            accO[j][0] *= scl0; accO[j][1] *= scl0;
            accO[j][2] *= scl1; accO[j][3] *= scl1;
        }

        uint32_t aph[2][4], apl[2][4];
        #pragma unroll
        for (int jj = 0; jj < 2; jj++) {
            int t0 = 2*jj, t1 = 2*jj + 1;
            pack_hilo(p[t0][0], p[t0][1], aph[jj][0], apl[jj][0]);
            pack_hilo(p[t0][2], p[t0][3], aph[jj][1], apl[jj][1]);
            pack_hilo(p[t1][0], p[t1][1], aph[jj][2], apl[jj][2]);
            pack_hilo(p[t1][2], p[t1][3], aph[jj][3], apl[jj][3]);
        }

        #pragma unroll
        for (int ks2 = 0; ks2 < 2; ks2++) {
            uint32_t vh2[4][4], vl2[4][4];
            #pragma unroll
            for (int ng = 0; ng < 4; ng++) {
                uint32_t ad = stg + 2*FB_KV_MAT + vAddrBase
                            + (uint32_t)ks2*16*FB_STRIDE_B + ng*32;
                ldmx4t(vh2[ng], ad);
                ldmx4t(vl2[ng], ad + FB_KV_MAT);
            }
            // pass-reordered: 8 independent accs per pass
            #pragma unroll
            for (int jd = 0; jd < 8; jd++)
                mma_bf16(accO[jd], aph[ks2], &vh2[jd>>1][(jd&1)*2]);
            #pragma unroll
            for (int jd = 0; jd < 8; jd++)
                mma_bf16(accO[jd], aph[ks2], &vl2[jd>>1][(jd&1)*2]);
            #pragma unroll
            for (int jd = 0; jd < 8; jd++)
                mma_bf16(accO[jd], apl[ks2], &vh2[jd>>1][(jd&1)*2]);
        }
        __syncthreads();
    }

    float inv0 = 1.f / l0, inv1 = 1.f / l1;
    size_t row0 = bS + q0 + warp*16 + g;
    #pragma unroll
    for (int jd = 0; jd < 8; jd++) {
        int c = hoff + jd*8 + tg*2;
        float2 o0; o0.x = accO[jd][0] * inv0; o0.y = accO[jd][1] * inv0;
        float2 o1; o1.x = accO[jd][2] * inv1; o1.y = accO[jd][3] * inv1;
        *(float2*)&out[row0 * EE + c]       = o0;
        *(float2*)&out[(row0 + 8) * EE + c] = o1;
    }
}

// ---------------- misc ------------------------------------------------------
__global__ void copy_f4(const float4* __restrict__ in, float4* __restrict__ out, int n4) {
    int i = blockIdx.x * blockDim.x + threadIdx.x;
    if (i < n4) out[i] = in[i];
}

// ---------------- launch ----------------------------------------------------
extern "C" void kernel_launch(void* const* d_in, const int* in_sizes, int n_in,
                              void* d_out, int out_size) {
    const float* x_in = (const float*)d_in[0];
    const int* mask = (const int*)d_in[1];
    const float* wq = (const float*)d_in[2];
    const float* bq = (const float*)d_in[3];
    const float* wk = (const float*)d_in[4];
    const float* bk = (const float*)d_in[5];
    const float* wv = (const float*)d_in[6];
    const float* bv = (const float*)d_in[7];
    const float* g1 = (const float*)d_in[8];
    const float* b1 = (const float*)d_in[9];
    const float* g2 = (const float*)d_in[10];
    const float* b2 = (const float*)d_in[11];
    const float* gf = (const float*)d_in[12];
    const float* bf = (const float*)d_in[13];
    const float* W1 = (const float*)d_in[14];
    const float* B1 = (const float*)d_in[15];
    const float* W2 = (const float*)d_in[16];
    const float* B2 = (const float*)d_in[17];
    float* outp = (float*)d_out;

    float *px, *pattn;
    __nv_bfloat16 *pqh, *pql, *pkh, *pkl, *pvh, *pvl;
    __nv_bfloat16 *phhi, *phlo, *pfhi, *pflo;
    __nv_bfloat16 *pwqh, *pwql, *pwkh, *pwkl, *pwvh, *pwvl, *pW1h, *pW1l, *pW2h, *pW2l;
    cudaGetSymbolAddress((void**)&px,    g_x);
    cudaGetSymbolAddress((void**)&pattn, g_attn);
    cudaGetSymbolAddress((void**)&pqh,   g_qhi);
    cudaGetSymbolAddress((void**)&pql,   g_qlo);
    cudaGetSymbolAddress((void**)&pkh,   g_khi);
    cudaGetSymbolAddress((void**)&pkl,   g_klo);
    cudaGetSymbolAddress((void**)&pvh,   g_vhi);
    cudaGetSymbolAddress((void**)&pvl,   g_vlo);
    cudaGetSymbolAddress((void**)&phhi,  g_hhi);
    cudaGetSymbolAddress((void**)&phlo,  g_hlo);
    cudaGetSymbolAddress((void**)&pfhi,  g_fhi);
    cudaGetSymbolAddress((void**)&pflo,  g_flo);
    cudaGetSymbolAddress((void**)&pwqh,  g_wqhi);
    cudaGetSymbolAddress((void**)&pwql,  g_wqlo);
    cudaGetSymbolAddress((void**)&pwkh,  g_wkhi);
    cudaGetSymbolAddress((void**)&pwkl,  g_wklo);
    cudaGetSymbolAddress((void**)&pwvh,  g_wvhi);
    cudaGetSymbolAddress((void**)&pwvl,  g_wvlo);
    cudaGetSymbolAddress((void**)&pW1h,  g_W1hi);
    cudaGetSymbolAddress((void**)&pW1l,  g_W1lo);
    cudaGetSymbolAddress((void**)&pW2h,  g_W2hi);
    cudaGetSymbolAddress((void**)&pW2l,  g_W2lo);

    cudaFuncSetAttribute(flash_attn_mma,
                         cudaFuncAttributeMaxDynamicSharedMemorySize, FB_SMEM);
    cudaFuncSetAttribute(gemm_mma_qkv,
                         cudaFuncAttributeMaxDynamicSharedMemorySize, GM_SMEM);
    cudaFuncSetAttribute(gemm_mma<1>,
                         cudaFuncAttributeMaxDynamicSharedMemorySize, GM_SMEM);
    cudaFuncSetAttribute(gemm_mma<2>,
                         cudaFuncAttributeMaxDynamicSharedMemorySize, GM_SMEM);

    {
        int n4 = NROWS * EE / 4;
        copy_f4<<<(n4 + 255) / 256, 256>>>((const float4*)x_in, (float4*)px, n4);
    }
    {
        int nq4 = NLAYERS * EE * EE / 4;
        cvt_kernel<<<(nq4 + 255) / 256, 256>>>((const float4*)wq,
            (__nv_bfloat162*)pwqh, (__nv_bfloat162*)pwql, nq4);
        cvt_kernel<<<(nq4 + 255) / 256, 256>>>((const float4*)wk,
            (__nv_bfloat162*)pwkh, (__nv_bfloat162*)pwkl, nq4);
        cvt_kernel<<<(nq4 + 255) / 256, 256>>>((const float4*)wv,
            (__nv_bfloat162*)pwvh, (__nv_bfloat162*)pwvl, nq4);
        int n14 = DFFN * EE / 4;
        cvt_kernel<<<(n14 + 255) / 256, 256>>>((const float4*)W1,
            (__nv_bfloat162*)pW1h, (__nv_bfloat162*)pW1l, n14);
        cvt_kernel<<<(n14 + 255) / 256, 256>>>((const float4*)W2,
            (__nv_bfloat162*)pW2h, (__nv_bfloat162*)pW2l, n14);
    }
    compact_idx<<<BB, 1024>>>(mask);       // mask is layer-invariant

    dim3 gQKV(EE / 128, NROWS / 128, 3);   // (4, 32, 3)
    dim3 gFF1(DFFN / 128, NROWS / 128);    // (16, 32)
    dim3 gFF2(EE / 128, NROWS / 128);      // (4, 32)
    dim3 gAtt(SEQ / 128, HH, BB);          // (16, 8, 2)
    dim3 gCpy(SEQ, BB);

    for (int l = 0; l < NLAYERS; l++) {
        const __nv_bfloat16* wqh = pwqh + (size_t)l * EE * EE;
        const __nv_bfloat16* wql = pwql + (size_t)l * EE * EE;
        const __nv_bfloat16* wkh = pwkh + (size_t)l * EE * EE;
        const __nv_bfloat16* wkl = pwkl + (size_t)l * EE * EE;
        const __nv_bfloat16* wvh = pwvh + (size_t)l * EE * EE;
        const __nv_bfloat16* wvl = pwvl + (size_t)l * EE * EE;
        const float* bql = bq + (size_t)l * EE;
        const float* bkl = bk + (size_t)l * EE;
        const float* bvl = bv + (size_t)l * EE;

        ln_bf16<<<NROWS, 128>>>(px, phhi, phlo, g1, b1);
        gemm_mma_qkv<<<gQKV, 256, GM_SMEM>>>(phhi, phlo,
            wqh, wql, wkh, wkl, wvh, wvl, bql, bkl, bvl,
            pqh, pql, pkh, pkl, pvh, pvl);
        compact_copy<<<gCpy, 256>>>(pkh, pkl, pvh, pvl);
        flash_attn_mma<<<gAtt, 256, FB_SMEM>>>(pqh, pql, pattn);
        fuse_attn_res_ln<<<NROWS, 128>>>(pattn, px, phhi, phlo, g2, b2);
        gemm_mma<1><<<gFF1, 256, GM_SMEM>>>(phhi, phlo, pW1h, pW1l,
            B1, EE, DFFN, nullptr, pfhi, pflo, nullptr);
        gemm_mma<2><<<gFF2, 256, GM_SMEM>>>(pfhi, pflo, pW2h, pW2l,
            B2, DFFN, EE, px, nullptr, nullptr, px);
    }
    ln_f32<<<NROWS, 128>>>(px, outp, gf, bf);
}

// round 13
// speedup vs baseline: 2.1513x; 2.0605x over previous
#include <cuda_runtime.h>
#include <cuda_fp16.h>
#include <stdint.h>

#define BB      2
#define SEQ     2048
#define EE      512
#define HH      8
#define DDIM    64
#define NLAYERS 2
#define DFFN    2048
#define NROWS   4096   // BB*SEQ

// mma.sync GEMM config: 128x128 tile, K-chunk 32 (fp16), single pass
#define GM_CHUNK     32
#define GM_STRIDE    80                    // 32 fp16 = 64B + 16B pad
#define GM_MAT_BYTES (128 * GM_STRIDE)     // 10240
#define GM_BUF_BYTES (2 * GM_MAT_BYTES)    // A, B = 20480
#define GM_SMEM      (2 * GM_BUF_BYTES)    // double buffered = 40960

// flash mma config: BQ=128, BK=32, 8 warps (16 q-rows each)
#define FB_STRIDE_B  144                   // 64 fp16 = 128B + 16B pad
#define FB_Q_BYTES   (128 * FB_STRIDE_B)   // 18432
#define FB_KV_MAT    (32 * FB_STRIDE_B)    // 4608
#define FB_STAGE     (2 * FB_KV_MAT)       // K, V = 9216
#define FB_SMEM      (FB_Q_BYTES + 2*FB_STAGE + 256)

// ---------------- scratch (device globals) ----------------------------------
__device__ float g_x[NROWS * EE];
__device__ float g_attn[NROWS * EE];
__device__ __half g_qh[NROWS*EE];
__device__ __half g_kh[NROWS*EE];
__device__ __half g_vh[NROWS*EE];
__device__ __half g_ckh[NROWS*EE];    // compacted K
__device__ __half g_cvh[NROWS*EE];    // compacted V
__device__ int g_cnt[BB];
__device__ int g_cidx[BB*SEQ];
__device__ __half g_hh[NROWS * EE];
__device__ __half g_fh[NROWS * DFFN];
__device__ __half g_wqh[NLAYERS*EE*EE];
__device__ __half g_wkh[NLAYERS*EE*EE];
__device__ __half g_wvh[NLAYERS*EE*EE];
__device__ __half g_W1h[DFFN*EE];
__device__ __half g_W2h[EE*DFFN];

// ---------------- PTX helpers ------------------------------------------------
__device__ __forceinline__ uint32_t smem_u32(const void* p) {
    uint32_t a;
    asm("{ .reg .u64 t; cvta.to.shared.u64 t, %1; cvt.u32.u64 %0, t; }" : "=r"(a) : "l"(p));
    return a;
}
__device__ __forceinline__ void cp16(uint32_t saddr, const void* g) {
    asm volatile("cp.async.cg.shared.global [%0], [%1], 16;" :: "r"(saddr), "l"(g));
}
__device__ __forceinline__ void cp_commit() {
    asm volatile("cp.async.commit_group;" ::: "memory");
}
__device__ __forceinline__ void cp_wait0() {
    asm volatile("cp.async.wait_group 0;" ::: "memory");
}
__device__ __forceinline__ void cp_wait1() {
    asm volatile("cp.async.wait_group 1;" ::: "memory");
}
__device__ __forceinline__ void ldmx4(uint32_t* r, uint32_t addr) {
    asm volatile("ldmatrix.sync.aligned.m8n8.x4.shared.b16 {%0,%1,%2,%3}, [%4];"
        : "=r"(r[0]), "=r"(r[1]), "=r"(r[2]), "=r"(r[3]) : "r"(addr));
}
__device__ __forceinline__ void ldmx4t(uint32_t* r, uint32_t addr) {
    asm volatile("ldmatrix.sync.aligned.m8n8.x4.trans.shared.b16 {%0,%1,%2,%3}, [%4];"
        : "=r"(r[0]), "=r"(r[1]), "=r"(r[2]), "=r"(r[3]) : "r"(addr));
}
__device__ __forceinline__ void mma_f16(float* d, const uint32_t* a, const uint32_t* b) {
    asm volatile(
        "mma.sync.aligned.m16n8k16.row.col.f32.f16.f16.f32 "
        "{%0,%1,%2,%3}, {%4,%5,%6,%7}, {%8,%9}, {%0,%1,%2,%3};"
        : "+f"(d[0]), "+f"(d[1]), "+f"(d[2]), "+f"(d[3])
        : "r"(a[0]), "r"(a[1]), "r"(a[2]), "r"(a[3]), "r"(b[0]), "r"(b[1]));
}

// ---------------- reductions -------------------------------------------------
__device__ __forceinline__ void block_reduce2(float& s, float& s2) {
    __shared__ float shm[8];
    #pragma unroll
    for (int o = 16; o > 0; o >>= 1) {
        s  += __shfl_down_sync(0xffffffffu, s,  o);
        s2 += __shfl_down_sync(0xffffffffu, s2, o);
    }
    int w = threadIdx.x >> 5;
    __syncthreads();
    if ((threadIdx.x & 31) == 0) { shm[w] = s; shm[4 + w] = s2; }
    __syncthreads();
    s  = shm[0] + shm[1] + shm[2] + shm[3];
    s2 = shm[4] + shm[5] + shm[6] + shm[7];
}

// ---------------- LayerNorm variants ----------------------------------------
__global__ void ln_f32(const float* __restrict__ in, float* __restrict__ outp,
                       const float* __restrict__ g, const float* __restrict__ b) {
    int row = blockIdx.x, t = threadIdx.x;
    const float* xr = in + (size_t)row * EE;
    float v[4], s = 0.f, s2 = 0.f;
    #pragma unroll
    for (int i = 0; i < 4; i++) { v[i] = xr[t + i*128]; s += v[i]; s2 += v[i]*v[i]; }
    block_reduce2(s, s2);
    float mu = s * (1.f/EE), var = s2 * (1.f/EE) - mu*mu, r = rsqrtf(var + 1e-5f);
    #pragma unroll
    for (int i = 0; i < 4; i++) {
        int idx = t + i*128;
        outp[(size_t)row*EE + idx] = (v[i]-mu)*r*g[idx] + b[idx];
    }
}
__global__ void ln_f16(const float* __restrict__ in, __half* __restrict__ hi,
                       const float* __restrict__ g, const float* __restrict__ b) {
    int row = blockIdx.x, t = threadIdx.x;
    const float* xr = in + (size_t)row * EE;
    float v[4], s = 0.f, s2 = 0.f;
    #pragma unroll
    for (int i = 0; i < 4; i++) { v[i] = xr[t + i*128]; s += v[i]; s2 += v[i]*v[i]; }
    block_reduce2(s, s2);
    float mu = s * (1.f/EE), var = s2 * (1.f/EE) - mu*mu, r = rsqrtf(var + 1e-5f);
    #pragma unroll
    for (int i = 0; i < 4; i++) {
        int idx = t + i*128;
        hi[(size_t)row*EE + idx] = __float2half((v[i]-mu)*r*g[idx] + b[idx]);
    }
}
__global__ void fuse_attn_res_ln(const float* __restrict__ attn, float* x,
                                 __half* __restrict__ hh,
                                 const float* __restrict__ g2, const float* __restrict__ b2) {
    int row = blockIdx.x, t = threadIdx.x;
    const float* ar = attn + (size_t)row * EE;
    float a[4], s = 0.f, s2 = 0.f;
    #pragma unroll
    for (int i = 0; i < 4; i++) { a[i] = ar[t + i*128]; s += a[i]; s2 += a[i]*a[i]; }
    block_reduce2(s, s2);
    float mu = s * (1.f/EE), var = s2 * (1.f/EE) - mu*mu, r = rsqrtf(var + 1e-5f);
    float xv[4];
    s = 0.f; s2 = 0.f;
    #pragma unroll
    for (int i = 0; i < 4; i++) {
        int idx = t + i*128;
        float y = (a[i]-mu)*r*g2[idx] + b2[idx];
        float xn = x[(size_t)row*EE + idx] + y;
        x[(size_t)row*EE + idx] = xn;
        xv[i] = xn; s += xn; s2 += xn*xn;
    }
    block_reduce2(s, s2);
    float mu2 = s * (1.f/EE), var2 = s2 * (1.f/EE) - mu2*mu2, r2 = rsqrtf(var2 + 1e-5f);
    #pragma unroll
    for (int i = 0; i < 4; i++) {
        int idx = t + i*128;
        hh[(size_t)row*EE + idx] = __float2half((xv[i]-mu2)*r2);
    }
}

// ---------------- weight fp32 -> fp16 (vectorized) ---------------------------
__global__ void cvt_kernel(const float4* __restrict__ in, __half2* __restrict__ hi, int n4) {
    int i = blockIdx.x * blockDim.x + threadIdx.x;
    if (i < n4) {
        float4 v = in[i];
        hi[2*i]   = __floats2half2_rn(v.x, v.y);
        hi[2*i+1] = __floats2half2_rn(v.z, v.w);
    }
}

// ---------------- mask compaction --------------------------------------------
__global__ __launch_bounds__(1024) void compact_idx(const int* __restrict__ mask) {
    __shared__ int part[1024];
    int b = blockIdx.x, t = threadIdx.x;
    const int* mb = mask + (size_t)b * SEQ;
    int v0 = (mb[2*t]   == 0);
    int v1 = (mb[2*t+1] == 0);
    part[t] = v0 + v1;
    __syncthreads();
    for (int o = 1; o < 1024; o <<= 1) {
        int x = part[t];
        int y = (t >= o) ? part[t-o] : 0;
        __syncthreads();
        part[t] = x + y;
        __syncthreads();
    }
    int incl = part[t];
    int excl = incl - (v0 + v1);
    if (v0) g_cidx[b*SEQ + excl]      = 2*t;
    if (v1) g_cidx[b*SEQ + excl + v0] = 2*t+1;
    if (t == 1023) g_cnt[b] = incl;
}

// gather unmasked K/V rows; block covers 2 rows; m: 0=K, 1=V; c: uint4 chunk
__global__ __launch_bounds__(256) void compact_copy(
    const __half* __restrict__ kh, const __half* __restrict__ vh) {
    int b = blockIdx.y, t = threadIdx.x;
    int j = blockIdx.x * 2 + (t >> 7);
    int m = (t >> 6) & 1;
    int c = t & 63;
    int cnt = g_cnt[b];
    int lim = (cnt + 31) & ~31;
    if (j >= lim) return;
    size_t dst = ((size_t)b * SEQ + j) * EE + c * 8;
    __half* dp = m ? g_cvh : g_ckh;
    if (j < cnt) {
        int src = g_cidx[b*SEQ + j];
        size_t sof = ((size_t)b * SEQ + src) * EE + c * 8;
        const __half* sp = m ? vh : kh;
        *(uint4*)(dp + dst) = *(const uint4*)(sp + sof);
    } else {
        uint4 z; z.x = 0; z.y = 0; z.z = 0; z.w = 0;
        *(uint4*)(dp + dst) = z;
    }
}

// ---------------- mma.sync GEMM (fp16 single pass) ---------------------------
// MODE 1: bias+relu -> fp16. MODE 2: fp32+bias+residual. MODE 3: bias -> fp16.
template<int MODE>
__device__ __forceinline__ void gemm_mma_body(
    const __half* __restrict__ A, const __half* __restrict__ B,
    const float* __restrict__ bias, int K, int N,
    float* __restrict__ Cf, __half* __restrict__ Ch,
    const float* __restrict__ res, int rowBase, int colBase)
{
    extern __shared__ char sm8[];
    uint32_t sbase = smem_u32(sm8);
    int tid = threadIdx.x, lane = tid & 31, warp = tid >> 5;
    int wm = warp >> 2, wn = warp & 3;

    float acc[4][4][4];
    #pragma unroll
    for (int i = 0; i < 4; i++)
        #pragma unroll
        for (int j = 0; j < 4; j++)
            #pragma unroll
            for (int c = 0; c < 4; c++) acc[i][j][c] = 0.f;

    uint32_t aAddr = (uint32_t)((wm*64 + ((lane>>3)&1)*8 + (lane&7)) * GM_STRIDE
                                + (lane>>4)*16);
    uint32_t bAddr = (uint32_t)((wn*32 + (lane>>4)*8 + (lane&7)) * GM_STRIDE
                                + ((lane>>3)&1)*16);

    const int T = K / GM_CHUNK;
    int lrow0 = tid >> 2, lseg = tid & 3;

    {
        uint32_t sb = sbase;
        #pragma unroll
        for (int j = 0; j < 2; j++) {
            int row = lrow0 + j*64;
            uint32_t so = row*GM_STRIDE + lseg*16;
            cp16(sb + 0*GM_MAT_BYTES + so, A + (size_t)(rowBase+row)*K + lseg*8);
            cp16(sb + 1*GM_MAT_BYTES + so, B + (size_t)(colBase+row)*K + lseg*8);
        }
        cp_commit();
    }

    for (int t = 0; t < T; t++) {
        cp_wait0();
        __syncthreads();
        if (t + 1 < T) {
            uint32_t sb = sbase + ((t+1) & 1) * GM_BUF_BYTES;
            int koff = (t+1) * GM_CHUNK;
            #pragma unroll
            for (int j = 0; j < 2; j++) {
                int row = lrow0 + j*64;
                uint32_t so = row*GM_STRIDE + lseg*16;
                cp16(sb + 0*GM_MAT_BYTES + so, A + (size_t)(rowBase+row)*K + koff + lseg*8);
                cp16(sb + 1*GM_MAT_BYTES + so, B + (size_t)(colBase+row)*K + koff + lseg*8);
            }
            cp_commit();
        }
        uint32_t buf = sbase + (t & 1) * GM_BUF_BYTES;
        #pragma unroll
        for (int ks = 0; ks < 2; ks++) {
            uint32_t ah[4][4], bh[2][4];
            #pragma unroll
            for (int i = 0; i < 4; i++)
                ldmx4(ah[i], buf + aAddr + i*16*GM_STRIDE + ks*32);
            #pragma unroll
            for (int p = 0; p < 2; p++)
                ldmx4(bh[p], buf + GM_MAT_BYTES + bAddr + p*16*GM_STRIDE + ks*32);
            #pragma unroll
            for (int i = 0; i < 4; i++)
                #pragma unroll
                for (int j = 0; j < 4; j++)
                    mma_f16(acc[i][j], ah[i], &bh[j>>1][(j&1)*2]);
        }
    }

    int g = lane >> 2, tg = lane & 3;
    #pragma unroll
    for (int i = 0; i < 4; i++) {
        int r0 = rowBase + wm*64 + i*16 + g;
        #pragma unroll
        for (int j = 0; j < 4; j++) {
            int c = colBase + wn*32 + j*8 + tg*2;
            float b0 = bias[c], b1 = bias[c+1];
            #pragma unroll
            for (int half = 0; half < 2; half++) {
                int r = r0 + half*8;
                float v0 = acc[i][j][half*2+0] + b0;
                float v1 = acc[i][j][half*2+1] + b1;
                if (MODE == 1 || MODE == 3) {
                    if (MODE == 1) { v0 = fmaxf(v0, 0.f); v1 = fmaxf(v1, 0.f); }
                    *(__half2*)&Ch[(size_t)r * N + c] = __floats2half2_rn(v0, v1);
                } else {
                    if (MODE == 2) {
                        float2 rv = *(const float2*)&res[(size_t)r * N + c];
                        v0 += rv.x; v1 += rv.y;
                    }
                    float2 o; o.x = v0; o.y = v1;
                    *(float2*)&Cf[(size_t)r * N + c] = o;
                }
            }
        }
    }
}

template<int MODE>
__global__ __launch_bounds__(256, 2) void gemm_mma(
    const __half* __restrict__ A, const __half* __restrict__ B,
    const float* __restrict__ bias, int K, int N,
    float* __restrict__ Cf, __half* __restrict__ Ch, const float* __restrict__ res)
{
    gemm_mma_body<MODE>(A, B, bias, K, N, Cf, Ch, res,
                        blockIdx.y * 128, blockIdx.x * 128);
}

__global__ __launch_bounds__(256, 2) void gemm_mma_qkv(
    const __half* __restrict__ hh,
    const __half* __restrict__ wqh, const __half* __restrict__ wkh,
    const __half* __restrict__ wvh,
    const float* __restrict__ bq, const float* __restrict__ bk, const float* __restrict__ bv,
    __half* qh, __half* kh, __half* vh)
{
    const __half* Bh; const float* bi; __half* Ch;
    if (blockIdx.z == 0)      { Bh = wqh; bi = bq; Ch = qh; }
    else if (blockIdx.z == 1) { Bh = wkh; bi = bk; Ch = kh; }
    else                      { Bh = wvh; bi = bv; Ch = vh; }
    gemm_mma_body<3>(hh, Bh, bi, EE, EE, nullptr, Ch, nullptr,
                     blockIdx.y * 128, blockIdx.x * 128);
}

// ---------------- Flash attention (fp16 single pass, compacted keys) ---------
__global__ __launch_bounds__(256) void flash_attn_mma(
    const __half* __restrict__ qh_g, float* __restrict__ out)
{
    extern __shared__ char fsm[];
    uint32_t sQ  = smem_u32(fsm);
    uint32_t sKV = sQ + FB_Q_BYTES;

    int tid = threadIdx.x, lane = tid & 31, warp = tid >> 5;
    int g = lane >> 2, tg = lane & 3;
    int q0 = blockIdx.x * 128;
    int h  = blockIdx.y;
    int b  = blockIdx.z;
    int hoff = h * DDIM;
    size_t bS = (size_t)b * SEQ;

    int cnt = g_cnt[b];
    const int T = (cnt + 31) >> 5;

    {
        int row = tid >> 3, seg = tid & 7;
        #pragma unroll
        for (int i = 0; i < 4; i++) {
            int r = row + i * 32;
            cp16(sQ + (uint32_t)r * FB_STRIDE_B + seg * 16,
                 qh_g + (bS + q0 + r) * EE + hoff + seg * 8);
        }
        uint32_t so = (uint32_t)row * FB_STRIDE_B + seg * 16;
        size_t gk = (bS + row) * EE + hoff + seg * 8;
        cp16(sKV + 0*FB_KV_MAT + so, g_ckh + gk);
        cp16(sKV + 1*FB_KV_MAT + so, g_cvh + gk);
        cp_commit();
    }
    cp_wait0();
    __syncthreads();

    uint32_t qf[4][4];
    {
        uint32_t base = (uint32_t)(warp*16 + ((lane>>3)&1)*8 + (lane&7)) * FB_STRIDE_B
                      + (lane>>4)*16;
        #pragma unroll
        for (int ks = 0; ks < 4; ks++)
            ldmx4(qf[ks], sQ + base + ks*32);
    }

    float accO[8][4];
    #pragma unroll
    for (int j = 0; j < 8; j++)
        #pragma unroll
        for (int c = 0; c < 4; c++) accO[j][c] = 0.f;
    float mOld0 = -1e30f, mOld1 = -1e30f, l0 = 0.f, l1 = 0.f;

    uint32_t kAddrBase = (uint32_t)(((lane>>4)*8 + (lane&7)) * FB_STRIDE_B)
                       + ((lane>>3)&1)*16;
    uint32_t vAddrBase = (uint32_t)((((lane>>3)&1)*8 + (lane&7)) * FB_STRIDE_B)
                       + (lane>>4)*16;

    for (int it = 0; it < T; it++) {
        if (it + 1 < T) {
            uint32_t stg2 = sKV + ((it+1) & 1) * FB_STAGE;
            int row = tid >> 3, seg = tid & 7;
            uint32_t so = (uint32_t)row * FB_STRIDE_B + seg * 16;
            size_t gk = (bS + (it+1)*32 + row) * EE + hoff + seg * 8;
            cp16(stg2 + 0*FB_KV_MAT + so, g_ckh + gk);
            cp16(stg2 + 1*FB_KV_MAT + so, g_cvh + gk);
            cp_commit();
            cp_wait1();
        } else {
            cp_wait0();
        }
        __syncthreads();

        uint32_t stg = sKV + (it & 1) * FB_STAGE;

        float accS[4][4];
        #pragma unroll
        for (int j = 0; j < 4; j++)
            #pragma unroll
            for (int c = 0; c < 4; c++) accS[j][c] = 0.f;
        #pragma unroll
        for (int ks = 0; ks < 4; ks++) {
            uint32_t bh[2][4];
            #pragma unroll
            for (int p = 0; p < 2; p++)
                ldmx4(bh[p], stg + kAddrBase + (uint32_t)p*16*FB_STRIDE_B + ks*32);
            #pragma unroll
            for (int j = 0; j < 4; j++)
                mma_f16(accS[j], qf[ks], &bh[j>>1][(j&1)*2]);
        }

        int lim = cnt - it*32;
        if (lim >= 32) {
            #pragma unroll
            for (int j = 0; j < 4; j++) {
                accS[j][0] *= 0.125f; accS[j][1] *= 0.125f;
                accS[j][2] *= 0.125f; accS[j][3] *= 0.125f;
            }
        } else {
            #pragma unroll
            for (int j = 0; j < 4; j++) {
                int n0 = j*8 + tg*2;
                bool k0 = n0 < lim, k1 = (n0 + 1) < lim;
                accS[j][0] = k0 ? accS[j][0]*0.125f : -1e30f;
                accS[j][1] = k1 ? accS[j][1]*0.125f : -1e30f;
                accS[j][2] = k0 ? accS[j][2]*0.125f : -1e30f;
                accS[j][3] = k1 ? accS[j][3]*0.125f : -1e30f;
            }
        }
        float mx0 = -1e30f, mx1 = -1e30f;
        #pragma unroll
        for (int j = 0; j < 4; j++) {
            mx0 = fmaxf(mx0, fmaxf(accS[j][0], accS[j][1]));
            mx1 = fmaxf(mx1, fmaxf(accS[j][2], accS[j][3]));
        }
        mx0 = fmaxf(mx0, __shfl_xor_sync(0xffffffffu, mx0, 1));
        mx0 = fmaxf(mx0, __shfl_xor_sync(0xffffffffu, mx0, 2));
        mx1 = fmaxf(mx1, __shfl_xor_sync(0xffffffffu, mx1, 1));
        mx1 = fmaxf(mx1, __shfl_xor_sync(0xffffffffu, mx1, 2));
        float mn0 = fmaxf(mOld0, mx0), mn1 = fmaxf(mOld1, mx1);
        float scl0 = __expf(mOld0 - mn0), scl1 = __expf(mOld1 - mn1);
        float p[4][4];
        float ls0 = 0.f, ls1 = 0.f;
        #pragma unroll
        for (int j = 0; j < 4; j++) {
            p[j][0] = __expf(accS[j][0] - mn0);
            p[j][1] = __expf(accS[j][1] - mn0);
            p[j][2] = __expf(accS[j][2] - mn1);
            p[j][3] = __expf(accS[j][3] - mn1);
            ls0 += p[j][0] + p[j][1];
            ls1 += p[j][2] + p[j][3];
        }
        ls0 += __shfl_xor_sync(0xffffffffu, ls0, 1);
        ls0 += __shfl_xor_sync(0xffffffffu, ls0, 2);
        ls1 += __shfl_xor_sync(0xffffffffu, ls1, 1);
        ls1 += __shfl_xor_sync(0xffffffffu, ls1, 2);
        l0 = l0 * scl0 + ls0;
        l1 = l1 * scl1 + ls1;
        mOld0 = mn0; mOld1 = mn1;
        #pragma unroll
        for (int j = 0; j < 8; j++) {
            accO[j][0] *= scl0; accO[j][1] *= scl0;
            accO[j][2] *= scl1; accO[j][3] *= scl1;
        }

        // P fragments (fp16) direct from registers
        uint32_t ap[2][4];
        #pragma unroll
        for (int jj = 0; jj < 2; jj++) {
            int t0 = 2*jj, t1 = 2*jj + 1;
            __half2 x0 = __floats2half2_rn(p[t0][0], p[t0][1]);
            __half2 x1 = __floats2half2_rn(p[t0][2], p[t0][3]);
            __half2 x2 = __floats2half2_rn(p[t1][0], p[t1][1]);
            __half2 x3 = __floats2half2_rn(p[t1][2], p[t1][3]);
            ap[jj][0] = *reinterpret_cast<uint32_t*>(&x0);
            ap[jj][1] = *reinterpret_cast<uint32_t*>(&x1);
            ap[jj][2] = *reinterpret_cast<uint32_t*>(&x2);
            ap[jj][3] = *reinterpret_cast<uint32_t*>(&x3);
        }

        #pragma unroll
        for (int ks2 = 0; ks2 < 2; ks2++) {
            uint32_t v2[4][4];
            #pragma unroll
            for (int ng = 0; ng < 4; ng++)
                ldmx4t(v2[ng], stg + FB_KV_MAT + vAddrBase
                               + (uint32_t)ks2*16*FB_STRIDE_B + ng*32);
            #pragma unroll
            for (int jd = 0; jd < 8; jd++)
                mma_f16(accO[jd], ap[ks2], &v2[jd>>1][(jd&1)*2]);
        }
        __syncthreads();
    }

    float inv0 = 1.f / l0, inv1 = 1.f / l1;
    size_t row0 = bS + q0 + warp*16 + g;
    #pragma unroll
    for (int jd = 0; jd < 8; jd++) {
        int c = hoff + jd*8 + tg*2;
        float2 o0; o0.x = accO[jd][0] * inv0; o0.y = accO[jd][1] * inv0;
        float2 o1; o1.x = accO[jd][2] * inv1; o1.y = accO[jd][3] * inv1;
        *(float2*)&out[row0 * EE + c]       = o0;
        *(float2*)&out[(row0 + 8) * EE + c] = o1;
    }
}

// ---------------- misc ------------------------------------------------------
__global__ void copy_f4(const float4* __restrict__ in, float4* __restrict__ out, int n4) {
    int i = blockIdx.x * blockDim.x + threadIdx.x;
    if (i < n4) out[i] = in[i];
}

// ---------------- launch ----------------------------------------------------
extern "C" void kernel_launch(void* const* d_in, const int* in_sizes, int n_in,
                              void* d_out, int out_size) {
    const float* x_in = (const float*)d_in[0];
    const int* mask = (const int*)d_in[1];
    const float* wq = (const float*)d_in[2];
    const float* bq = (const float*)d_in[3];
    const float* wk = (const float*)d_in[4];
    const float* bk = (const float*)d_in[5];
    const float* wv = (const float*)d_in[6];
    const float* bv = (const float*)d_in[7];
    const float* g1 = (const float*)d_in[8];
    const float* b1 = (const float*)d_in[9];
    const float* g2 = (const float*)d_in[10];
    const float* b2 = (const float*)d_in[11];
    const float* gf = (const float*)d_in[12];
    const float* bf = (const float*)d_in[13];
    const float* W1 = (const float*)d_in[14];
    const float* B1 = (const float*)d_in[15];
    const float* W2 = (const float*)d_in[16];
    const float* B2 = (const float*)d_in[17];
    float* outp = (float*)d_out;

    float *px, *pattn;
    __half *pqh, *pkh, *pvh, *phh, *pfh;
    __half *pwqh, *pwkh, *pwvh, *pW1h, *pW2h;
    cudaGetSymbolAddress((void**)&px,    g_x);
    cudaGetSymbolAddress((void**)&pattn, g_attn);
    cudaGetSymbolAddress((void**)&pqh,   g_qh);
    cudaGetSymbolAddress((void**)&pkh,   g_kh);
    cudaGetSymbolAddress((void**)&pvh,   g_vh);
    cudaGetSymbolAddress((void**)&phh,   g_hh);
    cudaGetSymbolAddress((void**)&pfh,   g_fh);
    cudaGetSymbolAddress((void**)&pwqh,  g_wqh);
    cudaGetSymbolAddress((void**)&pwkh,  g_wkh);
    cudaGetSymbolAddress((void**)&pwvh,  g_wvh);
    cudaGetSymbolAddress((void**)&pW1h,  g_W1h);
    cudaGetSymbolAddress((void**)&pW2h,  g_W2h);

    cudaFuncSetAttribute(flash_attn_mma,
                         cudaFuncAttributeMaxDynamicSharedMemorySize, FB_SMEM);
    cudaFuncSetAttribute(gemm_mma_qkv,
                         cudaFuncAttributeMaxDynamicSharedMemorySize, GM_SMEM);
    cudaFuncSetAttribute(gemm_mma<1>,
                         cudaFuncAttributeMaxDynamicSharedMemorySize, GM_SMEM);
    cudaFuncSetAttribute(gemm_mma<2>,
                         cudaFuncAttributeMaxDynamicSharedMemorySize, GM_SMEM);

    {
        int n4 = NROWS * EE / 4;
        copy_f4<<<(n4 + 255) / 256, 256>>>((const float4*)x_in, (float4*)px, n4);
    }
    {
        int nq4 = NLAYERS * EE * EE / 4;
        cvt_kernel<<<(nq4 + 255) / 256, 256>>>((const float4*)wq, (__half2*)pwqh, nq4);
        cvt_kernel<<<(nq4 + 255) / 256, 256>>>((const float4*)wk, (__half2*)pwkh, nq4);
        cvt_kernel<<<(nq4 + 255) / 256, 256>>>((const float4*)wv, (__half2*)pwvh, nq4);
        int n14 = DFFN * EE / 4;
        cvt_kernel<<<(n14 + 255) / 256, 256>>>((const float4*)W1, (__half2*)pW1h, n14);
        cvt_kernel<<<(n14 + 255) / 256, 256>>>((const float4*)W2, (__half2*)pW2h, n14);
    }
    compact_idx<<<BB, 1024>>>(mask);       // mask is layer-invariant

    dim3 gQKV(EE / 128, NROWS / 128, 3);   // (4, 32, 3)
    dim3 gFF1(DFFN / 128, NROWS / 128);    // (16, 32)
    dim3 gFF2(EE / 128, NROWS / 128);      // (4, 32)
    dim3 gAtt(SEQ / 128, HH, BB);          // (16, 8, 2)
    dim3 gCpy(SEQ / 2, BB);

    for (int l = 0; l < NLAYERS; l++) {
        const __half* wqhl = pwqh + (size_t)l * EE * EE;
        const __half* wkhl = pwkh + (size_t)l * EE * EE;
        const __half* wvhl = pwvh + (size_t)l * EE * EE;
        const float* bql = bq + (size_t)l * EE;
        const float* bkl = bk + (size_t)l * EE;
        const float* bvl = bv + (size_t)l * EE;

        ln_f16<<<NROWS, 128>>>(px, phh, g1, b1);
        gemm_mma_qkv<<<gQKV, 256, GM_SMEM>>>(phh, wqhl, wkhl, wvhl,
            bql, bkl, bvl, pqh, pkh, pvh);
        compact_copy<<<gCpy, 256>>>(pkh, pvh);
        flash_attn_mma<<<gAtt, 256, FB_SMEM>>>(pqh, pattn);
        fuse_attn_res_ln<<<NROWS, 128>>>(pattn, px, phh, g2, b2);
        gemm_mma<1><<<gFF1, 256, GM_SMEM>>>(phh, pW1h, B1, EE, DFFN,
            nullptr, pfh, nullptr);
        gemm_mma<2><<<gFF2, 256, GM_SMEM>>>(pfh, pW2h, B2, DFFN, EE,
            px, nullptr, px);
    }
    ln_f32<<<NROWS, 128>>>(px, outp, gf, bf);
}

// round 14
// speedup vs baseline: 2.2426x; 1.0424x over previous
#include <cuda_runtime.h>
#include <cuda_fp16.h>
#include <stdint.h>

#define BB      2
#define SEQ     2048
#define EE      512
#define HH      8
#define DDIM    64
#define NLAYERS 2
#define DFFN    2048
#define NROWS   4096   // BB*SEQ

// mma.sync GEMM config: 128x128 tile, K-chunk 32 (fp16), single pass
#define GM_CHUNK     32
#define GM_STRIDE    80                    // 32 fp16 = 64B + 16B pad
#define GM_MAT_BYTES (128 * GM_STRIDE)     // 10240
#define GM_BUF_BYTES (2 * GM_MAT_BYTES)    // A, B = 20480
#define GM_SMEM      (2 * GM_BUF_BYTES)    // double buffered = 40960

// flash mma config: BQ=128, BK=32, 8 warps (16 q-rows each)
#define FB_STRIDE_B  144                   // 64 fp16 = 128B + 16B pad
#define FB_Q_BYTES   (128 * FB_STRIDE_B)   // 18432
#define FB_KV_MAT    (32 * FB_STRIDE_B)    // 4608
#define FB_STAGE     (2 * FB_KV_MAT)       // K, V = 9216
#define FB_SMEM      (FB_Q_BYTES + 2*FB_STAGE + 256)

// ---------------- scratch (device globals) ----------------------------------
__device__ float g_x[NROWS * EE];
__device__ float g_attn[NROWS * EE];
__device__ __half g_qh[NROWS*EE];
__device__ __half g_ckh[NROWS*EE];    // compacted K (scatter target)
__device__ __half g_cvh[NROWS*EE];    // compacted V (scatter target)
__device__ int g_cnt[BB];
__device__ int g_cpos[BB*SEQ];        // src row -> compacted row (-1 = masked)
__device__ __half g_hh[NROWS * EE];
__device__ __half g_fh[NROWS * DFFN];
__device__ __half g_wqh[NLAYERS*EE*EE];
__device__ __half g_wkh[NLAYERS*EE*EE];
__device__ __half g_wvh[NLAYERS*EE*EE];
__device__ __half g_W1h[DFFN*EE];
__device__ __half g_W2h[EE*DFFN];

// ---------------- PTX helpers ------------------------------------------------
__device__ __forceinline__ uint32_t smem_u32(const void* p) {
    uint32_t a;
    asm("{ .reg .u64 t; cvta.to.shared.u64 t, %1; cvt.u32.u64 %0, t; }" : "=r"(a) : "l"(p));
    return a;
}
__device__ __forceinline__ void cp16(uint32_t saddr, const void* g) {
    asm volatile("cp.async.cg.shared.global [%0], [%1], 16;" :: "r"(saddr), "l"(g));
}
__device__ __forceinline__ void cp_commit() {
    asm volatile("cp.async.commit_group;" ::: "memory");
}
__device__ __forceinline__ void cp_wait0() {
    asm volatile("cp.async.wait_group 0;" ::: "memory");
}
__device__ __forceinline__ void cp_wait1() {
    asm volatile("cp.async.wait_group 1;" ::: "memory");
}
__device__ __forceinline__ void ldmx4(uint32_t* r, uint32_t addr) {
    asm volatile("ldmatrix.sync.aligned.m8n8.x4.shared.b16 {%0,%1,%2,%3}, [%4];"
        : "=r"(r[0]), "=r"(r[1]), "=r"(r[2]), "=r"(r[3]) : "r"(addr));
}
__device__ __forceinline__ void ldmx4t(uint32_t* r, uint32_t addr) {
    asm volatile("ldmatrix.sync.aligned.m8n8.x4.trans.shared.b16 {%0,%1,%2,%3}, [%4];"
        : "=r"(r[0]), "=r"(r[1]), "=r"(r[2]), "=r"(r[3]) : "r"(addr));
}
__device__ __forceinline__ void mma_f16(float* d, const uint32_t* a, const uint32_t* b) {
    asm volatile(
        "mma.sync.aligned.m16n8k16.row.col.f32.f16.f16.f32 "
        "{%0,%1,%2,%3}, {%4,%5,%6,%7}, {%8,%9}, {%0,%1,%2,%3};"
        : "+f"(d[0]), "+f"(d[1]), "+f"(d[2]), "+f"(d[3])
        : "r"(a[0]), "r"(a[1]), "r"(a[2]), "r"(a[3]), "r"(b[0]), "r"(b[1]));
}

// ---------------- reductions -------------------------------------------------
__device__ __forceinline__ void block_reduce2(float& s, float& s2) {
    __shared__ float shm[8];
    #pragma unroll
    for (int o = 16; o > 0; o >>= 1) {
        s  += __shfl_down_sync(0xffffffffu, s,  o);
        s2 += __shfl_down_sync(0xffffffffu, s2, o);
    }
    int w = threadIdx.x >> 5;
    __syncthreads();
    if ((threadIdx.x & 31) == 0) { shm[w] = s; shm[4 + w] = s2; }
    __syncthreads();
    s  = shm[0] + shm[1] + shm[2] + shm[3];
    s2 = shm[4] + shm[5] + shm[6] + shm[7];
}

// ---------------- LayerNorm variants ----------------------------------------
__global__ void ln_f32(const float* __restrict__ in, float* __restrict__ outp,
                       const float* __restrict__ g, const float* __restrict__ b) {
    int row = blockIdx.x, t = threadIdx.x;
    const float* xr = in + (size_t)row * EE;
    float v[4], s = 0.f, s2 = 0.f;
    #pragma unroll
    for (int i = 0; i < 4; i++) { v[i] = xr[t + i*128]; s += v[i]; s2 += v[i]*v[i]; }
    block_reduce2(s, s2);
    float mu = s * (1.f/EE), var = s2 * (1.f/EE) - mu*mu, r = rsqrtf(var + 1e-5f);
    #pragma unroll
    for (int i = 0; i < 4; i++) {
        int idx = t + i*128;
        outp[(size_t)row*EE + idx] = (v[i]-mu)*r*g[idx] + b[idx];
    }
}
__global__ void ln_f16(const float* __restrict__ in, __half* __restrict__ hi,
                       const float* __restrict__ g, const float* __restrict__ b) {
    int row = blockIdx.x, t = threadIdx.x;
    const float* xr = in + (size_t)row * EE;
    float v[4], s = 0.f, s2 = 0.f;
    #pragma unroll
    for (int i = 0; i < 4; i++) { v[i] = xr[t + i*128]; s += v[i]; s2 += v[i]*v[i]; }
    block_reduce2(s, s2);
    float mu = s * (1.f/EE), var = s2 * (1.f/EE) - mu*mu, r = rsqrtf(var + 1e-5f);
    #pragma unroll
    for (int i = 0; i < 4; i++) {
        int idx = t + i*128;
        hi[(size_t)row*EE + idx] = __float2half((v[i]-mu)*r*g[idx] + b[idx]);
    }
}
// x_out = x_in + LN(attn)*g2+b2 ; hh = f16(LN_noaffine(x_out))
__global__ void fuse_attn_res_ln(const float* __restrict__ attn,
                                 const float* __restrict__ xin, float* __restrict__ xout,
                                 __half* __restrict__ hh,
                                 const float* __restrict__ g2, const float* __restrict__ b2) {
    int row = blockIdx.x, t = threadIdx.x;
    const float* ar = attn + (size_t)row * EE;
    float a[4], s = 0.f, s2 = 0.f;
    #pragma unroll
    for (int i = 0; i < 4; i++) { a[i] = ar[t + i*128]; s += a[i]; s2 += a[i]*a[i]; }
    block_reduce2(s, s2);
    float mu = s * (1.f/EE), var = s2 * (1.f/EE) - mu*mu, r = rsqrtf(var + 1e-5f);
    float xv[4];
    s = 0.f; s2 = 0.f;
    #pragma unroll
    for (int i = 0; i < 4; i++) {
        int idx = t + i*128;
        float y = (a[i]-mu)*r*g2[idx] + b2[idx];
        float xn = xin[(size_t)row*EE + idx] + y;
        xout[(size_t)row*EE + idx] = xn;
        xv[i] = xn; s += xn; s2 += xn*xn;
    }
    block_reduce2(s, s2);
    float mu2 = s * (1.f/EE), var2 = s2 * (1.f/EE) - mu2*mu2, r2 = rsqrtf(var2 + 1e-5f);
    #pragma unroll
    for (int i = 0; i < 4; i++) {
        int idx = t + i*128;
        hh[(size_t)row*EE + idx] = __float2half((xv[i]-mu2)*r2);
    }
}

// ---------------- all weights fp32 -> fp16 in ONE launch ---------------------
__global__ void cvt_all(const float4* __restrict__ wq, const float4* __restrict__ wk,
                        const float4* __restrict__ wv, const float4* __restrict__ W1,
                        const float4* __restrict__ W2,
                        __half2* __restrict__ owq, __half2* __restrict__ owk,
                        __half2* __restrict__ owv, __half2* __restrict__ oW1,
                        __half2* __restrict__ oW2) {
    const int NQ = NLAYERS * EE * EE / 4;   // 131072
    const int NW = DFFN * EE / 4;           // 262144
    int i = blockIdx.x * blockDim.x + threadIdx.x;
    const float4* src; __half2* dst; int idx;
    if      (i < NQ)          { src = wq; dst = owq; idx = i; }
    else if (i < 2*NQ)        { src = wk; dst = owk; idx = i - NQ; }
    else if (i < 3*NQ)        { src = wv; dst = owv; idx = i - 2*NQ; }
    else if (i < 3*NQ + NW)   { src = W1; dst = oW1; idx = i - 3*NQ; }
    else if (i < 3*NQ + 2*NW) { src = W2; dst = oW2; idx = i - 3*NQ - NW; }
    else return;
    float4 v = src[idx];
    dst[2*idx]   = __floats2half2_rn(v.x, v.y);
    dst[2*idx+1] = __floats2half2_rn(v.z, v.w);
}

// ---------------- mask compaction: inverse perm + pad zeroing ---------------
__global__ __launch_bounds__(1024) void compact_idx(const int* __restrict__ mask) {
    __shared__ int part[1024];
    int b = blockIdx.x, t = threadIdx.x;
    const int* mb = mask + (size_t)b * SEQ;
    int v0 = (mb[2*t]   == 0);
    int v1 = (mb[2*t+1] == 0);
    part[t] = v0 + v1;
    __syncthreads();
    for (int o = 1; o < 1024; o <<= 1) {
        int x = part[t];
        int y = (t >= o) ? part[t-o] : 0;
        __syncthreads();
        part[t] = x + y;
        __syncthreads();
    }
    int incl = part[t];
    int excl = incl - (v0 + v1);
    g_cpos[b*SEQ + 2*t]   = v0 ? excl : -1;
    g_cpos[b*SEQ + 2*t+1] = v1 ? (excl + v0) : -1;
    int cnt = part[1023];
    if (t == 1023) g_cnt[b] = cnt;
    __syncthreads();
    // zero pad rows [cnt, lim) of compacted K/V (persist across both layers'
    // scatters, which only touch rows < cnt)
    int lim = (cnt + 31) & ~31;
    int padElems = (lim - cnt) * (EE / 8);      // uint4 chunks
    for (int e = t; e < padElems; e += 1024) {
        int j = cnt + e / (EE / 8);
        int c = e % (EE / 8);
        uint4 z; z.x = 0; z.y = 0; z.z = 0; z.w = 0;
        *(uint4*)(g_ckh + ((size_t)b*SEQ + j)*EE + c*8) = z;
        *(uint4*)(g_cvh + ((size_t)b*SEQ + j)*EE + c*8) = z;
    }
}

// ---------------- mma.sync GEMM (fp16 single pass) ---------------------------
// MODE 1: bias+relu -> fp16. MODE 2: fp32+bias+residual. MODE 3: bias -> fp16.
// MODE 5: bias -> fp16 with row scatter via remap (compacted K/V; dst<0 = drop).
template<int MODE>
__device__ __forceinline__ void gemm_mma_body(
    const __half* __restrict__ A, const __half* __restrict__ B,
    const float* __restrict__ bias, int K, int N,
    float* __restrict__ Cf, __half* __restrict__ Ch,
    const float* __restrict__ res, const int* __restrict__ remap,
    int rowBase, int colBase)
{
    extern __shared__ char sm8[];
    uint32_t sbase = smem_u32(sm8);
    int tid = threadIdx.x, lane = tid & 31, warp = tid >> 5;
    int wm = warp >> 2, wn = warp & 3;

    float acc[4][4][4];
    #pragma unroll
    for (int i = 0; i < 4; i++)
        #pragma unroll
        for (int j = 0; j < 4; j++)
            #pragma unroll
            for (int c = 0; c < 4; c++) acc[i][j][c] = 0.f;

    uint32_t aAddr = (uint32_t)((wm*64 + ((lane>>3)&1)*8 + (lane&7)) * GM_STRIDE
                                + (lane>>4)*16);
    uint32_t bAddr = (uint32_t)((wn*32 + (lane>>4)*8 + (lane&7)) * GM_STRIDE
                                + ((lane>>3)&1)*16);

    const int T = K / GM_CHUNK;
    int lrow0 = tid >> 2, lseg = tid & 3;

    {
        uint32_t sb = sbase;
        #pragma unroll
        for (int j = 0; j < 2; j++) {
            int row = lrow0 + j*64;
            uint32_t so = row*GM_STRIDE + lseg*16;
            cp16(sb + 0*GM_MAT_BYTES + so, A + (size_t)(rowBase+row)*K + lseg*8);
            cp16(sb + 1*GM_MAT_BYTES + so, B + (size_t)(colBase+row)*K + lseg*8);
        }
        cp_commit();
    }

    for (int t = 0; t < T; t++) {
        cp_wait0();
        __syncthreads();
        if (t + 1 < T) {
            uint32_t sb = sbase + ((t+1) & 1) * GM_BUF_BYTES;
            int koff = (t+1) * GM_CHUNK;
            #pragma unroll
            for (int j = 0; j < 2; j++) {
                int row = lrow0 + j*64;
                uint32_t so = row*GM_STRIDE + lseg*16;
                cp16(sb + 0*GM_MAT_BYTES + so, A + (size_t)(rowBase+row)*K + koff + lseg*8);
                cp16(sb + 1*GM_MAT_BYTES + so, B + (size_t)(colBase+row)*K + koff + lseg*8);
            }
            cp_commit();
        }
        uint32_t buf = sbase + (t & 1) * GM_BUF_BYTES;
        #pragma unroll
        for (int ks = 0; ks < 2; ks++) {
            uint32_t ah[4][4], bh[2][4];
            #pragma unroll
            for (int i = 0; i < 4; i++)
                ldmx4(ah[i], buf + aAddr + i*16*GM_STRIDE + ks*32);
            #pragma unroll
            for (int p = 0; p < 2; p++)
                ldmx4(bh[p], buf + GM_MAT_BYTES + bAddr + p*16*GM_STRIDE + ks*32);
            #pragma unroll
            for (int i = 0; i < 4; i++)
                #pragma unroll
                for (int j = 0; j < 4; j++)
                    mma_f16(acc[i][j], ah[i], &bh[j>>1][(j&1)*2]);
        }
    }

    int g = lane >> 2, tg = lane & 3;
    #pragma unroll
    for (int i = 0; i < 4; i++) {
        int r0 = rowBase + wm*64 + i*16 + g;
        #pragma unroll
        for (int j = 0; j < 4; j++) {
            int c = colBase + wn*32 + j*8 + tg*2;
            float b0 = bias[c], b1 = bias[c+1];
            #pragma unroll
            for (int half = 0; half < 2; half++) {
                int r = r0 + half*8;
                float v0 = acc[i][j][half*2+0] + b0;
                float v1 = acc[i][j][half*2+1] + b1;
                if (MODE == 1 || MODE == 3) {
                    if (MODE == 1) { v0 = fmaxf(v0, 0.f); v1 = fmaxf(v1, 0.f); }
                    *(__half2*)&Ch[(size_t)r * N + c] = __floats2half2_rn(v0, v1);
                } else if (MODE == 5) {
                    int dst = remap[r];
                    if (dst >= 0) {
                        size_t rr = (size_t)(r & ~(SEQ-1)) + dst;
                        *(__half2*)&Ch[rr * N + c] = __floats2half2_rn(v0, v1);
                    }
                } else {
                    if (MODE == 2) {
                        float2 rv = *(const float2*)&res[(size_t)r * N + c];
                        v0 += rv.x; v1 += rv.y;
                    }
                    float2 o; o.x = v0; o.y = v1;
                    *(float2*)&Cf[(size_t)r * N + c] = o;
                }
            }
        }
    }
}

template<int MODE>
__global__ __launch_bounds__(256, 2) void gemm_mma(
    const __half* __restrict__ A, const __half* __restrict__ B,
    const float* __restrict__ bias, int K, int N,
    float* __restrict__ Cf, __half* __restrict__ Ch, const float* __restrict__ res)
{
    gemm_mma_body<MODE>(A, B, bias, K, N, Cf, Ch, res, nullptr,
                        blockIdx.y * 128, blockIdx.x * 128);
}

__global__ __launch_bounds__(256, 2) void gemm_mma_qkv(
    const __half* __restrict__ hh,
    const __half* __restrict__ wqh, const __half* __restrict__ wkh,
    const __half* __restrict__ wvh,
    const float* __restrict__ bq, const float* __restrict__ bk, const float* __restrict__ bv,
    __half* qh)
{
    if (blockIdx.z == 0) {
        gemm_mma_body<3>(hh, wqh, bq, EE, EE, nullptr, qh, nullptr, nullptr,
                         blockIdx.y * 128, blockIdx.x * 128);
    } else if (blockIdx.z == 1) {
        gemm_mma_body<5>(hh, wkh, bk, EE, EE, nullptr, g_ckh, nullptr, g_cpos,
                         blockIdx.y * 128, blockIdx.x * 128);
    } else {
        gemm_mma_body<5>(hh, wvh, bv, EE, EE, nullptr, g_cvh, nullptr, g_cpos,
                         blockIdx.y * 128, blockIdx.x * 128);
    }
}

// ---------------- Flash attention (fp16 single pass, compacted keys) ---------
__global__ __launch_bounds__(256) void flash_attn_mma(
    const __half* __restrict__ qh_g, float* __restrict__ out)
{
    extern __shared__ char fsm[];
    uint32_t sQ  = smem_u32(fsm);
    uint32_t sKV = sQ + FB_Q_BYTES;

    int tid = threadIdx.x, lane = tid & 31, warp = tid >> 5;
    int g = lane >> 2, tg = lane & 3;
    int q0 = blockIdx.x * 128;
    int h  = blockIdx.y;
    int b  = blockIdx.z;
    int hoff = h * DDIM;
    size_t bS = (size_t)b * SEQ;

    int cnt = g_cnt[b];
    const int T = (cnt + 31) >> 5;

    {
        int row = tid >> 3, seg = tid & 7;
        #pragma unroll
        for (int i = 0; i < 4; i++) {
            int r = row + i * 32;
            cp16(sQ + (uint32_t)r * FB_STRIDE_B + seg * 16,
                 qh_g + (bS + q0 + r) * EE + hoff + seg * 8);
        }
        uint32_t so = (uint32_t)row * FB_STRIDE_B + seg * 16;
        size_t gk = (bS + row) * EE + hoff + seg * 8;
        cp16(sKV + 0*FB_KV_MAT + so, g_ckh + gk);
        cp16(sKV + 1*FB_KV_MAT + so, g_cvh + gk);
        cp_commit();
    }
    cp_wait0();
    __syncthreads();

    uint32_t qf[4][4];
    {
        uint32_t base = (uint32_t)(warp*16 + ((lane>>3)&1)*8 + (lane&7)) * FB_STRIDE_B
                      + (lane>>4)*16;
        #pragma unroll
        for (int ks = 0; ks < 4; ks++)
            ldmx4(qf[ks], sQ + base + ks*32);
    }

    float accO[8][4];
    #pragma unroll
    for (int j = 0; j < 8; j++)
        #pragma unroll
        for (int c = 0; c < 4; c++) accO[j][c] = 0.f;
    float mOld0 = -1e30f, mOld1 = -1e30f, l0 = 0.f, l1 = 0.f;

    uint32_t kAddrBase = (uint32_t)(((lane>>4)*8 + (lane&7)) * FB_STRIDE_B)
                       + ((lane>>3)&1)*16;
    uint32_t vAddrBase = (uint32_t)((((lane>>3)&1)*8 + (lane&7)) * FB_STRIDE_B)
                       + (lane>>4)*16;

    for (int it = 0; it < T; it++) {
        if (it + 1 < T) {
            uint32_t stg2 = sKV + ((it+1) & 1) * FB_STAGE;
            int row = tid >> 3, seg = tid & 7;
            uint32_t so = (uint32_t)row * FB_STRIDE_B + seg * 16;
            size_t gk = (bS + (it+1)*32 + row) * EE + hoff + seg * 8;
            cp16(stg2 + 0*FB_KV_MAT + so, g_ckh + gk);
            cp16(stg2 + 1*FB_KV_MAT + so, g_cvh + gk);
            cp_commit();
            cp_wait1();
        } else {
            cp_wait0();
        }
        __syncthreads();

        uint32_t stg = sKV + (it & 1) * FB_STAGE;

        float accS[4][4];
        #pragma unroll
        for (int j = 0; j < 4; j++)
            #pragma unroll
            for (int c = 0; c < 4; c++) accS[j][c] = 0.f;
        #pragma unroll
        for (int ks = 0; ks < 4; ks++) {
            uint32_t bh[2][4];
            #pragma unroll
            for (int p = 0; p < 2; p++)
                ldmx4(bh[p], stg + kAddrBase + (uint32_t)p*16*FB_STRIDE_B + ks*32);
            #pragma unroll
            for (int j = 0; j < 4; j++)
                mma_f16(accS[j], qf[ks], &bh[j>>1][(j&1)*2]);
        }

        int lim = cnt - it*32;
        if (lim >= 32) {
            #pragma unroll
            for (int j = 0; j < 4; j++) {
                accS[j][0] *= 0.125f; accS[j][1] *= 0.125f;
                accS[j][2] *= 0.125f; accS[j][3] *= 0.125f;
            }
        } else {
            #pragma unroll
            for (int j = 0; j < 4; j++) {
                int n0 = j*8 + tg*2;
                bool k0 = n0 < lim, k1 = (n0 + 1) < lim;
                accS[j][0] = k0 ? accS[j][0]*0.125f : -1e30f;
                accS[j][1] = k1 ? accS[j][1]*0.125f : -1e30f;
                accS[j][2] = k0 ? accS[j][2]*0.125f : -1e30f;
                accS[j][3] = k1 ? accS[j][3]*0.125f : -1e30f;
            }
        }
        float mx0 = -1e30f, mx1 = -1e30f;
        #pragma unroll
        for (int j = 0; j < 4; j++) {
            mx0 = fmaxf(mx0, fmaxf(accS[j][0], accS[j][1]));
            mx1 = fmaxf(mx1, fmaxf(accS[j][2], accS[j][3]));
        }
        mx0 = fmaxf(mx0, __shfl_xor_sync(0xffffffffu, mx0, 1));
        mx0 = fmaxf(mx0, __shfl_xor_sync(0xffffffffu, mx0, 2));
        mx1 = fmaxf(mx1, __shfl_xor_sync(0xffffffffu, mx1, 1));
        mx1 = fmaxf(mx1, __shfl_xor_sync(0xffffffffu, mx1, 2));
        float mn0 = fmaxf(mOld0, mx0), mn1 = fmaxf(mOld1, mx1);
        float scl0 = __expf(mOld0 - mn0), scl1 = __expf(mOld1 - mn1);
        float p[4][4];
        float ls0 = 0.f, ls1 = 0.f;
        #pragma unroll
        for (int j = 0; j < 4; j++) {
            p[j][0] = __expf(accS[j][0] - mn0);
            p[j][1] = __expf(accS[j][1] - mn0);
            p[j][2] = __expf(accS[j][2] - mn1);
            p[j][3] = __expf(accS[j][3] - mn1);
            ls0 += p[j][0] + p[j][1];
            ls1 += p[j][2] + p[j][3];
        }
        ls0 += __shfl_xor_sync(0xffffffffu, ls0, 1);
        ls0 += __shfl_xor_sync(0xffffffffu, ls0, 2);
        ls1 += __shfl_xor_sync(0xffffffffu, ls1, 1);
        ls1 += __shfl_xor_sync(0xffffffffu, ls1, 2);
        l0 = l0 * scl0 + ls0;
        l1 = l1 * scl1 + ls1;
        mOld0 = mn0; mOld1 = mn1;
        #pragma unroll
        for (int j = 0; j < 8; j++) {
            accO[j][0] *= scl0; accO[j][1] *= scl0;
            accO[j][2] *= scl1; accO[j][3] *= scl1;
        }

        uint32_t ap[2][4];
        #pragma unroll
        for (int jj = 0; jj < 2; jj++) {
            int t0 = 2*jj, t1 = 2*jj + 1;
            __half2 x0 = __floats2half2_rn(p[t0][0], p[t0][1]);
            __half2 x1 = __floats2half2_rn(p[t0][2], p[t0][3]);
            __half2 x2 = __floats2half2_rn(p[t1][0], p[t1][1]);
            __half2 x3 = __floats2half2_rn(p[t1][2], p[t1][3]);
            ap[jj][0] = *reinterpret_cast<uint32_t*>(&x0);
            ap[jj][1] = *reinterpret_cast<uint32_t*>(&x1);
            ap[jj][2] = *reinterpret_cast<uint32_t*>(&x2);
            ap[jj][3] = *reinterpret_cast<uint32_t*>(&x3);
        }

        #pragma unroll
        for (int ks2 = 0; ks2 < 2; ks2++) {
            uint32_t v2[4][4];
            #pragma unroll
            for (int ng = 0; ng < 4; ng++)
                ldmx4t(v2[ng], stg + FB_KV_MAT + vAddrBase
                               + (uint32_t)ks2*16*FB_STRIDE_B + ng*32);
            #pragma unroll
            for (int jd = 0; jd < 8; jd++)
                mma_f16(accO[jd], ap[ks2], &v2[jd>>1][(jd&1)*2]);
        }
        __syncthreads();
    }

    float inv0 = 1.f / l0, inv1 = 1.f / l1;
    size_t row0 = bS + q0 + warp*16 + g;
    #pragma unroll
    for (int jd = 0; jd < 8; jd++) {
        int c = hoff + jd*8 + tg*2;
        float2 o0; o0.x = accO[jd][0] * inv0; o0.y = accO[jd][1] * inv0;
        float2 o1; o1.x = accO[jd][2] * inv1; o1.y = accO[jd][3] * inv1;
        *(float2*)&out[row0 * EE + c]       = o0;
        *(float2*)&out[(row0 + 8) * EE + c] = o1;
    }
}

// ---------------- launch ----------------------------------------------------
extern "C" void kernel_launch(void* const* d_in, const int* in_sizes, int n_in,
                              void* d_out, int out_size) {
    const float* x_in = (const float*)d_in[0];
    const int* mask = (const int*)d_in[1];
    const float* wq = (const float*)d_in[2];
    const float* bq = (const float*)d_in[3];
    const float* wk = (const float*)d_in[4];
    const float* bk = (const float*)d_in[5];
    const float* wv = (const float*)d_in[6];
    const float* bv = (const float*)d_in[7];
    const float* g1 = (const float*)d_in[8];
    const float* b1 = (const float*)d_in[9];
    const float* g2 = (const float*)d_in[10];
    const float* b2 = (const float*)d_in[11];
    const float* gf = (const float*)d_in[12];
    const float* bf = (const float*)d_in[13];
    const float* W1 = (const float*)d_in[14];
    const float* B1 = (const float*)d_in[15];
    const float* W2 = (const float*)d_in[16];
    const float* B2 = (const float*)d_in[17];
    float* outp = (float*)d_out;

    float *px, *pattn;
    __half *pqh, *phh, *pfh;
    __half *pwqh, *pwkh, *pwvh, *pW1h, *pW2h;
    cudaGetSymbolAddress((void**)&px,    g_x);
    cudaGetSymbolAddress((void**)&pattn, g_attn);
    cudaGetSymbolAddress((void**)&pqh,   g_qh);
    cudaGetSymbolAddress((void**)&phh,   g_hh);
    cudaGetSymbolAddress((void**)&pfh,   g_fh);
    cudaGetSymbolAddress((void**)&pwqh,  g_wqh);
    cudaGetSymbolAddress((void**)&pwkh,  g_wkh);
    cudaGetSymbolAddress((void**)&pwvh,  g_wvh);
    cudaGetSymbolAddress((void**)&pW1h,  g_W1h);
    cudaGetSymbolAddress((void**)&pW2h,  g_W2h);

    cudaFuncSetAttribute(flash_attn_mma,
                         cudaFuncAttributeMaxDynamicSharedMemorySize, FB_SMEM);
    cudaFuncSetAttribute(gemm_mma_qkv,
                         cudaFuncAttributeMaxDynamicSharedMemorySize, GM_SMEM);
    cudaFuncSetAttribute(gemm_mma<1>,
                         cudaFuncAttributeMaxDynamicSharedMemorySize, GM_SMEM);
    cudaFuncSetAttribute(gemm_mma<2>,
                         cudaFuncAttributeMaxDynamicSharedMemorySize, GM_SMEM);

    {
        const int NQ = NLAYERS * EE * EE / 4;
        const int NW = DFFN * EE / 4;
        int total = 3*NQ + 2*NW;
        cvt_all<<<(total + 255) / 256, 256>>>(
            (const float4*)wq, (const float4*)wk, (const float4*)wv,
            (const float4*)W1, (const float4*)W2,
            (__half2*)pwqh, (__half2*)pwkh, (__half2*)pwvh,
            (__half2*)pW1h, (__half2*)pW2h);
    }
    compact_idx<<<BB, 1024>>>(mask);       // mask is layer-invariant

    dim3 gQKV(EE / 128, NROWS / 128, 3);   // (4, 32, 3)
    dim3 gFF1(DFFN / 128, NROWS / 128);    // (16, 32)
    dim3 gFF2(EE / 128, NROWS / 128);      // (4, 32)
    dim3 gAtt(SEQ / 128, HH, BB);          // (16, 8, 2)

    for (int l = 0; l < NLAYERS; l++) {
        const __half* wqhl = pwqh + (size_t)l * EE * EE;
        const __half* wkhl = pwkh + (size_t)l * EE * EE;
        const __half* wvhl = pwvh + (size_t)l * EE * EE;
        const float* bql = bq + (size_t)l * EE;
        const float* bkl = bk + (size_t)l * EE;
        const float* bvl = bv + (size_t)l * EE;
        const float* xsrc = (l == 0) ? x_in : px;

        ln_f16<<<NROWS, 128>>>(xsrc, phh, g1, b1);
        gemm_mma_qkv<<<gQKV, 256, GM_SMEM>>>(phh, wqhl, wkhl, wvhl,
            bql, bkl, bvl, pqh);
        flash_attn_mma<<<gAtt, 256, FB_SMEM>>>(pqh, pattn);
        fuse_attn_res_ln<<<NROWS, 128>>>(pattn, xsrc, px, phh, g2, b2);
        gemm_mma<1><<<gFF1, 256, GM_SMEM>>>(phh, pW1h, B1, EE, DFFN,
            nullptr, pfh, nullptr);
        gemm_mma<2><<<gFF2, 256, GM_SMEM>>>(pfh, pW2h, B2, DFFN, EE,
            px, nullptr, px);
    }
    ln_f32<<<NROWS, 128>>>(px, outp, gf, bf);
}

// round 15
// speedup vs baseline: 2.2530x; 1.0046x over previous
#include <cuda_runtime.h>
#include <cuda_fp16.h>
#include <stdint.h>

#define BB      2
#define SEQ     2048
#define EE      512
#define HH      8
#define DDIM    64
#define NLAYERS 2
#define DFFN    2048
#define NROWS   4096   // BB*SEQ

// mma.sync GEMM config: 128x128 tile, K-chunk 32 (fp16), 4-stage pipeline
#define GM_CHUNK     32
#define GM_STRIDE    80                    // 32 fp16 = 64B + 16B pad
#define GM_MAT_BYTES (128 * GM_STRIDE)     // 10240
#define GM_BUF_BYTES (2 * GM_MAT_BYTES)    // A, B = 20480
#define GM_STAGES    4
#define GM_SMEM      (GM_STAGES * GM_BUF_BYTES)   // 81920

// flash mma config: BQ=128, BK=32, 8 warps, 4-stage KV pipeline
#define FB_STRIDE_B  144                   // 64 fp16 = 128B + 16B pad
#define FB_Q_BYTES   (128 * FB_STRIDE_B)   // 18432
#define FB_KV_MAT    (32 * FB_STRIDE_B)    // 4608
#define FB_STAGE     (2 * FB_KV_MAT)       // K, V = 9216
#define FB_STAGES    4
#define FB_SMEM      (FB_Q_BYTES + FB_STAGES*FB_STAGE + 256)

// ---------------- scratch (device globals) ----------------------------------
__device__ float g_x[NROWS * EE];
__device__ float g_attn[NROWS * EE];
__device__ __half g_qh[NROWS*EE];
__device__ __half g_ckh[NROWS*EE];    // compacted K (scatter target)
__device__ __half g_cvh[NROWS*EE];    // compacted V (scatter target)
__device__ int g_cnt[BB];
__device__ int g_cpos[BB*SEQ];        // src row -> compacted row (-1 = masked)
__device__ __half g_hh[NROWS * EE];
__device__ __half g_fh[NROWS * DFFN];
__device__ __half g_wqh[NLAYERS*EE*EE];
__device__ __half g_wkh[NLAYERS*EE*EE];
__device__ __half g_wvh[NLAYERS*EE*EE];
__device__ __half g_W1h[DFFN*EE];
__device__ __half g_W2h[EE*DFFN];

// ---------------- PTX helpers ------------------------------------------------
__device__ __forceinline__ uint32_t smem_u32(const void* p) {
    uint32_t a;
    asm("{ .reg .u64 t; cvta.to.shared.u64 t, %1; cvt.u32.u64 %0, t; }" : "=r"(a) : "l"(p));
    return a;
}
__device__ __forceinline__ void cp16(uint32_t saddr, const void* g) {
    asm volatile("cp.async.cg.shared.global [%0], [%1], 16;" :: "r"(saddr), "l"(g));
}
__device__ __forceinline__ void cp_commit() {
    asm volatile("cp.async.commit_group;" ::: "memory");
}
__device__ __forceinline__ void cp_wait0() {
    asm volatile("cp.async.wait_group 0;" ::: "memory");
}
__device__ __forceinline__ void cp_wait2() {
    asm volatile("cp.async.wait_group 2;" ::: "memory");
}
__device__ __forceinline__ void ldmx4(uint32_t* r, uint32_t addr) {
    asm volatile("ldmatrix.sync.aligned.m8n8.x4.shared.b16 {%0,%1,%2,%3}, [%4];"
        : "=r"(r[0]), "=r"(r[1]), "=r"(r[2]), "=r"(r[3]) : "r"(addr));
}
__device__ __forceinline__ void ldmx4t(uint32_t* r, uint32_t addr) {
    asm volatile("ldmatrix.sync.aligned.m8n8.x4.trans.shared.b16 {%0,%1,%2,%3}, [%4];"
        : "=r"(r[0]), "=r"(r[1]), "=r"(r[2]), "=r"(r[3]) : "r"(addr));
}
__device__ __forceinline__ void mma_f16(float* d, const uint32_t* a, const uint32_t* b) {
    asm volatile(
        "mma.sync.aligned.m16n8k16.row.col.f32.f16.f16.f32 "
        "{%0,%1,%2,%3}, {%4,%5,%6,%7}, {%8,%9}, {%0,%1,%2,%3};"
        : "+f"(d[0]), "+f"(d[1]), "+f"(d[2]), "+f"(d[3])
        : "r"(a[0]), "r"(a[1]), "r"(a[2]), "r"(a[3]), "r"(b[0]), "r"(b[1]));
}

// ---------------- reductions -------------------------------------------------
__device__ __forceinline__ void block_reduce2(float& s, float& s2) {
    __shared__ float shm[8];
    #pragma unroll
    for (int o = 16; o > 0; o >>= 1) {
        s  += __shfl_down_sync(0xffffffffu, s,  o);
        s2 += __shfl_down_sync(0xffffffffu, s2, o);
    }
    int w = threadIdx.x >> 5;
    __syncthreads();
    if ((threadIdx.x & 31) == 0) { shm[w] = s; shm[4 + w] = s2; }
    __syncthreads();
    s  = shm[0] + shm[1] + shm[2] + shm[3];
    s2 = shm[4] + shm[5] + shm[6] + shm[7];
}

// ---------------- LayerNorm variants ----------------------------------------
__global__ void ln_f32(const float* __restrict__ in, float* __restrict__ outp,
                       const float* __restrict__ g, const float* __restrict__ b) {
    int row = blockIdx.x, t = threadIdx.x;
    const float* xr = in + (size_t)row * EE;
    float v[4], s = 0.f, s2 = 0.f;
    #pragma unroll
    for (int i = 0; i < 4; i++) { v[i] = xr[t + i*128]; s += v[i]; s2 += v[i]*v[i]; }
    block_reduce2(s, s2);
    float mu = s * (1.f/EE), var = s2 * (1.f/EE) - mu*mu, r = rsqrtf(var + 1e-5f);
    #pragma unroll
    for (int i = 0; i < 4; i++) {
        int idx = t + i*128;
        outp[(size_t)row*EE + idx] = (v[i]-mu)*r*g[idx] + b[idx];
    }
}
__global__ void ln_f16(const float* __restrict__ in, __half* __restrict__ hi,
                       const float* __restrict__ g, const float* __restrict__ b) {
    int row = blockIdx.x, t = threadIdx.x;
    const float* xr = in + (size_t)row * EE;
    float v[4], s = 0.f, s2 = 0.f;
    #pragma unroll
    for (int i = 0; i < 4; i++) { v[i] = xr[t + i*128]; s += v[i]; s2 += v[i]*v[i]; }
    block_reduce2(s, s2);
    float mu = s * (1.f/EE), var = s2 * (1.f/EE) - mu*mu, r = rsqrtf(var + 1e-5f);
    #pragma unroll
    for (int i = 0; i < 4; i++) {
        int idx = t + i*128;
        hi[(size_t)row*EE + idx] = __float2half((v[i]-mu)*r*g[idx] + b[idx]);
    }
}
// x_out = x_in + LN(attn)*g2+b2 ; hh = f16(LN_noaffine(x_out))
__global__ void fuse_attn_res_ln(const float* __restrict__ attn,
                                 const float* __restrict__ xin, float* __restrict__ xout,
                                 __half* __restrict__ hh,
                                 const float* __restrict__ g2, const float* __restrict__ b2) {
    int row = blockIdx.x, t = threadIdx.x;
    const float* ar = attn + (size_t)row * EE;
    float a[4], s = 0.f, s2 = 0.f;
    #pragma unroll
    for (int i = 0; i < 4; i++) { a[i] = ar[t + i*128]; s += a[i]; s2 += a[i]*a[i]; }
    block_reduce2(s, s2);
    float mu = s * (1.f/EE), var = s2 * (1.f/EE) - mu*mu, r = rsqrtf(var + 1e-5f);
    float xv[4];
    s = 0.f; s2 = 0.f;
    #pragma unroll
    for (int i = 0; i < 4; i++) {
        int idx = t + i*128;
        float y = (a[i]-mu)*r*g2[idx] + b2[idx];
        float xn = xin[(size_t)row*EE + idx] + y;
        xout[(size_t)row*EE + idx] = xn;
        xv[i] = xn; s += xn; s2 += xn*xn;
    }
    block_reduce2(s, s2);
    float mu2 = s * (1.f/EE), var2 = s2 * (1.f/EE) - mu2*mu2, r2 = rsqrtf(var2 + 1e-5f);
    #pragma unroll
    for (int i = 0; i < 4; i++) {
        int idx = t + i*128;
        hh[(size_t)row*EE + idx] = __float2half((xv[i]-mu2)*r2);
    }
}

// ---------------- all weights fp32 -> fp16 in ONE launch ---------------------
__global__ void cvt_all(const float4* __restrict__ wq, const float4* __restrict__ wk,
                        const float4* __restrict__ wv, const float4* __restrict__ W1,
                        const float4* __restrict__ W2,
                        __half2* __restrict__ owq, __half2* __restrict__ owk,
                        __half2* __restrict__ owv, __half2* __restrict__ oW1,
                        __half2* __restrict__ oW2) {
    const int NQ = NLAYERS * EE * EE / 4;
    const int NW = DFFN * EE / 4;
    int i = blockIdx.x * blockDim.x + threadIdx.x;
    const float4* src; __half2* dst; int idx;
    if      (i < NQ)          { src = wq; dst = owq; idx = i; }
    else if (i < 2*NQ)        { src = wk; dst = owk; idx = i - NQ; }
    else if (i < 3*NQ)        { src = wv; dst = owv; idx = i - 2*NQ; }
    else if (i < 3*NQ + NW)   { src = W1; dst = oW1; idx = i - 3*NQ; }
    else if (i < 3*NQ + 2*NW) { src = W2; dst = oW2; idx = i - 3*NQ - NW; }
    else return;
    float4 v = src[idx];
    dst[2*idx]   = __floats2half2_rn(v.x, v.y);
    dst[2*idx+1] = __floats2half2_rn(v.z, v.w);
}

// ---------------- mask compaction: inverse perm + pad zeroing ---------------
__global__ __launch_bounds__(1024) void compact_idx(const int* __restrict__ mask) {
    __shared__ int part[1024];
    int b = blockIdx.x, t = threadIdx.x;
    const int* mb = mask + (size_t)b * SEQ;
    int v0 = (mb[2*t]   == 0);
    int v1 = (mb[2*t+1] == 0);
    part[t] = v0 + v1;
    __syncthreads();
    for (int o = 1; o < 1024; o <<= 1) {
        int x = part[t];
        int y = (t >= o) ? part[t-o] : 0;
        __syncthreads();
        part[t] = x + y;
        __syncthreads();
    }
    int incl = part[t];
    int excl = incl - (v0 + v1);
    g_cpos[b*SEQ + 2*t]   = v0 ? excl : -1;
    g_cpos[b*SEQ + 2*t+1] = v1 ? (excl + v0) : -1;
    int cnt = part[1023];
    if (t == 1023) g_cnt[b] = cnt;
    __syncthreads();
    int lim = (cnt + 31) & ~31;
    int padElems = (lim - cnt) * (EE / 8);
    for (int e = t; e < padElems; e += 1024) {
        int j = cnt + e / (EE / 8);
        int c = e % (EE / 8);
        uint4 z; z.x = 0; z.y = 0; z.z = 0; z.w = 0;
        *(uint4*)(g_ckh + ((size_t)b*SEQ + j)*EE + c*8) = z;
        *(uint4*)(g_cvh + ((size_t)b*SEQ + j)*EE + c*8) = z;
    }
}

// ---------------- mma.sync GEMM (fp16, 4-stage cp.async pipeline) ------------
// MODE 1: bias+relu -> fp16. MODE 2: fp32+bias+residual. MODE 3: bias -> fp16.
// MODE 5: bias -> fp16 with row scatter via remap (compacted K/V; dst<0 = drop).
template<int MODE>
__device__ __forceinline__ void gemm_mma_body(
    const __half* __restrict__ A, const __half* __restrict__ B,
    const float* __restrict__ bias, int K, int N,
    float* __restrict__ Cf, __half* __restrict__ Ch,
    const float* __restrict__ res, const int* __restrict__ remap,
    int rowBase, int colBase)
{
    extern __shared__ char sm8[];
    uint32_t sbase = smem_u32(sm8);
    int tid = threadIdx.x, lane = tid & 31, warp = tid >> 5;
    int wm = warp >> 2, wn = warp & 3;

    float acc[4][4][4];
    #pragma unroll
    for (int i = 0; i < 4; i++)
        #pragma unroll
        for (int j = 0; j < 4; j++)
            #pragma unroll
            for (int c = 0; c < 4; c++) acc[i][j][c] = 0.f;

    uint32_t aAddr = (uint32_t)((wm*64 + ((lane>>3)&1)*8 + (lane&7)) * GM_STRIDE
                                + (lane>>4)*16);
    uint32_t bAddr = (uint32_t)((wn*32 + (lane>>4)*8 + (lane&7)) * GM_STRIDE
                                + ((lane>>3)&1)*16);

    const int T = K / GM_CHUNK;
    int lrow0 = tid >> 2, lseg = tid & 3;

    // prologue: issue stages 0..2 (one commit group each)
    #pragma unroll
    for (int s = 0; s < GM_STAGES - 1; s++) {
        if (s < T) {
            uint32_t sb = sbase + s * GM_BUF_BYTES;
            int koff = s * GM_CHUNK;
            #pragma unroll
            for (int j = 0; j < 2; j++) {
                int row = lrow0 + j*64;
                uint32_t so = row*GM_STRIDE + lseg*16;
                cp16(sb + 0*GM_MAT_BYTES + so, A + (size_t)(rowBase+row)*K + koff + lseg*8);
                cp16(sb + 1*GM_MAT_BYTES + so, B + (size_t)(colBase+row)*K + koff + lseg*8);
            }
        }
        cp_commit();
    }

    for (int t = 0; t < T; t++) {
        cp_wait2();                 // chunk t's group complete
        __syncthreads();
        // prefetch chunk t+3 into buffer (t+3)%4 (consumed at t-1, all synced)
        if (t + GM_STAGES - 1 < T) {
            uint32_t sb = sbase + ((t + GM_STAGES - 1) & (GM_STAGES-1)) * GM_BUF_BYTES;
            int koff = (t + GM_STAGES - 1) * GM_CHUNK;
            #pragma unroll
            for (int j = 0; j < 2; j++) {
                int row = lrow0 + j*64;
                uint32_t so = row*GM_STRIDE + lseg*16;
                cp16(sb + 0*GM_MAT_BYTES + so, A + (size_t)(rowBase+row)*K + koff + lseg*8);
                cp16(sb + 1*GM_MAT_BYTES + so, B + (size_t)(colBase+row)*K + koff + lseg*8);
            }
        }
        cp_commit();                // always commit (empty groups keep counts uniform)

        uint32_t buf = sbase + (t & (GM_STAGES-1)) * GM_BUF_BYTES;
        #pragma unroll
        for (int ks = 0; ks < 2; ks++) {
            uint32_t ah[4][4], bh[2][4];
            #pragma unroll
            for (int i = 0; i < 4; i++)
                ldmx4(ah[i], buf + aAddr + i*16*GM_STRIDE + ks*32);
            #pragma unroll
            for (int p = 0; p < 2; p++)
                ldmx4(bh[p], buf + GM_MAT_BYTES + bAddr + p*16*GM_STRIDE + ks*32);
            #pragma unroll
            for (int i = 0; i < 4; i++)
                #pragma unroll
                for (int j = 0; j < 4; j++)
                    mma_f16(acc[i][j], ah[i], &bh[j>>1][(j&1)*2]);
        }
    }

    int g = lane >> 2, tg = lane & 3;
    #pragma unroll
    for (int i = 0; i < 4; i++) {
        int r0 = rowBase + wm*64 + i*16 + g;
        #pragma unroll
        for (int j = 0; j < 4; j++) {
            int c = colBase + wn*32 + j*8 + tg*2;
            float b0 = bias[c], b1 = bias[c+1];
            #pragma unroll
            for (int half = 0; half < 2; half++) {
                int r = r0 + half*8;
                float v0 = acc[i][j][half*2+0] + b0;
                float v1 = acc[i][j][half*2+1] + b1;
                if (MODE == 1 || MODE == 3) {
                    if (MODE == 1) { v0 = fmaxf(v0, 0.f); v1 = fmaxf(v1, 0.f); }
                    *(__half2*)&Ch[(size_t)r * N + c] = __floats2half2_rn(v0, v1);
                } else if (MODE == 5) {
                    int dst = remap[r];
                    if (dst >= 0) {
                        size_t rr = (size_t)(r & ~(SEQ-1)) + dst;
                        *(__half2*)&Ch[rr * N + c] = __floats2half2_rn(v0, v1);
                    }
                } else {
                    if (MODE == 2) {
                        float2 rv = *(const float2*)&res[(size_t)r * N + c];
                        v0 += rv.x; v1 += rv.y;
                    }
                    float2 o; o.x = v0; o.y = v1;
                    *(float2*)&Cf[(size_t)r * N + c] = o;
                }
            }
        }
    }
}

template<int MODE>
__global__ __launch_bounds__(256, 2) void gemm_mma(
    const __half* __restrict__ A, const __half* __restrict__ B,
    const float* __restrict__ bias, int K, int N,
    float* __restrict__ Cf, __half* __restrict__ Ch, const float* __restrict__ res)
{
    gemm_mma_body<MODE>(A, B, bias, K, N, Cf, Ch, res, nullptr,
                        blockIdx.y * 128, blockIdx.x * 128);
}

__global__ __launch_bounds__(256, 2) void gemm_mma_qkv(
    const __half* __restrict__ hh,
    const __half* __restrict__ wqh, const __half* __restrict__ wkh,
    const __half* __restrict__ wvh,
    const float* __restrict__ bq, const float* __restrict__ bk, const float* __restrict__ bv,
    __half* qh)
{
    if (blockIdx.z == 0) {
        gemm_mma_body<3>(hh, wqh, bq, EE, EE, nullptr, qh, nullptr, nullptr,
                         blockIdx.y * 128, blockIdx.x * 128);
    } else if (blockIdx.z == 1) {
        gemm_mma_body<5>(hh, wkh, bk, EE, EE, nullptr, g_ckh, nullptr, g_cpos,
                         blockIdx.y * 128, blockIdx.x * 128);
    } else {
        gemm_mma_body<5>(hh, wvh, bv, EE, EE, nullptr, g_cvh, nullptr, g_cpos,
                         blockIdx.y * 128, blockIdx.x * 128);
    }
}

// ---------------- Flash attention (fp16, 4-stage KV pipeline) ----------------
__global__ __launch_bounds__(256) void flash_attn_mma(
    const __half* __restrict__ qh_g, float* __restrict__ out)
{
    extern __shared__ char fsm[];
    uint32_t sQ  = smem_u32(fsm);
    uint32_t sKV = sQ + FB_Q_BYTES;

    int tid = threadIdx.x, lane = tid & 31, warp = tid >> 5;
    int g = lane >> 2, tg = lane & 3;
    int q0 = blockIdx.x * 128;
    int h  = blockIdx.y;
    int b  = blockIdx.z;
    int hoff = h * DDIM;
    size_t bS = (size_t)b * SEQ;

    int cnt = g_cnt[b];
    const int T = (cnt + 31) >> 5;

    // prologue: Q + KV stage 0 as group 0; KV stages 1,2 as groups 1,2
    {
        int row = tid >> 3, seg = tid & 7;
        #pragma unroll
        for (int i = 0; i < 4; i++) {
            int r = row + i * 32;
            cp16(sQ + (uint32_t)r * FB_STRIDE_B + seg * 16,
                 qh_g + (bS + q0 + r) * EE + hoff + seg * 8);
        }
        uint32_t so = (uint32_t)row * FB_STRIDE_B + seg * 16;
        #pragma unroll
        for (int s = 0; s < FB_STAGES - 1; s++) {
            if (s < T) {
                uint32_t stg = sKV + s * FB_STAGE;
                size_t gk = (bS + s*32 + row) * EE + hoff + seg * 8;
                cp16(stg + 0*FB_KV_MAT + so, g_ckh + gk);
                cp16(stg + 1*FB_KV_MAT + so, g_cvh + gk);
            }
            cp_commit();
        }
    }
    cp_wait2();
    __syncthreads();

    uint32_t qf[4][4];
    {
        uint32_t base = (uint32_t)(warp*16 + ((lane>>3)&1)*8 + (lane&7)) * FB_STRIDE_B
                      + (lane>>4)*16;
        #pragma unroll
        for (int ks = 0; ks < 4; ks++)
            ldmx4(qf[ks], sQ + base + ks*32);
    }

    float accO[8][4];
    #pragma unroll
    for (int j = 0; j < 8; j++)
        #pragma unroll
        for (int c = 0; c < 4; c++) accO[j][c] = 0.f;
    float mOld0 = -1e30f, mOld1 = -1e30f, l0 = 0.f, l1 = 0.f;

    uint32_t kAddrBase = (uint32_t)(((lane>>4)*8 + (lane&7)) * FB_STRIDE_B)
                       + ((lane>>3)&1)*16;
    uint32_t vAddrBase = (uint32_t)((((lane>>3)&1)*8 + (lane&7)) * FB_STRIDE_B)
                       + (lane>>4)*16;

    for (int it = 0; it < T; it++) {
        if (it > 0) {          // group for stage `it` already awaited at it=0
            cp_wait2();
            __syncthreads();
        }
        // prefetch stage it+3 (guarded issue, unconditional commit)
        if (it + FB_STAGES - 1 < T) {
            uint32_t stg2 = sKV + ((it + FB_STAGES - 1) & (FB_STAGES-1)) * FB_STAGE;
            int row = tid >> 3, seg = tid & 7;
            uint32_t so = (uint32_t)row * FB_STRIDE_B + seg * 16;
            size_t gk = (bS + (it + FB_STAGES - 1)*32 + row) * EE + hoff + seg * 8;
            cp16(stg2 + 0*FB_KV_MAT + so, g_ckh + gk);
            cp16(stg2 + 1*FB_KV_MAT + so, g_cvh + gk);
        }
        cp_commit();

        uint32_t stg = sKV + (it & (FB_STAGES-1)) * FB_STAGE;

        float accS[4][4];
        #pragma unroll
        for (int j = 0; j < 4; j++)
            #pragma unroll
            for (int c = 0; c < 4; c++) accS[j][c] = 0.f;
        #pragma unroll
        for (int ks = 0; ks < 4; ks++) {
            uint32_t bh[2][4];
            #pragma unroll
            for (int p = 0; p < 2; p++)
                ldmx4(bh[p], stg + kAddrBase + (uint32_t)p*16*FB_STRIDE_B + ks*32);
            #pragma unroll
            for (int j = 0; j < 4; j++)
                mma_f16(accS[j], qf[ks], &bh[j>>1][(j&1)*2]);
        }

        int lim = cnt - it*32;
        if (lim >= 32) {
            #pragma unroll
            for (int j = 0; j < 4; j++) {
                accS[j][0] *= 0.125f; accS[j][1] *= 0.125f;
                accS[j][2] *= 0.125f; accS[j][3] *= 0.125f;
            }
        } else {
            #pragma unroll
            for (int j = 0; j < 4; j++) {
                int n0 = j*8 + tg*2;
                bool k0 = n0 < lim, k1 = (n0 + 1) < lim;
                accS[j][0] = k0 ? accS[j][0]*0.125f : -1e30f;
                accS[j][1] = k1 ? accS[j][1]*0.125f : -1e30f;
                accS[j][2] = k0 ? accS[j][2]*0.125f : -1e30f;
                accS[j][3] = k1 ? accS[j][3]*0.125f : -1e30f;
            }
        }
        float mx0 = -1e30f, mx1 = -1e30f;
        #pragma unroll
        for (int j = 0; j < 4; j++) {
            mx0 = fmaxf(mx0, fmaxf(accS[j][0], accS[j][1]));
            mx1 = fmaxf(mx1, fmaxf(accS[j][2], accS[j][3]));
        }
        mx0 = fmaxf(mx0, __shfl_xor_sync(0xffffffffu, mx0, 1));
        mx0 = fmaxf(mx0, __shfl_xor_sync(0xffffffffu, mx0, 2));
        mx1 = fmaxf(mx1, __shfl_xor_sync(0xffffffffu, mx1, 1));
        mx1 = fmaxf(mx1, __shfl_xor_sync(0xffffffffu, mx1, 2));
        float mn0 = fmaxf(mOld0, mx0), mn1 = fmaxf(mOld1, mx1);
        float scl0 = __expf(mOld0 - mn0), scl1 = __expf(mOld1 - mn1);
        float p[4][4];
        float ls0 = 0.f, ls1 = 0.f;
        #pragma unroll
        for (int j = 0; j < 4; j++) {
            p[j][0] = __expf(accS[j][0] - mn0);
            p[j][1] = __expf(accS[j][1] - mn0);
            p[j][2] = __expf(accS[j][2] - mn1);
            p[j][3] = __expf(accS[j][3] - mn1);
            ls0 += p[j][0] + p[j][1];
            ls1 += p[j][2] + p[j][3];
        }
        ls0 += __shfl_xor_sync(0xffffffffu, ls0, 1);
        ls0 += __shfl_xor_sync(0xffffffffu, ls0, 2);
        ls1 += __shfl_xor_sync(0xffffffffu, ls1, 1);
        ls1 += __shfl_xor_sync(0xffffffffu, ls1, 2);
        l0 = l0 * scl0 + ls0;
        l1 = l1 * scl1 + ls1;
        mOld0 = mn0; mOld1 = mn1;
        #pragma unroll
        for (int j = 0; j < 8; j++) {
            accO[j][0] *= scl0; accO[j][1] *= scl0;
            accO[j][2] *= scl1; accO[j][3] *= scl1;
        }

        uint32_t ap[2][4];
        #pragma unroll
        for (int jj = 0; jj < 2; jj++) {
            int t0 = 2*jj, t1 = 2*jj + 1;
            __half2 x0 = __floats2half2_rn(p[t0][0], p[t0][1]);
            __half2 x1 = __floats2half2_rn(p[t0][2], p[t0][3]);
            __half2 x2 = __floats2half2_rn(p[t1][0], p[t1][1]);
            __half2 x3 = __floats2half2_rn(p[t1][2], p[t1][3]);
            ap[jj][0] = *reinterpret_cast<uint32_t*>(&x0);
            ap[jj][1] = *reinterpret_cast<uint32_t*>(&x1);
            ap[jj][2] = *reinterpret_cast<uint32_t*>(&x2);
            ap[jj][3] = *reinterpret_cast<uint32_t*>(&x3);
        }

        #pragma unroll
        for (int ks2 = 0; ks2 < 2; ks2++) {
            uint32_t v2[4][4];
            #pragma unroll
            for (int ng = 0; ng < 4; ng++)
                ldmx4t(v2[ng], stg + FB_KV_MAT + vAddrBase
                               + (uint32_t)ks2*16*FB_STRIDE_B + ng*32);
            #pragma unroll
            for (int jd = 0; jd < 8; jd++)
                mma_f16(accO[jd], ap[ks2], &v2[jd>>1][(jd&1)*2]);
        }
        __syncthreads();
    }

    float inv0 = 1.f / l0, inv1 = 1.f / l1;
    size_t row0 = bS + q0 + warp*16 + g;
    #pragma unroll
    for (int jd = 0; jd < 8; jd++) {
        int c = hoff + jd*8 + tg*2;
        float2 o0; o0.x = accO[jd][0] * inv0; o0.y = accO[jd][1] * inv0;
        float2 o1; o1.x = accO[jd][2] * inv1; o1.y = accO[jd][3] * inv1;
        *(float2*)&out[row0 * EE + c]       = o0;
        *(float2*)&out[(row0 + 8) * EE + c] = o1;
    }
}

// ---------------- launch ----------------------------------------------------
extern "C" void kernel_launch(void* const* d_in, const int* in_sizes, int n_in,
                              void* d_out, int out_size) {
    const float* x_in = (const float*)d_in[0];
    const int* mask = (const int*)d_in[1];
    const float* wq = (const float*)d_in[2];
    const float* bq = (const float*)d_in[3];
    const float* wk = (const float*)d_in[4];
    const float* bk = (const float*)d_in[5];
    const float* wv = (const float*)d_in[6];
    const float* bv = (const float*)d_in[7];
    const float* g1 = (const float*)d_in[8];
    const float* b1 = (const float*)d_in[9];
    const float* g2 = (const float*)d_in[10];
    const float* b2 = (const float*)d_in[11];
    const float* gf = (const float*)d_in[12];
    const float* bf = (const float*)d_in[13];
    const float* W1 = (const float*)d_in[14];
    const float* B1 = (const float*)d_in[15];
    const float* W2 = (const float*)d_in[16];
    const float* B2 = (const float*)d_in[17];
    float* outp = (float*)d_out;

    float *px, *pattn;
    __half *pqh, *phh, *pfh;
    __half *pwqh, *pwkh, *pwvh, *pW1h, *pW2h;
    cudaGetSymbolAddress((void**)&px,    g_x);
    cudaGetSymbolAddress((void**)&pattn, g_attn);
    cudaGetSymbolAddress((void**)&pqh,   g_qh);
    cudaGetSymbolAddress((void**)&phh,   g_hh);
    cudaGetSymbolAddress((void**)&pfh,   g_fh);
    cudaGetSymbolAddress((void**)&pwqh,  g_wqh);
    cudaGetSymbolAddress((void**)&pwkh,  g_wkh);
    cudaGetSymbolAddress((void**)&pwvh,  g_wvh);
    cudaGetSymbolAddress((void**)&pW1h,  g_W1h);
    cudaGetSymbolAddress((void**)&pW2h,  g_W2h);

    cudaFuncSetAttribute(flash_attn_mma,
                         cudaFuncAttributeMaxDynamicSharedMemorySize, FB_SMEM);
    cudaFuncSetAttribute(gemm_mma_qkv,
                         cudaFuncAttributeMaxDynamicSharedMemorySize, GM_SMEM);
    cudaFuncSetAttribute(gemm_mma<1>,
                         cudaFuncAttributeMaxDynamicSharedMemorySize, GM_SMEM);
    cudaFuncSetAttribute(gemm_mma<2>,
                         cudaFuncAttributeMaxDynamicSharedMemorySize, GM_SMEM);

    {
        const int NQ = NLAYERS * EE * EE / 4;
        const int NW = DFFN * EE / 4;
        int total = 3*NQ + 2*NW;
        cvt_all<<<(total + 255) / 256, 256>>>(
            (const float4*)wq, (const float4*)wk, (const float4*)wv,
            (const float4*)W1, (const float4*)W2,
            (__half2*)pwqh, (__half2*)pwkh, (__half2*)pwvh,
            (__half2*)pW1h, (__half2*)pW2h);
    }
    compact_idx<<<BB, 1024>>>(mask);       // mask is layer-invariant

    dim3 gQKV(EE / 128, NROWS / 128, 3);   // (4, 32, 3)
    dim3 gFF1(DFFN / 128, NROWS / 128);    // (16, 32)
    dim3 gFF2(EE / 128, NROWS / 128);      // (4, 32)
    dim3 gAtt(SEQ / 128, HH, BB);          // (16, 8, 2)

    for (int l = 0; l < NLAYERS; l++) {
        const __half* wqhl = pwqh + (size_t)l * EE * EE;
        const __half* wkhl = pwkh + (size_t)l * EE * EE;
        const __half* wvhl = pwvh + (size_t)l * EE * EE;
        const float* bql = bq + (size_t)l * EE;
        const float* bkl = bk + (size_t)l * EE;
        const float* bvl = bv + (size_t)l * EE;
        const float* xsrc = (l == 0) ? x_in : px;

        ln_f16<<<NROWS, 128>>>(xsrc, phh, g1, b1);
        gemm_mma_qkv<<<gQKV, 256, GM_SMEM>>>(phh, wqhl, wkhl, wvhl,
            bql, bkl, bvl, pqh);
        flash_attn_mma<<<gAtt, 256, FB_SMEM>>>(pqh, pattn);
        fuse_attn_res_ln<<<NROWS, 128>>>(pattn, xsrc, px, phh, g2, b2);
        gemm_mma<1><<<gFF1, 256, GM_SMEM>>>(phh, pW1h, B1, EE, DFFN,
            nullptr, pfh, nullptr);
        gemm_mma<2><<<gFF2, 256, GM_SMEM>>>(pfh, pW2h, B2, DFFN, EE,
            px, nullptr, px);
    }
    ln_f32<<<NROWS, 128>>>(px, outp, gf, bf);
}

// round 16
// speedup vs baseline: 2.4858x; 1.1033x over previous
#include <cuda_runtime.h>
#include <cuda_fp16.h>
#include <stdint.h>

#define BB      2
#define SEQ     2048
#define EE      512
#define HH      8
#define DDIM    64
#define NLAYERS 2
#define DFFN    2048
#define NROWS   4096   // BB*SEQ

// mma.sync GEMM config: 128x128 tile, K-chunk 64 (fp16), 2-stage pipeline
#define GM_CHUNK     64
#define GM_STRIDE    144                   // 64 fp16 = 128B + 16B pad
#define GM_MAT_BYTES (128 * GM_STRIDE)     // 18432
#define GM_BUF_BYTES (2 * GM_MAT_BYTES)    // A, B = 36864
#define GM_SMEM      (2 * GM_BUF_BYTES)    // 73728

// flash mma config: BQ=128, BK=64, 8 warps, 2-stage KV pipeline
#define FB_STRIDE_B  144                   // 64 fp16 = 128B + 16B pad
#define FB_Q_BYTES   (128 * FB_STRIDE_B)   // 18432
#define FB_KV_MAT    (64 * FB_STRIDE_B)    // 9216
#define FB_STAGE     (2 * FB_KV_MAT)       // K, V = 18432
#define FB_SMEM      (FB_Q_BYTES + 2*FB_STAGE + 256)

// ---------------- scratch (device globals) ----------------------------------
__device__ float g_x[NROWS * EE];
__device__ float g_attn[NROWS * EE];
__device__ __half g_qh[NROWS*EE];
__device__ __half g_ckh[NROWS*EE];    // compacted K (scatter target)
__device__ __half g_cvh[NROWS*EE];    // compacted V (scatter target)
__device__ int g_cnt[BB];
__device__ int g_cpos[BB*SEQ];        // src row -> compacted row (-1 = masked)
__device__ __half g_hh[NROWS * EE];
__device__ __half g_fh[NROWS * DFFN];
__device__ __half g_wqh[NLAYERS*EE*EE];
__device__ __half g_wkh[NLAYERS*EE*EE];
__device__ __half g_wvh[NLAYERS*EE*EE];
__device__ __half g_W1h[DFFN*EE];
__device__ __half g_W2h[EE*DFFN];

// ---------------- PTX helpers ------------------------------------------------
__device__ __forceinline__ uint32_t smem_u32(const void* p) {
    uint32_t a;
    asm("{ .reg .u64 t; cvta.to.shared.u64 t, %1; cvt.u32.u64 %0, t; }" : "=r"(a) : "l"(p));
    return a;
}
__device__ __forceinline__ void cp16(uint32_t saddr, const void* g) {
    asm volatile("cp.async.cg.shared.global [%0], [%1], 16;" :: "r"(saddr), "l"(g));
}
__device__ __forceinline__ void cp_commit() {
    asm volatile("cp.async.commit_group;" ::: "memory");
}
__device__ __forceinline__ void cp_wait0() {
    asm volatile("cp.async.wait_group 0;" ::: "memory");
}
__device__ __forceinline__ void cp_wait1() {
    asm volatile("cp.async.wait_group 1;" ::: "memory");
}
__device__ __forceinline__ void ldmx4(uint32_t* r, uint32_t addr) {
    asm volatile("ldmatrix.sync.aligned.m8n8.x4.shared.b16 {%0,%1,%2,%3}, [%4];"
        : "=r"(r[0]), "=r"(r[1]), "=r"(r[2]), "=r"(r[3]) : "r"(addr));
}
__device__ __forceinline__ void ldmx4t(uint32_t* r, uint32_t addr) {
    asm volatile("ldmatrix.sync.aligned.m8n8.x4.trans.shared.b16 {%0,%1,%2,%3}, [%4];"
        : "=r"(r[0]), "=r"(r[1]), "=r"(r[2]), "=r"(r[3]) : "r"(addr));
}
__device__ __forceinline__ void mma_f16(float* d, const uint32_t* a, const uint32_t* b) {
    asm volatile(
        "mma.sync.aligned.m16n8k16.row.col.f32.f16.f16.f32 "
        "{%0,%1,%2,%3}, {%4,%5,%6,%7}, {%8,%9}, {%0,%1,%2,%3};"
        : "+f"(d[0]), "+f"(d[1]), "+f"(d[2]), "+f"(d[3])
        : "r"(a[0]), "r"(a[1]), "r"(a[2]), "r"(a[3]), "r"(b[0]), "r"(b[1]));
}

// ---------------- reductions -------------------------------------------------
__device__ __forceinline__ void block_reduce2(float& s, float& s2) {
    __shared__ float shm[8];
    #pragma unroll
    for (int o = 16; o > 0; o >>= 1) {
        s  += __shfl_down_sync(0xffffffffu, s,  o);
        s2 += __shfl_down_sync(0xffffffffu, s2, o);
    }
    int w = threadIdx.x >> 5;
    __syncthreads();
    if ((threadIdx.x & 31) == 0) { shm[w] = s; shm[4 + w] = s2; }
    __syncthreads();
    s  = shm[0] + shm[1] + shm[2] + shm[3];
    s2 = shm[4] + shm[5] + shm[6] + shm[7];
}

// ---------------- LayerNorm variants ----------------------------------------
__global__ void ln_f32(const float* __restrict__ in, float* __restrict__ outp,
                       const float* __restrict__ g, const float* __restrict__ b) {
    int row = blockIdx.x, t = threadIdx.x;
    const float* xr = in + (size_t)row * EE;
    float v[4], s = 0.f, s2 = 0.f;
    #pragma unroll
    for (int i = 0; i < 4; i++) { v[i] = xr[t + i*128]; s += v[i]; s2 += v[i]*v[i]; }
    block_reduce2(s, s2);
    float mu = s * (1.f/EE), var = s2 * (1.f/EE) - mu*mu, r = rsqrtf(var + 1e-5f);
    #pragma unroll
    for (int i = 0; i < 4; i++) {
        int idx = t + i*128;
        outp[(size_t)row*EE + idx] = (v[i]-mu)*r*g[idx] + b[idx];
    }
}
__global__ void ln_f16(const float* __restrict__ in, __half* __restrict__ hi,
                       const float* __restrict__ g, const float* __restrict__ b) {
    int row = blockIdx.x, t = threadIdx.x;
    const float* xr = in + (size_t)row * EE;
    float v[4], s = 0.f, s2 = 0.f;
    #pragma unroll
    for (int i = 0; i < 4; i++) { v[i] = xr[t + i*128]; s += v[i]; s2 += v[i]*v[i]; }
    block_reduce2(s, s2);
    float mu = s * (1.f/EE), var = s2 * (1.f/EE) - mu*mu, r = rsqrtf(var + 1e-5f);
    #pragma unroll
    for (int i = 0; i < 4; i++) {
        int idx = t + i*128;
        hi[(size_t)row*EE + idx] = __float2half((v[i]-mu)*r*g[idx] + b[idx]);
    }
}
// x_out = x_in + LN(attn)*g2+b2 ; hh = f16(LN_noaffine(x_out))
__global__ void fuse_attn_res_ln(const float* __restrict__ attn,
                                 const float* __restrict__ xin, float* __restrict__ xout,
                                 __half* __restrict__ hh,
                                 const float* __restrict__ g2, const float* __restrict__ b2) {
    int row = blockIdx.x, t = threadIdx.x;
    const float* ar = attn + (size_t)row * EE;
    float a[4], s = 0.f, s2 = 0.f;
    #pragma unroll
    for (int i = 0; i < 4; i++) { a[i] = ar[t + i*128]; s += a[i]; s2 += a[i]*a[i]; }
    block_reduce2(s, s2);
    float mu = s * (1.f/EE), var = s2 * (1.f/EE) - mu*mu, r = rsqrtf(var + 1e-5f);
    float xv[4];
    s = 0.f; s2 = 0.f;
    #pragma unroll
    for (int i = 0; i < 4; i++) {
        int idx = t + i*128;
        float y = (a[i]-mu)*r*g2[idx] + b2[idx];
        float xn = xin[(size_t)row*EE + idx] + y;
        xout[(size_t)row*EE + idx] = xn;
        xv[i] = xn; s += xn; s2 += xn*xn;
    }
    block_reduce2(s, s2);
    float mu2 = s * (1.f/EE), var2 = s2 * (1.f/EE) - mu2*mu2, r2 = rsqrtf(var2 + 1e-5f);
    #pragma unroll
    for (int i = 0; i < 4; i++) {
        int idx = t + i*128;
        hh[(size_t)row*EE + idx] = __float2half((xv[i]-mu2)*r2);
    }
}

// ---------------- all weights fp32 -> fp16 in ONE launch ---------------------
__global__ void cvt_all(const float4* __restrict__ wq, const float4* __restrict__ wk,
                        const float4* __restrict__ wv, const float4* __restrict__ W1,
                        const float4* __restrict__ W2,
                        __half2* __restrict__ owq, __half2* __restrict__ owk,
                        __half2* __restrict__ owv, __half2* __restrict__ oW1,
                        __half2* __restrict__ oW2) {
    const int NQ = NLAYERS * EE * EE / 4;
    const int NW = DFFN * EE / 4;
    int i = blockIdx.x * blockDim.x + threadIdx.x;
    const float4* src; __half2* dst; int idx;
    if      (i < NQ)          { src = wq; dst = owq; idx = i; }
    else if (i < 2*NQ)        { src = wk; dst = owk; idx = i - NQ; }
    else if (i < 3*NQ)        { src = wv; dst = owv; idx = i - 2*NQ; }
    else if (i < 3*NQ + NW)   { src = W1; dst = oW1; idx = i - 3*NQ; }
    else if (i < 3*NQ + 2*NW) { src = W2; dst = oW2; idx = i - 3*NQ - NW; }
    else return;
    float4 v = src[idx];
    dst[2*idx]   = __floats2half2_rn(v.x, v.y);
    dst[2*idx+1] = __floats2half2_rn(v.z, v.w);
}

// ---------------- mask compaction: inverse perm + pad zeroing ---------------
__global__ __launch_bounds__(1024) void compact_idx(const int* __restrict__ mask) {
    __shared__ int part[1024];
    int b = blockIdx.x, t = threadIdx.x;
    const int* mb = mask + (size_t)b * SEQ;
    int v0 = (mb[2*t]   == 0);
    int v1 = (mb[2*t+1] == 0);
    part[t] = v0 + v1;
    __syncthreads();
    for (int o = 1; o < 1024; o <<= 1) {
        int x = part[t];
        int y = (t >= o) ? part[t-o] : 0;
        __syncthreads();
        part[t] = x + y;
        __syncthreads();
    }
    int incl = part[t];
    int excl = incl - (v0 + v1);
    g_cpos[b*SEQ + 2*t]   = v0 ? excl : -1;
    g_cpos[b*SEQ + 2*t+1] = v1 ? (excl + v0) : -1;
    int cnt = part[1023];
    if (t == 1023) g_cnt[b] = cnt;
    __syncthreads();
    // zero pad rows [cnt, lim) of compacted K/V; lim = 64-row multiple (BK=64)
    int lim = (cnt + 63) & ~63;
    if (lim > SEQ) lim = SEQ;
    int padElems = (lim - cnt) * (EE / 8);
    for (int e = t; e < padElems; e += 1024) {
        int j = cnt + e / (EE / 8);
        int c = e % (EE / 8);
        uint4 z; z.x = 0; z.y = 0; z.z = 0; z.w = 0;
        *(uint4*)(g_ckh + ((size_t)b*SEQ + j)*EE + c*8) = z;
        *(uint4*)(g_cvh + ((size_t)b*SEQ + j)*EE + c*8) = z;
    }
}

// ---------------- mma.sync GEMM (fp16, K-chunk 64, 2-stage) ------------------
// MODE 1: bias+relu -> fp16. MODE 2: fp32+bias+residual. MODE 3: bias -> fp16.
// MODE 5: bias -> fp16 with row scatter via remap (compacted K/V; dst<0 = drop).
template<int MODE>
__device__ __forceinline__ void gemm_mma_body(
    const __half* __restrict__ A, const __half* __restrict__ B,
    const float* __restrict__ bias, int K, int N,
    float* __restrict__ Cf, __half* __restrict__ Ch,
    const float* __restrict__ res, const int* __restrict__ remap,
    int rowBase, int colBase)
{
    extern __shared__ char sm8[];
    uint32_t sbase = smem_u32(sm8);
    int tid = threadIdx.x, lane = tid & 31, warp = tid >> 5;
    int wm = warp >> 2, wn = warp & 3;

    float acc[4][4][4];
    #pragma unroll
    for (int i = 0; i < 4; i++)
        #pragma unroll
        for (int j = 0; j < 4; j++)
            #pragma unroll
            for (int c = 0; c < 4; c++) acc[i][j][c] = 0.f;

    uint32_t aAddr = (uint32_t)((wm*64 + ((lane>>3)&1)*8 + (lane&7)) * GM_STRIDE
                                + (lane>>4)*16);
    uint32_t bAddr = (uint32_t)((wn*32 + (lane>>4)*8 + (lane&7)) * GM_STRIDE
                                + ((lane>>3)&1)*16);

    const int T = K / GM_CHUNK;
    int lrow = tid >> 3, lseg = tid & 7;      // 32 rows x 8 segs

    {   // stage 0
        #pragma unroll
        for (int j = 0; j < 4; j++) {
            int row = lrow + j*32;
            uint32_t so = row*GM_STRIDE + lseg*16;
            cp16(sbase + 0*GM_MAT_BYTES + so, A + (size_t)(rowBase+row)*K + lseg*8);
            cp16(sbase + 1*GM_MAT_BYTES + so, B + (size_t)(colBase+row)*K + lseg*8);
        }
        cp_commit();
    }

    for (int t = 0; t < T; t++) {
        if (t + 1 < T) {
            uint32_t sb = sbase + ((t+1) & 1) * GM_BUF_BYTES;
            int koff = (t+1) * GM_CHUNK;
            #pragma unroll
            for (int j = 0; j < 4; j++) {
                int row = lrow + j*32;
                uint32_t so = row*GM_STRIDE + lseg*16;
                cp16(sb + 0*GM_MAT_BYTES + so, A + (size_t)(rowBase+row)*K + koff + lseg*8);
                cp16(sb + 1*GM_MAT_BYTES + so, B + (size_t)(colBase+row)*K + koff + lseg*8);
            }
            cp_commit();
            cp_wait1();
        } else {
            cp_wait0();
        }
        __syncthreads();

        uint32_t buf = sbase + (t & 1) * GM_BUF_BYTES;
        #pragma unroll
        for (int ks = 0; ks < 4; ks++) {
            uint32_t ah[4][4], bh[2][4];
            #pragma unroll
            for (int i = 0; i < 4; i++)
                ldmx4(ah[i], buf + aAddr + i*16*GM_STRIDE + ks*32);
            #pragma unroll
            for (int p = 0; p < 2; p++)
                ldmx4(bh[p], buf + GM_MAT_BYTES + bAddr + p*16*GM_STRIDE + ks*32);
            #pragma unroll
            for (int i = 0; i < 4; i++)
                #pragma unroll
                for (int j = 0; j < 4; j++)
                    mma_f16(acc[i][j], ah[i], &bh[j>>1][(j&1)*2]);
        }
        __syncthreads();
    }

    int g = lane >> 2, tg = lane & 3;
    #pragma unroll
    for (int i = 0; i < 4; i++) {
        int r0 = rowBase + wm*64 + i*16 + g;
        #pragma unroll
        for (int j = 0; j < 4; j++) {
            int c = colBase + wn*32 + j*8 + tg*2;
            float b0 = bias[c], b1 = bias[c+1];
            #pragma unroll
            for (int half = 0; half < 2; half++) {
                int r = r0 + half*8;
                float v0 = acc[i][j][half*2+0] + b0;
                float v1 = acc[i][j][half*2+1] + b1;
                if (MODE == 1 || MODE == 3) {
                    if (MODE == 1) { v0 = fmaxf(v0, 0.f); v1 = fmaxf(v1, 0.f); }
                    *(__half2*)&Ch[(size_t)r * N + c] = __floats2half2_rn(v0, v1);
                } else if (MODE == 5) {
                    int dst = remap[r];
                    if (dst >= 0) {
                        size_t rr = (size_t)(r & ~(SEQ-1)) + dst;
                        *(__half2*)&Ch[rr * N + c] = __floats2half2_rn(v0, v1);
                    }
                } else {
                    if (MODE == 2) {
                        float2 rv = *(const float2*)&res[(size_t)r * N + c];
                        v0 += rv.x; v1 += rv.y;
                    }
                    float2 o; o.x = v0; o.y = v1;
                    *(float2*)&Cf[(size_t)r * N + c] = o;
                }
            }
        }
    }
}

template<int MODE>
__global__ __launch_bounds__(256, 2) void gemm_mma(
    const __half* __restrict__ A, const __half* __restrict__ B,
    const float* __restrict__ bias, int K, int N,
    float* __restrict__ Cf, __half* __restrict__ Ch, const float* __restrict__ res)
{
    gemm_mma_body<MODE>(A, B, bias, K, N, Cf, Ch, res, nullptr,
                        blockIdx.y * 128, blockIdx.x * 128);
}

__global__ __launch_bounds__(256, 2) void gemm_mma_qkv(
    const __half* __restrict__ hh,
    const __half* __restrict__ wqh, const __half* __restrict__ wkh,
    const __half* __restrict__ wvh,
    const float* __restrict__ bq, const float* __restrict__ bk, const float* __restrict__ bv,
    __half* qh)
{
    if (blockIdx.z == 0) {
        gemm_mma_body<3>(hh, wqh, bq, EE, EE, nullptr, qh, nullptr, nullptr,
                         blockIdx.y * 128, blockIdx.x * 128);
    } else if (blockIdx.z == 1) {
        gemm_mma_body<5>(hh, wkh, bk, EE, EE, nullptr, g_ckh, nullptr, g_cpos,
                         blockIdx.y * 128, blockIdx.x * 128);
    } else {
        gemm_mma_body<5>(hh, wvh, bv, EE, EE, nullptr, g_cvh, nullptr, g_cpos,
                         blockIdx.y * 128, blockIdx.x * 128);
    }
}

// ---------------- Flash attention (fp16, BK=64, 2-stage) ---------------------
__global__ __launch_bounds__(256) void flash_attn_mma(
    const __half* __restrict__ qh_g, float* __restrict__ out)
{
    extern __shared__ char fsm[];
    uint32_t sQ  = smem_u32(fsm);
    uint32_t sKV = sQ + FB_Q_BYTES;

    int tid = threadIdx.x, lane = tid & 31, warp = tid >> 5;
    int g = lane >> 2, tg = lane & 3;
    int q0 = blockIdx.x * 128;
    int h  = blockIdx.y;
    int b  = blockIdx.z;
    int hoff = h * DDIM;
    size_t bS = (size_t)b * SEQ;

    int cnt = g_cnt[b];
    const int T = (cnt + 63) >> 6;

    {   // Q + KV stage 0 in one group
        int row = tid >> 3, seg = tid & 7;
        #pragma unroll
        for (int i = 0; i < 4; i++) {
            int r = row + i * 32;
            cp16(sQ + (uint32_t)r * FB_STRIDE_B + seg * 16,
                 qh_g + (bS + q0 + r) * EE + hoff + seg * 8);
        }
        #pragma unroll
        for (int i = 0; i < 2; i++) {
            int r = row + i * 32;
            uint32_t so = (uint32_t)r * FB_STRIDE_B + seg * 16;
            size_t gk = (bS + r) * EE + hoff + seg * 8;
            cp16(sKV + 0*FB_KV_MAT + so, g_ckh + gk);
            cp16(sKV + 1*FB_KV_MAT + so, g_cvh + gk);
        }
        cp_commit();
    }
    cp_wait0();
    __syncthreads();

    uint32_t qf[4][4];
    {
        uint32_t base = (uint32_t)(warp*16 + ((lane>>3)&1)*8 + (lane&7)) * FB_STRIDE_B
                      + (lane>>4)*16;
        #pragma unroll
        for (int ks = 0; ks < 4; ks++)
            ldmx4(qf[ks], sQ + base + ks*32);
    }

    float accO[8][4];
    #pragma unroll
    for (int j = 0; j < 8; j++)
        #pragma unroll
        for (int c = 0; c < 4; c++) accO[j][c] = 0.f;
    float mOld0 = -1e30f, mOld1 = -1e30f, l0 = 0.f, l1 = 0.f;

    uint32_t kAddrBase = (uint32_t)(((lane>>4)*8 + (lane&7)) * FB_STRIDE_B)
                       + ((lane>>3)&1)*16;
    uint32_t vAddrBase = (uint32_t)((((lane>>3)&1)*8 + (lane&7)) * FB_STRIDE_B)
                       + (lane>>4)*16;

    for (int it = 0; it < T; it++) {
        if (it + 1 < T) {
            uint32_t stg2 = sKV + ((it+1) & 1) * FB_STAGE;
            int row = tid >> 3, seg = tid & 7;
            #pragma unroll
            for (int i = 0; i < 2; i++) {
                int r = row + i * 32;
                uint32_t so = (uint32_t)r * FB_STRIDE_B + seg * 16;
                size_t gk = (bS + (it+1)*64 + r) * EE + hoff + seg * 8;
                cp16(stg2 + 0*FB_KV_MAT + so, g_ckh + gk);
                cp16(stg2 + 1*FB_KV_MAT + so, g_cvh + gk);
            }
            cp_commit();
            cp_wait1();
        } else {
            cp_wait0();
        }
        __syncthreads();

        uint32_t stg = sKV + (it & 1) * FB_STAGE;

        // S = Q K^T over 64 keys: 8 n-tiles
        float accS[8][4];
        #pragma unroll
        for (int j = 0; j < 8; j++)
            #pragma unroll
            for (int c = 0; c < 4; c++) accS[j][c] = 0.f;
        #pragma unroll
        for (int ks = 0; ks < 4; ks++) {
            uint32_t bh[4][4];
            #pragma unroll
            for (int p = 0; p < 4; p++)
                ldmx4(bh[p], stg + kAddrBase + (uint32_t)p*16*FB_STRIDE_B + ks*32);
            #pragma unroll
            for (int j = 0; j < 8; j++)
                mma_f16(accS[j], qf[ks], &bh[j>>1][(j&1)*2]);
        }

        int lim = cnt - it*64;
        if (lim >= 64) {
            #pragma unroll
            for (int j = 0; j < 8; j++) {
                accS[j][0] *= 0.125f; accS[j][1] *= 0.125f;
                accS[j][2] *= 0.125f; accS[j][3] *= 0.125f;
            }
        } else {
            #pragma unroll
            for (int j = 0; j < 8; j++) {
                int n0 = j*8 + tg*2;
                bool k0 = n0 < lim, k1 = (n0 + 1) < lim;
                accS[j][0] = k0 ? accS[j][0]*0.125f : -1e30f;
                accS[j][1] = k1 ? accS[j][1]*0.125f : -1e30f;
                accS[j][2] = k0 ? accS[j][2]*0.125f : -1e30f;
                accS[j][3] = k1 ? accS[j][3]*0.125f : -1e30f;
            }
        }
        float mx0 = -1e30f, mx1 = -1e30f;
        #pragma unroll
        for (int j = 0; j < 8; j++) {
            mx0 = fmaxf(mx0, fmaxf(accS[j][0], accS[j][1]));
            mx1 = fmaxf(mx1, fmaxf(accS[j][2], accS[j][3]));
        }
        mx0 = fmaxf(mx0, __shfl_xor_sync(0xffffffffu, mx0, 1));
        mx0 = fmaxf(mx0, __shfl_xor_sync(0xffffffffu, mx0, 2));
        mx1 = fmaxf(mx1, __shfl_xor_sync(0xffffffffu, mx1, 1));
        mx1 = fmaxf(mx1, __shfl_xor_sync(0xffffffffu, mx1, 2));
        float mn0 = fmaxf(mOld0, mx0), mn1 = fmaxf(mOld1, mx1);
        float scl0 = __expf(mOld0 - mn0), scl1 = __expf(mOld1 - mn1);
        float p[8][4];
        float ls0 = 0.f, ls1 = 0.f;
        #pragma unroll
        for (int j = 0; j < 8; j++) {
            p[j][0] = __expf(accS[j][0] - mn0);
            p[j][1] = __expf(accS[j][1] - mn0);
            p[j][2] = __expf(accS[j][2] - mn1);
            p[j][3] = __expf(accS[j][3] - mn1);
            ls0 += p[j][0] + p[j][1];
            ls1 += p[j][2] + p[j][3];
        }
        ls0 += __shfl_xor_sync(0xffffffffu, ls0, 1);
        ls0 += __shfl_xor_sync(0xffffffffu, ls0, 2);
        ls1 += __shfl_xor_sync(0xffffffffu, ls1, 1);
        ls1 += __shfl_xor_sync(0xffffffffu, ls1, 2);
        l0 = l0 * scl0 + ls0;
        l1 = l1 * scl1 + ls1;
        mOld0 = mn0; mOld1 = mn1;
        #pragma unroll
        for (int j = 0; j < 8; j++) {
            accO[j][0] *= scl0; accO[j][1] *= scl0;
            accO[j][2] *= scl1; accO[j][3] *= scl1;
        }

        // P fragments: ap[ks2] covers keys ks2*16..+15
        uint32_t ap[4][4];
        #pragma unroll
        for (int jj = 0; jj < 4; jj++) {
            int t0 = 2*jj, t1 = 2*jj + 1;
            __half2 x0 = __floats2half2_rn(p[t0][0], p[t0][1]);
            __half2 x1 = __floats2half2_rn(p[t0][2], p[t0][3]);
            __half2 x2 = __floats2half2_rn(p[t1][0], p[t1][1]);
            __half2 x3 = __floats2half2_rn(p[t1][2], p[t1][3]);
            ap[jj][0] = *reinterpret_cast<uint32_t*>(&x0);
            ap[jj][1] = *reinterpret_cast<uint32_t*>(&x1);
            ap[jj][2] = *reinterpret_cast<uint32_t*>(&x2);
            ap[jj][3] = *reinterpret_cast<uint32_t*>(&x3);
        }

        // O += P V over 64 keys
        #pragma unroll
        for (int ks2 = 0; ks2 < 4; ks2++) {
            uint32_t v2[4][4];
            #pragma unroll
            for (int ng = 0; ng < 4; ng++)
                ldmx4t(v2[ng], stg + FB_KV_MAT + vAddrBase
                               + (uint32_t)ks2*16*FB_STRIDE_B + ng*32);
            #pragma unroll
            for (int jd = 0; jd < 8; jd++)
                mma_f16(accO[jd], ap[ks2], &v2[jd>>1][(jd&1)*2]);
        }
        __syncthreads();
    }

    float inv0 = 1.f / l0, inv1 = 1.f / l1;
    size_t row0 = bS + q0 + warp*16 + g;
    #pragma unroll
    for (int jd = 0; jd < 8; jd++) {
        int c = hoff + jd*8 + tg*2;
        float2 o0; o0.x = accO[jd][0] * inv0; o0.y = accO[jd][1] * inv0;
        float2 o1; o1.x = accO[jd][2] * inv1; o1.y = accO[jd][3] * inv1;
        *(float2*)&out[row0 * EE + c]       = o0;
        *(float2*)&out[(row0 + 8) * EE + c] = o1;
    }
}

// ---------------- launch ----------------------------------------------------
extern "C" void kernel_launch(void* const* d_in, const int* in_sizes, int n_in,
                              void* d_out, int out_size) {
    const float* x_in = (const float*)d_in[0];
    const int* mask = (const int*)d_in[1];
    const float* wq = (const float*)d_in[2];
    const float* bq = (const float*)d_in[3];
    const float* wk = (const float*)d_in[4];
    const float* bk = (const float*)d_in[5];
    const float* wv = (const float*)d_in[6];
    const float* bv = (const float*)d_in[7];
    const float* g1 = (const float*)d_in[8];
    const float* b1 = (const float*)d_in[9];
    const float* g2 = (const float*)d_in[10];
    const float* b2 = (const float*)d_in[11];
    const float* gf = (const float*)d_in[12];
    const float* bf = (const float*)d_in[13];
    const float* W1 = (const float*)d_in[14];
    const float* B1 = (const float*)d_in[15];
    const float* W2 = (const float*)d_in[16];
    const float* B2 = (const float*)d_in[17];
    float* outp = (float*)d_out;

    float *px, *pattn;
    __half *pqh, *phh, *pfh;
    __half *pwqh, *pwkh, *pwvh, *pW1h, *pW2h;
    cudaGetSymbolAddress((void**)&px,    g_x);
    cudaGetSymbolAddress((void**)&pattn, g_attn);
    cudaGetSymbolAddress((void**)&pqh,   g_qh);
    cudaGetSymbolAddress((void**)&phh,   g_hh);
    cudaGetSymbolAddress((void**)&pfh,   g_fh);
    cudaGetSymbolAddress((void**)&pwqh,  g_wqh);
    cudaGetSymbolAddress((void**)&pwkh,  g_wkh);
    cudaGetSymbolAddress((void**)&pwvh,  g_wvh);
    cudaGetSymbolAddress((void**)&pW1h,  g_W1h);
    cudaGetSymbolAddress((void**)&pW2h,  g_W2h);

    cudaFuncSetAttribute(flash_attn_mma,
                         cudaFuncAttributeMaxDynamicSharedMemorySize, FB_SMEM);
    cudaFuncSetAttribute(gemm_mma_qkv,
                         cudaFuncAttributeMaxDynamicSharedMemorySize, GM_SMEM);
    cudaFuncSetAttribute(gemm_mma<1>,
                         cudaFuncAttributeMaxDynamicSharedMemorySize, GM_SMEM);
    cudaFuncSetAttribute(gemm_mma<2>,
                         cudaFuncAttributeMaxDynamicSharedMemorySize, GM_SMEM);

    {
        const int NQ = NLAYERS * EE * EE / 4;
        const int NW = DFFN * EE / 4;
        int total = 3*NQ + 2*NW;
        cvt_all<<<(total + 255) / 256, 256>>>(
            (const float4*)wq, (const float4*)wk, (const float4*)wv,
            (const float4*)W1, (const float4*)W2,
            (__half2*)pwqh, (__half2*)pwkh, (__half2*)pwvh,
            (__half2*)pW1h, (__half2*)pW2h);
    }
    compact_idx<<<BB, 1024>>>(mask);       // mask is layer-invariant

    dim3 gQKV(EE / 128, NROWS / 128, 3);   // (4, 32, 3)
    dim3 gFF1(DFFN / 128, NROWS / 128);    // (16, 32)
    dim3 gFF2(EE / 128, NROWS / 128);      // (4, 32)
    dim3 gAtt(SEQ / 128, HH, BB);          // (16, 8, 2)

    for (int l = 0; l < NLAYERS; l++) {
        const __half* wqhl = pwqh + (size_t)l * EE * EE;
        const __half* wkhl = pwkh + (size_t)l * EE * EE;
        const __half* wvhl = pwvh + (size_t)l * EE * EE;
        const float* bql = bq + (size_t)l * EE;
        const float* bkl = bk + (size_t)l * EE;
        const float* bvl = bv + (size_t)l * EE;
        const float* xsrc = (l == 0) ? x_in : px;

        ln_f16<<<NROWS, 128>>>(xsrc, phh, g1, b1);
        gemm_mma_qkv<<<gQKV, 256, GM_SMEM>>>(phh, wqhl, wkhl, wvhl,
            bql, bkl, bvl, pqh);
        flash_attn_mma<<<gAtt, 256, FB_SMEM>>>(pqh, pattn);
        fuse_attn_res_ln<<<NROWS, 128>>>(pattn, xsrc, px, phh, g2, b2);
        gemm_mma<1><<<gFF1, 256, GM_SMEM>>>(phh, pW1h, B1, EE, DFFN,
            nullptr, pfh, nullptr);
        gemm_mma<2><<<gFF2, 256, GM_SMEM>>>(pfh, pW2h, B2, DFFN, EE,
            px, nullptr, px);
    }
    ln_f32<<<NROWS, 128>>>(px, outp, gf, bf);
}